// round 1
// baseline (speedup 1.0000x reference)
#include <cuda_runtime.h>
#include <math.h>

// Problem constants (B=1)
#define S     1024
#define H     32
#define HKV   8
#define D     128
#define HID   4096
#define KVHID 1024
#define GROUPS 4

// ---------------- scratch (static device globals: no allocs allowed) -------
__device__ float g_q[(size_t)S * HID];          // 16 MB
__device__ float g_k[(size_t)S * KVHID];        // 4 MB
__device__ float g_v[(size_t)S * KVHID];        // 4 MB
__device__ float g_vT[(size_t)KVHID * S];       // 4 MB (scaled, transposed)
__device__ float g_scores[(size_t)H * S * S];   // 134 MB
__device__ float g_ctx[(size_t)S * HID];        // 16 MB

// ---------------- generic batched NT SGEMM ---------------------------------
// C[z][m][n] = sum_k A[z][m][k] * B[z/zdivB][n][k]
// grid: (N/BN, M/BM, Z). All dims assumed multiples of tile sizes (true here).
#define BM 128
#define BN 128
#define BKT 16
#define TM 8
#define TN 8

__global__ __launch_bounds__(256) void sgemm_nt(
    const float* __restrict__ A, const float* __restrict__ B, float* __restrict__ C,
    int K, int lda, int ldb, int ldc,
    size_t sA, size_t sB, size_t sC, int zdivB)
{
    A += (size_t)blockIdx.z * sA;
    B += (size_t)(blockIdx.z / zdivB) * sB;
    C += (size_t)blockIdx.z * sC;

    __shared__ float As[BKT][BM];
    __shared__ float Bs[BKT][BN];

    const int tid = threadIdx.x;
    const int tx  = tid & 15;   // 0..15 -> N
    const int ty  = tid >> 4;   // 0..15 -> M

    const float* Ab = A + (size_t)blockIdx.y * BM * lda;
    const float* Bb = B + (size_t)blockIdx.x * BN * ldb;

    float acc[TM][TN];
#pragma unroll
    for (int i = 0; i < TM; i++)
#pragma unroll
        for (int j = 0; j < TN; j++) acc[i][j] = 0.0f;

    const int row0 = tid >> 2;          // 0..63
    const int kc0  = (tid & 3) << 2;    // 0,4,8,12

    for (int k0 = 0; k0 < K; k0 += BKT) {
#pragma unroll
        for (int t = 0; t < 2; t++) {
            int row = row0 + t * 64;
            float4 a = *(const float4*)(Ab + (size_t)row * lda + k0 + kc0);
            As[kc0 + 0][row] = a.x; As[kc0 + 1][row] = a.y;
            As[kc0 + 2][row] = a.z; As[kc0 + 3][row] = a.w;
            float4 b = *(const float4*)(Bb + (size_t)row * ldb + k0 + kc0);
            Bs[kc0 + 0][row] = b.x; Bs[kc0 + 1][row] = b.y;
            Bs[kc0 + 2][row] = b.z; Bs[kc0 + 3][row] = b.w;
        }
        __syncthreads();

#pragma unroll
        for (int kk = 0; kk < BKT; kk++) {
            float a[TM], b[TN];
            float4 a0 = *(const float4*)&As[kk][ty * TM];
            float4 a1 = *(const float4*)&As[kk][ty * TM + 4];
            a[0] = a0.x; a[1] = a0.y; a[2] = a0.z; a[3] = a0.w;
            a[4] = a1.x; a[5] = a1.y; a[6] = a1.z; a[7] = a1.w;
            float4 b0 = *(const float4*)&Bs[kk][tx * TN];
            float4 b1 = *(const float4*)&Bs[kk][tx * TN + 4];
            b[0] = b0.x; b[1] = b0.y; b[2] = b0.z; b[3] = b0.w;
            b[4] = b1.x; b[5] = b1.y; b[6] = b1.z; b[7] = b1.w;
#pragma unroll
            for (int i = 0; i < TM; i++)
#pragma unroll
                for (int j = 0; j < TN; j++)
                    acc[i][j] = fmaf(a[i], b[j], acc[i][j]);
        }
        __syncthreads();
    }

    float* Cb = C + (size_t)(blockIdx.y * BM + ty * TM) * ldc
                  + blockIdx.x * BN + tx * TN;
#pragma unroll
    for (int i = 0; i < TM; i++) {
        float4 c0 = make_float4(acc[i][0], acc[i][1], acc[i][2], acc[i][3]);
        float4 c1 = make_float4(acc[i][4], acc[i][5], acc[i][6], acc[i][7]);
        *(float4*)(Cb + (size_t)i * ldc)     = c0;
        *(float4*)(Cb + (size_t)i * ldc + 4) = c1;
    }
}

// ---------------- RoPE (q and k) + gamma steering scale on k ---------------
// grid: (S, H + HKV), 64 threads (one per rotation pair)
__global__ void rope_scale_kernel(float* __restrict__ q, float* __restrict__ k,
                                  const int* __restrict__ pos,
                                  const float* __restrict__ prior)
{
    int s = blockIdx.x;
    int h = blockIdx.y;
    int d = threadIdx.x;   // 0..63

    float p = (float)pos[s];
    float inv = powf(10000.0f, -(2.0f * (float)d) / 128.0f);
    float sn, c;
    sincosf(p * inv, &sn, &c);

    float* base;
    float scale = 1.0f;
    if (h < H) {
        base = q + (size_t)s * HID + h * D;
    } else {
        base = k + (size_t)s * KVHID + (h - H) * D;
        float g = 1.0f + 0.5f * prior[s];
        scale = fminf(fmaxf(g, 0.5f), 2.0f);   // gamma clip
    }
    float x1 = base[d];
    float x2 = base[d + 64];
    base[d]      = (x1 * c - x2 * sn) * scale;
    base[d + 64] = (x2 * c + x1 * sn) * scale;
}

// ---------------- v: eta steering scale + transpose ------------------------
// grid: (S, KVHID/128), 128 threads
__global__ void v_scale_transpose(const float* __restrict__ v, float* __restrict__ vT,
                                  const float* __restrict__ prior)
{
    int s = blockIdx.x;
    int c = blockIdx.y * 128 + threadIdx.x;
    float e = 1.0f + 0.5f * prior[s];
    float eta = fminf(fmaxf(e, 0.5f), 2.0f);
    vT[(size_t)c * S + s] = v[(size_t)s * KVHID + c] * eta;
}

// ---------------- fused scale + bias-steer + mask + softmax + post-steer ---
// grid: (S rows, H heads), 256 threads. In-place on g_scores.
__global__ __launch_bounds__(256) void softmax_steer(
    float* __restrict__ scores, const float* __restrict__ mask,
    const float* __restrict__ prior, const float* __restrict__ m1,
    const float* __restrict__ m2)
{
    int row = blockIdx.x;
    int h   = blockIdx.y;
    float* srow = scores + ((size_t)h * S + row) * S;
    const float* mrow = mask + (size_t)row * S;

    __shared__ float buf[S];
    __shared__ float red[256];
    int tid = threadIdx.x;

    float l1 = m1[h], l2 = m2[h];
    const float rsq = 0.08838834764831845f;   // 1/sqrt(128)

    // pass 1: scale, bias steering, mask; track max
    float lmax = -1e30f;
    for (int j = tid; j < S; j += 256) {
        float pj = prior[j];
        float bias = fminf(fmaxf(pj, -5.0f), 5.0f);   // clip(BETA_BIAS*prior, +-BIAS_CAP)
        float a = srow[j] * rsq + bias * l1 + mrow[j];
        buf[j] = a;
        lmax = fmaxf(lmax, a);
    }
    red[tid] = lmax; __syncthreads();
    for (int off = 128; off > 0; off >>= 1) {
        if (tid < off) red[tid] = fmaxf(red[tid], red[tid + off]);
        __syncthreads();
    }
    float M = red[0];
    __syncthreads();

    // pass 2: exp; accumulate plain sum and prior-weighted sum
    float ls = 0.0f, lw = 0.0f;
    for (int j = tid; j < S; j += 256) {
        float e = expf(buf[j] - M);
        buf[j] = e;
        ls += e;
        lw += e * (1.0f + 0.5f * prior[j]);
    }
    red[tid] = ls; __syncthreads();
    for (int off = 128; off > 0; off >>= 1) {
        if (tid < off) red[tid] += red[tid + off];
        __syncthreads();
    }
    float sum = red[0];
    __syncthreads();
    red[tid] = lw; __syncthreads();
    for (int off = 128; off > 0; off >>= 1) {
        if (tid < off) red[tid] += red[tid + off];
        __syncthreads();
    }
    float wsum = red[0];
    __syncthreads();

    // pass 3: mix plain softmax and post-steered, renormalized softmax
    float invs = 1.0f / sum;
    float invw = 1.0f / wsum;
    for (int j = tid; j < S; j += 256) {
        float e  = buf[j];
        float p  = e * invs;
        float sp = e * (1.0f + 0.5f * prior[j]) * invw;
        srow[j] = p + (sp - p) * l2;
    }
}

// ---------------- launch ----------------------------------------------------
extern "C" void kernel_launch(void* const* d_in, const int* in_sizes, int n_in,
                              void* d_out, int out_size)
{
    const float* hs    = (const float*)d_in[0];   // [1,S,HID]
    const float* mask  = (const float*)d_in[1];   // [1,1,S,S]
    const int*   pos   = (const int*)  d_in[2];   // [1,S]
    const float* Wq    = (const float*)d_in[3];   // [HID,HID]
    const float* Wk    = (const float*)d_in[4];   // [KVHID,HID]
    const float* Wv    = (const float*)d_in[5];   // [KVHID,HID]
    const float* Wo    = (const float*)d_in[6];   // [HID,HID]
    const float* prior = (const float*)d_in[7];   // [S]
    const float* m1    = (const float*)d_in[8];   // [H]
    const float* m2    = (const float*)d_in[9];   // [H]
    float* out = (float*)d_out;                   // [1,S,HID]

    float *q, *k, *v, *vT, *sc, *ctx;
    cudaGetSymbolAddress((void**)&q,   g_q);
    cudaGetSymbolAddress((void**)&k,   g_k);
    cudaGetSymbolAddress((void**)&v,   g_v);
    cudaGetSymbolAddress((void**)&vT,  g_vT);
    cudaGetSymbolAddress((void**)&sc,  g_scores);
    cudaGetSymbolAddress((void**)&ctx, g_ctx);

    dim3 blk(256);

    // 1) Q = hs @ Wq^T   [S,HID]
    sgemm_nt<<<dim3(HID / BN, S / BM, 1), blk>>>(hs, Wq, q,
        HID, HID, HID, HID, 0, 0, 0, 1);
    // 2) K = hs @ Wk^T   [S,KVHID]
    sgemm_nt<<<dim3(KVHID / BN, S / BM, 1), blk>>>(hs, Wk, k,
        HID, HID, HID, KVHID, 0, 0, 0, 1);
    // 3) V = hs @ Wv^T   [S,KVHID]
    sgemm_nt<<<dim3(KVHID / BN, S / BM, 1), blk>>>(hs, Wv, v,
        HID, HID, HID, KVHID, 0, 0, 0, 1);

    // 4) RoPE on q,k + gamma scale on k
    rope_scale_kernel<<<dim3(S, H + HKV), 64>>>(q, k, pos, prior);
    // 5) eta scale on v + transpose -> vT [KVHID, S]
    v_scale_transpose<<<dim3(S, KVHID / 128), 128>>>(v, vT, prior);

    // 6) scores[h] = Q_h @ K_{h/4}^T / (scaling applied in softmax)
    //    per head: M=S, N=S, K=D
    sgemm_nt<<<dim3(S / BN, S / BM, H), blk>>>(q, k, sc,
        D, HID, KVHID, S,
        (size_t)D, (size_t)D, (size_t)S * S, GROUPS);

    // 7) fused steering softmax (in place)
    softmax_steer<<<dim3(S, H), blk>>>(sc, mask, prior, m1, m2);

    // 8) ctx[h] = P_h @ V_{h/4}  via NT on vT: M=S, N=D, K=S
    sgemm_nt<<<dim3(D / BN, S / BM, H), blk>>>(sc, vT, ctx,
        S, S, S, HID,
        (size_t)S * S, (size_t)D * S, (size_t)D, GROUPS);

    // 9) out = ctx @ Wo^T  [S,HID]
    sgemm_nt<<<dim3(HID / BN, S / BM, 1), blk>>>(ctx, Wo, out,
        HID, HID, HID, HID, 0, 0, 0, 1);
}

// round 3
// speedup vs baseline: 2.2279x; 2.2279x over previous
#include <cuda_runtime.h>
#include <cuda_bf16.h>
#include <math.h>
#include <stdint.h>

// Problem constants (B=1)
#define S     1024
#define H     32
#define HKV   8
#define D     128
#define HID   4096
#define KVHID 1024
#define GROUPS 4

typedef __nv_bfloat16 bf16;

// ---------------- scratch (static device globals: no allocs allowed) -------
__device__ float g_q[(size_t)S * HID];
__device__ float g_k[(size_t)S * KVHID];
__device__ float g_v[(size_t)S * KVHID];
__device__ float g_scores[(size_t)H * S * S];   // 134 MB
__device__ float g_ctx[(size_t)S * HID];

__device__ bf16 g_hs_hi[(size_t)S * HID],     g_hs_lo[(size_t)S * HID];
__device__ bf16 g_wq_hi[(size_t)HID * HID],   g_wq_lo[(size_t)HID * HID];
__device__ bf16 g_wk_hi[(size_t)KVHID * HID], g_wk_lo[(size_t)KVHID * HID];
__device__ bf16 g_wv_hi[(size_t)KVHID * HID], g_wv_lo[(size_t)KVHID * HID];
__device__ bf16 g_wo_hi[(size_t)HID * HID],   g_wo_lo[(size_t)HID * HID];
__device__ bf16 g_q_hi[(size_t)S * HID],      g_q_lo[(size_t)S * HID];
__device__ bf16 g_k_hi[(size_t)S * KVHID],    g_k_lo[(size_t)S * KVHID];
__device__ bf16 g_vT_hi[(size_t)KVHID * S],   g_vT_lo[(size_t)KVHID * S];
__device__ bf16 g_p_hi[(size_t)H * S * S],    g_p_lo[(size_t)H * S * S];
__device__ bf16 g_ctx_hi[(size_t)S * HID],    g_ctx_lo[(size_t)S * HID];

// ---------------- helpers ---------------------------------------------------
__device__ __forceinline__ void split_bf16(float x, bf16& hi, bf16& lo) {
    hi = __float2bfloat16(x);
    lo = __float2bfloat16(x - __bfloat162float(hi));
}

__device__ __forceinline__ void mma16816(float* c, const uint32_t* a, const uint32_t* b) {
    asm volatile(
        "mma.sync.aligned.m16n8k16.row.col.f32.bf16.bf16.f32 "
        "{%0,%1,%2,%3}, {%4,%5,%6,%7}, {%8,%9}, {%0,%1,%2,%3};"
        : "+f"(c[0]), "+f"(c[1]), "+f"(c[2]), "+f"(c[3])
        : "r"(a[0]), "r"(a[1]), "r"(a[2]), "r"(a[3]), "r"(b[0]), "r"(b[1]));
}

__device__ __forceinline__ void cp_async16(uint32_t smem_addr, const void* gptr) {
    asm volatile("cp.async.cg.shared.global [%0], [%1], 16;"
                 :: "r"(smem_addr), "l"(gptr));
}
__device__ __forceinline__ void cp_commit() {
    asm volatile("cp.async.commit_group;" ::: "memory");
}
template <int N>
__device__ __forceinline__ void cp_wait() {
    asm volatile("cp.async.wait_group %0;" :: "n"(N) : "memory");
}

__device__ __forceinline__ uint32_t smem_u32(const void* p) {
    uint32_t a;
    asm("{ .reg .u64 t; cvta.to.shared.u64 t, %1; cvt.u32.u64 %0, t; }"
        : "=r"(a) : "l"(p));
    return a;
}

// ============ generic batched NT GEMM: fp32 via 3x bf16 HMMA ================
// C[z][m][n] = sum_k A[z][m][k]*B[z/zdivB][n][k], A/B pre-split into hi/lo.
// Block tile 128x128, BK=32. 256 threads = 8 warps (4 M x 2 N), warp 32x64.
#define SROWB 80               // padded SMEM row stride (32 bf16 -> 80 bytes)
#define ARRB  (128 * SROWB)    // 10240 B per operand array
#define STGB  (4 * ARRB)       // 40960 B per stage (Ahi|Alo|Bhi|Blo)
#define GSMEM (2 * STGB)       // 81920 B

__global__ void __launch_bounds__(256, 1) gemm_bf16x3(
    const bf16* __restrict__ Ahi, const bf16* __restrict__ Alo,
    const bf16* __restrict__ Bhi, const bf16* __restrict__ Blo,
    float* __restrict__ C, int K, int lda, int ldb, int ldc,
    size_t sA, size_t sB, size_t sC, int zdivB)
{
    extern __shared__ char smem[];
    const uint32_t smem_b = smem_u32(smem);
    const int tid = threadIdx.x;
    const int wid = tid >> 5;
    const int lane = tid & 31;
    const int g  = lane >> 2;     // 0..7
    const int tc = lane & 3;      // 0..3
    const int warp_m = wid & 3;   // 4 warps along M (32 rows each)
    const int warp_n = wid >> 2;  // 2 warps along N (64 cols each)

    const size_t zoffA = (size_t)blockIdx.z * sA + (size_t)blockIdx.y * 128 * lda;
    const size_t zoffB = (size_t)(blockIdx.z / zdivB) * sB + (size_t)blockIdx.x * 128 * ldb;
    Ahi += zoffA; Alo += zoffA;
    Bhi += zoffB; Blo += zoffB;
    C += (size_t)blockIdx.z * sC;

    // per-thread load slots: 2 chunks of 16B per operand array
    const int r0 = tid >> 2;            // idx = tid      -> row tid>>2,      c tid&3
    const int c0 = tid & 3;
    const int r1 = (tid + 256) >> 2;    // idx = tid+256
    const int c1 = c0;                  // (tid+256)&3 == tid&3

    const uint32_t sts0 = r0 * SROWB + c0 * 16;
    const uint32_t sts1 = r1 * SROWB + c1 * 16;

    float acc[2][8][4];
#pragma unroll
    for (int i = 0; i < 2; i++)
#pragma unroll
        for (int j = 0; j < 8; j++)
#pragma unroll
            for (int e = 0; e < 4; e++) acc[i][j][e] = 0.0f;

    const int KT = K / 32;

    // issue loads for one stage
    auto issue_stage = [&](int kt, int s) {
        const uint32_t sb = smem_b + s * STGB;
        int kk = kt * 32;
        cp_async16(sb + 0*ARRB + sts0, Ahi + (size_t)r0 * lda + kk + c0 * 8);
        cp_async16(sb + 0*ARRB + sts1, Ahi + (size_t)r1 * lda + kk + c1 * 8);
        cp_async16(sb + 1*ARRB + sts0, Alo + (size_t)r0 * lda + kk + c0 * 8);
        cp_async16(sb + 1*ARRB + sts1, Alo + (size_t)r1 * lda + kk + c1 * 8);
        cp_async16(sb + 2*ARRB + sts0, Bhi + (size_t)r0 * ldb + kk + c0 * 8);
        cp_async16(sb + 2*ARRB + sts1, Bhi + (size_t)r1 * ldb + kk + c1 * 8);
        cp_async16(sb + 3*ARRB + sts0, Blo + (size_t)r0 * ldb + kk + c0 * 8);
        cp_async16(sb + 3*ARRB + sts1, Blo + (size_t)r1 * ldb + kk + c1 * 8);
        cp_commit();
    };

    issue_stage(0, 0);

    for (int kt = 0; kt < KT; kt++) {
        const int s = kt & 1;
        if (kt + 1 < KT) {
            issue_stage(kt + 1, s ^ 1);
            cp_wait<1>();
        } else {
            cp_wait<0>();
        }
        __syncthreads();

        const char* sa_hi = smem + s * STGB + 0 * ARRB;
        const char* sa_lo = smem + s * STGB + 1 * ARRB;
        const char* sb_hi = smem + s * STGB + 2 * ARRB;
        const char* sb_lo = smem + s * STGB + 3 * ARRB;

#pragma unroll
        for (int ks = 0; ks < 2; ks++) {
            const int ka = ks * 32 + tc * 4;   // byte offset within row

            uint32_t AH[2][4], AL[2][4];
#pragma unroll
            for (int mt = 0; mt < 2; mt++) {
                int rr = warp_m * 32 + mt * 16 + g;
                AH[mt][0] = *(const uint32_t*)(sa_hi + rr * SROWB + ka);
                AH[mt][1] = *(const uint32_t*)(sa_hi + (rr + 8) * SROWB + ka);
                AH[mt][2] = *(const uint32_t*)(sa_hi + rr * SROWB + ka + 16);
                AH[mt][3] = *(const uint32_t*)(sa_hi + (rr + 8) * SROWB + ka + 16);
                AL[mt][0] = *(const uint32_t*)(sa_lo + rr * SROWB + ka);
                AL[mt][1] = *(const uint32_t*)(sa_lo + (rr + 8) * SROWB + ka);
                AL[mt][2] = *(const uint32_t*)(sa_lo + rr * SROWB + ka + 16);
                AL[mt][3] = *(const uint32_t*)(sa_lo + (rr + 8) * SROWB + ka + 16);
            }
            uint32_t BH[8][2], BL[8][2];
#pragma unroll
            for (int nt = 0; nt < 8; nt++) {
                int cc = warp_n * 64 + nt * 8 + g;
                BH[nt][0] = *(const uint32_t*)(sb_hi + cc * SROWB + ka);
                BH[nt][1] = *(const uint32_t*)(sb_hi + cc * SROWB + ka + 16);
                BL[nt][0] = *(const uint32_t*)(sb_lo + cc * SROWB + ka);
                BL[nt][1] = *(const uint32_t*)(sb_lo + cc * SROWB + ka + 16);
            }
#pragma unroll
            for (int mt = 0; mt < 2; mt++)
#pragma unroll
                for (int nt = 0; nt < 8; nt++) {
                    mma16816(acc[mt][nt], AH[mt], BH[nt]);
                    mma16816(acc[mt][nt], AH[mt], BL[nt]);
                    mma16816(acc[mt][nt], AL[mt], BH[nt]);
                }
        }
        __syncthreads();
    }

    // epilogue: direct GMEM stores (float2, 32B-sector friendly)
    const int rowb = blockIdx.y * 128 + warp_m * 32;
    const int colb = blockIdx.x * 128 + warp_n * 64;
#pragma unroll
    for (int mt = 0; mt < 2; mt++) {
#pragma unroll
        for (int nt = 0; nt < 8; nt++) {
            int rr = rowb + mt * 16 + g;
            int cc = colb + nt * 8 + tc * 2;
            *(float2*)(C + (size_t)rr * ldc + cc) =
                make_float2(acc[mt][nt][0], acc[mt][nt][1]);
            *(float2*)(C + (size_t)(rr + 8) * ldc + cc) =
                make_float2(acc[mt][nt][2], acc[mt][nt][3]);
        }
    }
}

// ---------------- fp32 -> bf16 hi/lo split (elementwise) -------------------
__global__ void split_kernel(const float* __restrict__ src,
                             bf16* __restrict__ hi, bf16* __restrict__ lo, int n)
{
    int i = blockIdx.x * blockDim.x + threadIdx.x;
    if (i < n) {
        bf16 h, l;
        split_bf16(src[i], h, l);
        hi[i] = h; lo[i] = l;
    }
}

// ---------------- RoPE + gamma steering; emits bf16 hi/lo ------------------
__global__ void rope_scale_kernel(const float* __restrict__ q, const float* __restrict__ k,
                                  const int* __restrict__ pos,
                                  const float* __restrict__ prior,
                                  bf16* __restrict__ qhi, bf16* __restrict__ qlo,
                                  bf16* __restrict__ khi, bf16* __restrict__ klo)
{
    int s = blockIdx.x;
    int h = blockIdx.y;
    int d = threadIdx.x;   // 0..63

    float p = (float)pos[s];
    float inv = powf(10000.0f, -(2.0f * (float)d) / 128.0f);
    float sn, c;
    sincosf(p * inv, &sn, &c);

    if (h < H) {
        size_t base = (size_t)s * HID + h * D;
        float x1 = q[base + d], x2 = q[base + d + 64];
        float y1 = x1 * c - x2 * sn;
        float y2 = x2 * c + x1 * sn;
        bf16 hh, ll;
        split_bf16(y1, hh, ll); qhi[base + d] = hh;      qlo[base + d] = ll;
        split_bf16(y2, hh, ll); qhi[base + d + 64] = hh; qlo[base + d + 64] = ll;
    } else {
        size_t base = (size_t)s * KVHID + (h - H) * D;
        float gg = 1.0f + 0.5f * prior[s];
        float scale = fminf(fmaxf(gg, 0.5f), 2.0f);
        float x1 = k[base + d], x2 = k[base + d + 64];
        float y1 = (x1 * c - x2 * sn) * scale;
        float y2 = (x2 * c + x1 * sn) * scale;
        bf16 hh, ll;
        split_bf16(y1, hh, ll); khi[base + d] = hh;      klo[base + d] = ll;
        split_bf16(y2, hh, ll); khi[base + d + 64] = hh; klo[base + d + 64] = ll;
    }
}

// ---------------- v: eta scale + transpose; emits bf16 hi/lo ---------------
__global__ void v_scale_transpose(const float* __restrict__ v,
                                  bf16* __restrict__ vThi, bf16* __restrict__ vTlo,
                                  const float* __restrict__ prior)
{
    int s = blockIdx.x;
    int c = blockIdx.y * 128 + threadIdx.x;
    float e = 1.0f + 0.5f * prior[s];
    float eta = fminf(fmaxf(e, 0.5f), 2.0f);
    bf16 hh, ll;
    split_bf16(v[(size_t)s * KVHID + c] * eta, hh, ll);
    vThi[(size_t)c * S + s] = hh;
    vTlo[(size_t)c * S + s] = ll;
}

// ---------------- fused steering softmax; emits bf16 hi/lo probs -----------
__global__ __launch_bounds__(256) void softmax_steer(
    const float* __restrict__ scores, const float* __restrict__ mask,
    const float* __restrict__ prior, const float* __restrict__ m1,
    const float* __restrict__ m2,
    bf16* __restrict__ phi, bf16* __restrict__ plo)
{
    int row = blockIdx.x;
    int h   = blockIdx.y;
    const float* srow = scores + ((size_t)h * S + row) * S;
    const float* mrow = mask + (size_t)row * S;

    __shared__ float buf[S];
    __shared__ float red[256];
    int tid = threadIdx.x;

    float l1 = m1[h], l2 = m2[h];
    const float rsq = 0.08838834764831845f;   // 1/sqrt(128)

    float lmax = -1e30f;
    for (int j = tid; j < S; j += 256) {
        float pj = prior[j];
        float bias = fminf(fmaxf(pj, -5.0f), 5.0f);
        float a = srow[j] * rsq + bias * l1 + mrow[j];
        buf[j] = a;
        lmax = fmaxf(lmax, a);
    }
    red[tid] = lmax; __syncthreads();
    for (int off = 128; off > 0; off >>= 1) {
        if (tid < off) red[tid] = fmaxf(red[tid], red[tid + off]);
        __syncthreads();
    }
    float M = red[0];
    __syncthreads();

    float ls = 0.0f, lw = 0.0f;
    for (int j = tid; j < S; j += 256) {
        float e = expf(buf[j] - M);
        buf[j] = e;
        ls += e;
        lw += e * (1.0f + 0.5f * prior[j]);
    }
    red[tid] = ls; __syncthreads();
    for (int off = 128; off > 0; off >>= 1) {
        if (tid < off) red[tid] += red[tid + off];
        __syncthreads();
    }
    float sum = red[0];
    __syncthreads();
    red[tid] = lw; __syncthreads();
    for (int off = 128; off > 0; off >>= 1) {
        if (tid < off) red[tid] += red[tid + off];
        __syncthreads();
    }
    float wsum = red[0];
    __syncthreads();

    float invs = 1.0f / sum;
    float invw = 1.0f / wsum;
    size_t obase = ((size_t)h * S + row) * S;
    for (int j = tid; j < S; j += 256) {
        float e  = buf[j];
        float p  = e * invs;
        float sp = e * (1.0f + 0.5f * prior[j]) * invw;
        float pf = p + (sp - p) * l2;
        bf16 hh, ll;
        split_bf16(pf, hh, ll);
        phi[obase + j] = hh;
        plo[obase + j] = ll;
    }
}

// ---------------- launch ----------------------------------------------------
extern "C" void kernel_launch(void* const* d_in, const int* in_sizes, int n_in,
                              void* d_out, int out_size)
{
    const float* hs    = (const float*)d_in[0];
    const float* mask  = (const float*)d_in[1];
    const int*   pos   = (const int*)  d_in[2];
    const float* Wq    = (const float*)d_in[3];
    const float* Wk    = (const float*)d_in[4];
    const float* Wv    = (const float*)d_in[5];
    const float* Wo    = (const float*)d_in[6];
    const float* prior = (const float*)d_in[7];
    const float* m1    = (const float*)d_in[8];
    const float* m2    = (const float*)d_in[9];
    float* out = (float*)d_out;

    float *q, *k, *v, *sc, *ctx;
    bf16 *hshi, *hslo, *wqhi, *wqlo, *wkhi, *wklo, *wvhi, *wvlo, *wohi, *wolo;
    bf16 *qhi, *qlo, *khi, *klo, *vthi, *vtlo, *phi, *plo, *cxhi, *cxlo;
    cudaGetSymbolAddress((void**)&q,    g_q);
    cudaGetSymbolAddress((void**)&k,    g_k);
    cudaGetSymbolAddress((void**)&v,    g_v);
    cudaGetSymbolAddress((void**)&sc,   g_scores);
    cudaGetSymbolAddress((void**)&ctx,  g_ctx);
    cudaGetSymbolAddress((void**)&hshi, g_hs_hi); cudaGetSymbolAddress((void**)&hslo, g_hs_lo);
    cudaGetSymbolAddress((void**)&wqhi, g_wq_hi); cudaGetSymbolAddress((void**)&wqlo, g_wq_lo);
    cudaGetSymbolAddress((void**)&wkhi, g_wk_hi); cudaGetSymbolAddress((void**)&wklo, g_wk_lo);
    cudaGetSymbolAddress((void**)&wvhi, g_wv_hi); cudaGetSymbolAddress((void**)&wvlo, g_wv_lo);
    cudaGetSymbolAddress((void**)&wohi, g_wo_hi); cudaGetSymbolAddress((void**)&wolo, g_wo_lo);
    cudaGetSymbolAddress((void**)&qhi,  g_q_hi);  cudaGetSymbolAddress((void**)&qlo,  g_q_lo);
    cudaGetSymbolAddress((void**)&khi,  g_k_hi);  cudaGetSymbolAddress((void**)&klo,  g_k_lo);
    cudaGetSymbolAddress((void**)&vthi, g_vT_hi); cudaGetSymbolAddress((void**)&vtlo, g_vT_lo);
    cudaGetSymbolAddress((void**)&phi,  g_p_hi);  cudaGetSymbolAddress((void**)&plo,  g_p_lo);
    cudaGetSymbolAddress((void**)&cxhi, g_ctx_hi); cudaGetSymbolAddress((void**)&cxlo, g_ctx_lo);

    static int configured = 0;
    if (!configured) {
        cudaFuncSetAttribute(gemm_bf16x3, cudaFuncAttributeMaxDynamicSharedMemorySize, GSMEM);
        configured = 1;
    }

    dim3 blk(256);

    // 0) split inputs to bf16 hi/lo
    split_kernel<<<(S * HID + 255) / 256, 256>>>(hs, hshi, hslo, S * HID);
    split_kernel<<<(HID * HID + 255) / 256, 256>>>(Wq, wqhi, wqlo, HID * HID);
    split_kernel<<<(KVHID * HID + 255) / 256, 256>>>(Wk, wkhi, wklo, KVHID * HID);
    split_kernel<<<(KVHID * HID + 255) / 256, 256>>>(Wv, wvhi, wvlo, KVHID * HID);
    split_kernel<<<(HID * HID + 255) / 256, 256>>>(Wo, wohi, wolo, HID * HID);

    // 1-3) projections (fp32 out)
    gemm_bf16x3<<<dim3(HID / 128, S / 128, 1), blk, GSMEM>>>(
        hshi, hslo, wqhi, wqlo, q, HID, HID, HID, HID, 0, 0, 0, 1);
    gemm_bf16x3<<<dim3(KVHID / 128, S / 128, 1), blk, GSMEM>>>(
        hshi, hslo, wkhi, wklo, k, HID, HID, HID, KVHID, 0, 0, 0, 1);
    gemm_bf16x3<<<dim3(KVHID / 128, S / 128, 1), blk, GSMEM>>>(
        hshi, hslo, wvhi, wvlo, v, HID, HID, HID, KVHID, 0, 0, 0, 1);

    // 4) RoPE + gamma; emit q/k hi/lo
    rope_scale_kernel<<<dim3(S, H + HKV), 64>>>(q, k, pos, prior, qhi, qlo, khi, klo);
    // 5) eta scale + transpose; emit vT hi/lo
    v_scale_transpose<<<dim3(S, KVHID / 128), 128>>>(v, vthi, vtlo, prior);

    // 6) scores[h] = Q_h @ K_{h/4}^T (fp32)
    gemm_bf16x3<<<dim3(S / 128, S / 128, H), blk, GSMEM>>>(
        qhi, qlo, khi, klo, sc, D, HID, KVHID, S,
        (size_t)D, (size_t)D, (size_t)S * S, GROUPS);

    // 7) fused steering softmax -> probs hi/lo
    softmax_steer<<<dim3(S, H), blk>>>(sc, mask, prior, m1, m2, phi, plo);

    // 8) ctx[h] = P_h @ V_{h/4} (NT on vT): M=S, N=D, K=S
    gemm_bf16x3<<<dim3(D / 128, S / 128, H), blk, GSMEM>>>(
        phi, plo, vthi, vtlo, ctx, S, S, S, HID,
        (size_t)S * S, (size_t)D * S, (size_t)D, GROUPS);

    // 8b) split ctx
    split_kernel<<<(S * HID + 255) / 256, 256>>>(ctx, cxhi, cxlo, S * HID);

    // 9) out = ctx @ Wo^T
    gemm_bf16x3<<<dim3(HID / 128, S / 128, 1), blk, GSMEM>>>(
        cxhi, cxlo, wohi, wolo, out, HID, HID, HID, HID, 0, 0, 0, 1);
}

// round 4
// speedup vs baseline: 2.4273x; 1.0895x over previous
#include <cuda_runtime.h>
#include <cuda_bf16.h>
#include <math.h>
#include <stdint.h>

// Problem constants (B=1)
#define S     1024
#define H     32
#define HKV   8
#define D     128
#define HID   4096
#define KVHID 1024
#define GROUPS 4

typedef __nv_bfloat16 bf16;

// ---------------- scratch (static device globals: no allocs allowed) -------
__device__ float g_q[(size_t)S * HID];
__device__ float g_k[(size_t)S * KVHID];
__device__ float g_v[(size_t)S * KVHID];
__device__ float g_scores[(size_t)H * S * S];   // 134 MB

__device__ bf16 g_hs_hi[(size_t)S * HID],     g_hs_lo[(size_t)S * HID];
__device__ bf16 g_wq_hi[(size_t)HID * HID],   g_wq_lo[(size_t)HID * HID];
__device__ bf16 g_wk_hi[(size_t)KVHID * HID], g_wk_lo[(size_t)KVHID * HID];
__device__ bf16 g_wv_hi[(size_t)KVHID * HID], g_wv_lo[(size_t)KVHID * HID];
__device__ bf16 g_wo_hi[(size_t)HID * HID],   g_wo_lo[(size_t)HID * HID];
__device__ bf16 g_q_hi[(size_t)S * HID],      g_q_lo[(size_t)S * HID];
__device__ bf16 g_k_hi[(size_t)S * KVHID],    g_k_lo[(size_t)S * KVHID];
__device__ bf16 g_vT_hi[(size_t)KVHID * S],   g_vT_lo[(size_t)KVHID * S];
__device__ bf16 g_p_hi[(size_t)H * S * S],    g_p_lo[(size_t)H * S * S];
__device__ bf16 g_ctx_hi[(size_t)S * HID],    g_ctx_lo[(size_t)S * HID];

// ---------------- helpers ---------------------------------------------------
__device__ __forceinline__ void split_bf16(float x, bf16& hi, bf16& lo) {
    hi = __float2bfloat16(x);
    lo = __float2bfloat16(x - __bfloat162float(hi));
}

__device__ __forceinline__ void mma16816(float* c, const uint32_t* a, const uint32_t* b) {
    asm volatile(
        "mma.sync.aligned.m16n8k16.row.col.f32.bf16.bf16.f32 "
        "{%0,%1,%2,%3}, {%4,%5,%6,%7}, {%8,%9}, {%0,%1,%2,%3};"
        : "+f"(c[0]), "+f"(c[1]), "+f"(c[2]), "+f"(c[3])
        : "r"(a[0]), "r"(a[1]), "r"(a[2]), "r"(a[3]), "r"(b[0]), "r"(b[1]));
}

__device__ __forceinline__ void cp_async16(uint32_t smem_addr, const void* gptr) {
    asm volatile("cp.async.cg.shared.global [%0], [%1], 16;"
                 :: "r"(smem_addr), "l"(gptr));
}
__device__ __forceinline__ void cp_commit() {
    asm volatile("cp.async.commit_group;" ::: "memory");
}
template <int N>
__device__ __forceinline__ void cp_wait() {
    asm volatile("cp.async.wait_group %0;" :: "n"(N) : "memory");
}

__device__ __forceinline__ uint32_t smem_u32(const void* p) {
    uint32_t a;
    asm("{ .reg .u64 t; cvta.to.shared.u64 t, %1; cvt.u32.u64 %0, t; }"
        : "=r"(a) : "l"(p));
    return a;
}

// ============ generic batched NT GEMM: fp32 via 3x bf16 HMMA ================
// C[z][m][n] = sum_k A[z][m][k]*B[z/zdivB][n][k], A/B pre-split into hi/lo.
// Block tile 128x128, BK=32, 4-stage cp.async pipeline, one sync per K-tile.
// 256 threads = 8 warps (4 M x 2 N), warp tile 32x64.
// causal_mode: 0 = none; 1 = skip tiles with bx > by (scores);
//              2 = clamp K-loop to (by+1)*128 keys (PV).
#define SROWB 80               // padded SMEM row stride (32 bf16 -> 80 bytes)
#define ARRB  (128 * SROWB)    // 10240 B per operand array
#define STGB  (4 * ARRB)       // 40960 B per stage (Ahi|Alo|Bhi|Blo)
#define STAGES 4
#define GSMEM (STAGES * STGB)  // 163840 B

__global__ void __launch_bounds__(256, 1) gemm_bf16x3(
    const bf16* __restrict__ Ahi, const bf16* __restrict__ Alo,
    const bf16* __restrict__ Bhi, const bf16* __restrict__ Blo,
    float* __restrict__ C, bf16* __restrict__ Chi, bf16* __restrict__ Clo,
    int K, int lda, int ldb, int ldc,
    size_t sA, size_t sB, size_t sC, int zdivB, int causal_mode)
{
    if (causal_mode == 1 && blockIdx.x > blockIdx.y) return;

    int KT = K / 32;
    if (causal_mode == 2) {
        int kt_max = (blockIdx.y + 1) * 4;   // (by+1)*128 keys / 32
        if (KT > kt_max) KT = kt_max;
    }

    extern __shared__ char smem[];
    const uint32_t smem_b = smem_u32(smem);
    const int tid = threadIdx.x;
    const int wid = tid >> 5;
    const int lane = tid & 31;
    const int g  = lane >> 2;     // 0..7
    const int tc = lane & 3;      // 0..3
    const int warp_m = wid & 3;   // 4 warps along M (32 rows each)
    const int warp_n = wid >> 2;  // 2 warps along N (64 cols each)

    const size_t zoffA = (size_t)blockIdx.z * sA + (size_t)blockIdx.y * 128 * lda;
    const size_t zoffB = (size_t)(blockIdx.z / zdivB) * sB + (size_t)blockIdx.x * 128 * ldb;
    Ahi += zoffA; Alo += zoffA;
    Bhi += zoffB; Blo += zoffB;

    // per-thread load slots: 2 chunks of 16B per operand array
    const int r0 = tid >> 2;
    const int c0 = tid & 3;
    const int r1 = (tid + 256) >> 2;
    const int c1 = c0;

    const uint32_t sts0 = r0 * SROWB + c0 * 16;
    const uint32_t sts1 = r1 * SROWB + c1 * 16;

    float acc[2][8][4];
#pragma unroll
    for (int i = 0; i < 2; i++)
#pragma unroll
        for (int j = 0; j < 8; j++)
#pragma unroll
            for (int e = 0; e < 4; e++) acc[i][j][e] = 0.0f;

    auto issue_stage = [&](int kt, int s) {
        const uint32_t sb = smem_b + s * STGB;
        int kk = kt * 32;
        cp_async16(sb + 0*ARRB + sts0, Ahi + (size_t)r0 * lda + kk + c0 * 8);
        cp_async16(sb + 0*ARRB + sts1, Ahi + (size_t)r1 * lda + kk + c1 * 8);
        cp_async16(sb + 1*ARRB + sts0, Alo + (size_t)r0 * lda + kk + c0 * 8);
        cp_async16(sb + 1*ARRB + sts1, Alo + (size_t)r1 * lda + kk + c1 * 8);
        cp_async16(sb + 2*ARRB + sts0, Bhi + (size_t)r0 * ldb + kk + c0 * 8);
        cp_async16(sb + 2*ARRB + sts1, Bhi + (size_t)r1 * ldb + kk + c1 * 8);
        cp_async16(sb + 3*ARRB + sts0, Blo + (size_t)r0 * ldb + kk + c0 * 8);
        cp_async16(sb + 3*ARRB + sts1, Blo + (size_t)r1 * ldb + kk + c1 * 8);
    };

    // prologue: fill STAGES-1 stages
#pragma unroll
    for (int p = 0; p < STAGES - 1; p++) {
        if (p < KT) issue_stage(p, p);
        cp_commit();
    }

    for (int kt = 0; kt < KT; kt++) {
        const int s = kt & (STAGES - 1);
        cp_wait<STAGES - 2>();
        __syncthreads();

        // issue next stage early (stage (kt+3)&3 was fully consumed at kt-1,
        // and everyone passed the barrier above)
        int nk = kt + STAGES - 1;
        if (nk < KT) issue_stage(nk, nk & (STAGES - 1));
        cp_commit();

        const char* sa_hi = smem + s * STGB + 0 * ARRB;
        const char* sa_lo = smem + s * STGB + 1 * ARRB;
        const char* sb_hi = smem + s * STGB + 2 * ARRB;
        const char* sb_lo = smem + s * STGB + 3 * ARRB;

#pragma unroll
        for (int ks = 0; ks < 2; ks++) {
            const int ka = ks * 32 + tc * 4;   // byte offset within row

            uint32_t AH[2][4], AL[2][4];
#pragma unroll
            for (int mt = 0; mt < 2; mt++) {
                int rr = warp_m * 32 + mt * 16 + g;
                AH[mt][0] = *(const uint32_t*)(sa_hi + rr * SROWB + ka);
                AH[mt][1] = *(const uint32_t*)(sa_hi + (rr + 8) * SROWB + ka);
                AH[mt][2] = *(const uint32_t*)(sa_hi + rr * SROWB + ka + 16);
                AH[mt][3] = *(const uint32_t*)(sa_hi + (rr + 8) * SROWB + ka + 16);
                AL[mt][0] = *(const uint32_t*)(sa_lo + rr * SROWB + ka);
                AL[mt][1] = *(const uint32_t*)(sa_lo + (rr + 8) * SROWB + ka);
                AL[mt][2] = *(const uint32_t*)(sa_lo + rr * SROWB + ka + 16);
                AL[mt][3] = *(const uint32_t*)(sa_lo + (rr + 8) * SROWB + ka + 16);
            }
            uint32_t BH[8][2], BL[8][2];
#pragma unroll
            for (int nt = 0; nt < 8; nt++) {
                int cc = warp_n * 64 + nt * 8 + g;
                BH[nt][0] = *(const uint32_t*)(sb_hi + cc * SROWB + ka);
                BH[nt][1] = *(const uint32_t*)(sb_hi + cc * SROWB + ka + 16);
                BL[nt][0] = *(const uint32_t*)(sb_lo + cc * SROWB + ka);
                BL[nt][1] = *(const uint32_t*)(sb_lo + cc * SROWB + ka + 16);
            }
#pragma unroll
            for (int mt = 0; mt < 2; mt++)
#pragma unroll
                for (int nt = 0; nt < 8; nt++) {
                    mma16816(acc[mt][nt], AH[mt], BH[nt]);
                    mma16816(acc[mt][nt], AH[mt], BL[nt]);
                    mma16816(acc[mt][nt], AL[mt], BH[nt]);
                }
        }
        __syncthreads();
    }

    // epilogue
    const int rowb = blockIdx.y * 128 + warp_m * 32;
    const int colb = blockIdx.x * 128 + warp_n * 64;
    if (C) {
        float* Cz = C + (size_t)blockIdx.z * sC;
#pragma unroll
        for (int mt = 0; mt < 2; mt++)
#pragma unroll
            for (int nt = 0; nt < 8; nt++) {
                int rr = rowb + mt * 16 + g;
                int cc = colb + nt * 8 + tc * 2;
                *(float2*)(Cz + (size_t)rr * ldc + cc) =
                    make_float2(acc[mt][nt][0], acc[mt][nt][1]);
                *(float2*)(Cz + (size_t)(rr + 8) * ldc + cc) =
                    make_float2(acc[mt][nt][2], acc[mt][nt][3]);
            }
    }
    if (Chi) {
        bf16* Hz = Chi + (size_t)blockIdx.z * sC;
        bf16* Lz = Clo + (size_t)blockIdx.z * sC;
#pragma unroll
        for (int mt = 0; mt < 2; mt++)
#pragma unroll
            for (int nt = 0; nt < 8; nt++) {
                int rr = rowb + mt * 16 + g;
                int cc = colb + nt * 8 + tc * 2;
                bf16 h0, l0, h1, l1;
#pragma unroll
                for (int half = 0; half < 2; half++) {
                    int r2 = rr + half * 8;
                    split_bf16(acc[mt][nt][half * 2 + 0], h0, l0);
                    split_bf16(acc[mt][nt][half * 2 + 1], h1, l1);
                    *(__nv_bfloat162*)(Hz + (size_t)r2 * ldc + cc) =
                        __nv_bfloat162(h0, h1);
                    *(__nv_bfloat162*)(Lz + (size_t)r2 * ldc + cc) =
                        __nv_bfloat162(l0, l1);
                }
            }
    }
}

// ---------------- fp32 -> bf16 hi/lo split (elementwise) -------------------
__global__ void split_kernel(const float* __restrict__ src,
                             bf16* __restrict__ hi, bf16* __restrict__ lo, int n)
{
    int i = blockIdx.x * blockDim.x + threadIdx.x;
    if (i < n) {
        bf16 h, l;
        split_bf16(src[i], h, l);
        hi[i] = h; lo[i] = l;
    }
}

// ---------------- RoPE + gamma steering; emits bf16 hi/lo ------------------
__global__ void rope_scale_kernel(const float* __restrict__ q, const float* __restrict__ k,
                                  const int* __restrict__ pos,
                                  const float* __restrict__ prior,
                                  bf16* __restrict__ qhi, bf16* __restrict__ qlo,
                                  bf16* __restrict__ khi, bf16* __restrict__ klo)
{
    int s = blockIdx.x;
    int h = blockIdx.y;
    int d = threadIdx.x;   // 0..63

    float p = (float)pos[s];
    float inv = powf(10000.0f, -(2.0f * (float)d) / 128.0f);
    float sn, c;
    sincosf(p * inv, &sn, &c);

    if (h < H) {
        size_t base = (size_t)s * HID + h * D;
        float x1 = q[base + d], x2 = q[base + d + 64];
        float y1 = x1 * c - x2 * sn;
        float y2 = x2 * c + x1 * sn;
        bf16 hh, ll;
        split_bf16(y1, hh, ll); qhi[base + d] = hh;      qlo[base + d] = ll;
        split_bf16(y2, hh, ll); qhi[base + d + 64] = hh; qlo[base + d + 64] = ll;
    } else {
        size_t base = (size_t)s * KVHID + (h - H) * D;
        float gg = 1.0f + 0.5f * prior[s];
        float scale = fminf(fmaxf(gg, 0.5f), 2.0f);
        float x1 = k[base + d], x2 = k[base + d + 64];
        float y1 = (x1 * c - x2 * sn) * scale;
        float y2 = (x2 * c + x1 * sn) * scale;
        bf16 hh, ll;
        split_bf16(y1, hh, ll); khi[base + d] = hh;      klo[base + d] = ll;
        split_bf16(y2, hh, ll); khi[base + d + 64] = hh; klo[base + d + 64] = ll;
    }
}

// ---------------- v: eta scale + transpose; emits bf16 hi/lo ---------------
__global__ void v_scale_transpose(const float* __restrict__ v,
                                  bf16* __restrict__ vThi, bf16* __restrict__ vTlo,
                                  const float* __restrict__ prior)
{
    int s = blockIdx.x;
    int c = blockIdx.y * 128 + threadIdx.x;
    float e = 1.0f + 0.5f * prior[s];
    float eta = fminf(fmaxf(e, 0.5f), 2.0f);
    bf16 hh, ll;
    split_bf16(v[(size_t)s * KVHID + c] * eta, hh, ll);
    vThi[(size_t)c * S + s] = hh;
    vTlo[(size_t)c * S + s] = ll;
}

// ---------------- fused steering softmax (causal, arithmetic mask) ---------
// probs for j > row are exactly 0 (reference: exp(x-1e9-M) underflows to 0).
__global__ __launch_bounds__(256) void softmax_steer(
    const float* __restrict__ scores,
    const float* __restrict__ prior, const float* __restrict__ m1,
    const float* __restrict__ m2,
    bf16* __restrict__ phi, bf16* __restrict__ plo)
{
    int row = blockIdx.x;
    int h   = blockIdx.y;
    const float* srow = scores + ((size_t)h * S + row) * S;
    const int n = row + 1;                // valid keys: 0..row

    __shared__ float buf[S];
    __shared__ float red[256];
    int tid = threadIdx.x;

    float l1 = m1[h], l2 = m2[h];
    const float rsq = 0.08838834764831845f;   // 1/sqrt(128)

    float lmax = -1e30f;
    for (int j = tid; j < n; j += 256) {
        float pj = prior[j];
        float bias = fminf(fmaxf(pj, -5.0f), 5.0f);
        float a = srow[j] * rsq + bias * l1;
        buf[j] = a;
        lmax = fmaxf(lmax, a);
    }
    red[tid] = lmax; __syncthreads();
    for (int off = 128; off > 0; off >>= 1) {
        if (tid < off) red[tid] = fmaxf(red[tid], red[tid + off]);
        __syncthreads();
    }
    float M = red[0];
    __syncthreads();

    float ls = 0.0f, lw = 0.0f;
    for (int j = tid; j < n; j += 256) {
        float e = expf(buf[j] - M);
        buf[j] = e;
        ls += e;
        lw += e * (1.0f + 0.5f * prior[j]);
    }
    red[tid] = ls; __syncthreads();
    for (int off = 128; off > 0; off >>= 1) {
        if (tid < off) red[tid] += red[tid + off];
        __syncthreads();
    }
    float sum = red[0];
    __syncthreads();
    red[tid] = lw; __syncthreads();
    for (int off = 128; off > 0; off >>= 1) {
        if (tid < off) red[tid] += red[tid + off];
        __syncthreads();
    }
    float wsum = red[0];
    __syncthreads();

    float invs = 1.0f / sum;
    float invw = 1.0f / wsum;
    size_t obase = ((size_t)h * S + row) * S;
    for (int j = tid; j < n; j += 256) {
        float e  = buf[j];
        float p  = e * invs;
        float sp = e * (1.0f + 0.5f * prior[j]) * invw;
        float pf = p + (sp - p) * l2;
        bf16 hh, ll;
        split_bf16(pf, hh, ll);
        phi[obase + j] = hh;
        plo[obase + j] = ll;
    }
    // zero the masked region (PV reads full 128-wide key tiles)
    const bf16 z = __float2bfloat16(0.0f);
    for (int j = n + tid; j < S; j += 256) {
        phi[obase + j] = z;
        plo[obase + j] = z;
    }
}

// ---------------- launch ----------------------------------------------------
extern "C" void kernel_launch(void* const* d_in, const int* in_sizes, int n_in,
                              void* d_out, int out_size)
{
    const float* hs    = (const float*)d_in[0];
    const int*   pos   = (const int*)  d_in[2];
    const float* Wq    = (const float*)d_in[3];
    const float* Wk    = (const float*)d_in[4];
    const float* Wv    = (const float*)d_in[5];
    const float* Wo    = (const float*)d_in[6];
    const float* prior = (const float*)d_in[7];
    const float* m1    = (const float*)d_in[8];
    const float* m2    = (const float*)d_in[9];
    float* out = (float*)d_out;

    float *q, *k, *v, *sc;
    bf16 *hshi, *hslo, *wqhi, *wqlo, *wkhi, *wklo, *wvhi, *wvlo, *wohi, *wolo;
    bf16 *qhi, *qlo, *khi, *klo, *vthi, *vtlo, *phi, *plo, *cxhi, *cxlo;
    cudaGetSymbolAddress((void**)&q,    g_q);
    cudaGetSymbolAddress((void**)&k,    g_k);
    cudaGetSymbolAddress((void**)&v,    g_v);
    cudaGetSymbolAddress((void**)&sc,   g_scores);
    cudaGetSymbolAddress((void**)&hshi, g_hs_hi); cudaGetSymbolAddress((void**)&hslo, g_hs_lo);
    cudaGetSymbolAddress((void**)&wqhi, g_wq_hi); cudaGetSymbolAddress((void**)&wqlo, g_wq_lo);
    cudaGetSymbolAddress((void**)&wkhi, g_wk_hi); cudaGetSymbolAddress((void**)&wklo, g_wk_lo);
    cudaGetSymbolAddress((void**)&wvhi, g_wv_hi); cudaGetSymbolAddress((void**)&wvlo, g_wv_lo);
    cudaGetSymbolAddress((void**)&wohi, g_wo_hi); cudaGetSymbolAddress((void**)&wolo, g_wo_lo);
    cudaGetSymbolAddress((void**)&qhi,  g_q_hi);  cudaGetSymbolAddress((void**)&qlo,  g_q_lo);
    cudaGetSymbolAddress((void**)&khi,  g_k_hi);  cudaGetSymbolAddress((void**)&klo,  g_k_lo);
    cudaGetSymbolAddress((void**)&vthi, g_vT_hi); cudaGetSymbolAddress((void**)&vtlo, g_vT_lo);
    cudaGetSymbolAddress((void**)&phi,  g_p_hi);  cudaGetSymbolAddress((void**)&plo,  g_p_lo);
    cudaGetSymbolAddress((void**)&cxhi, g_ctx_hi); cudaGetSymbolAddress((void**)&cxlo, g_ctx_lo);

    static int configured = 0;
    if (!configured) {
        cudaFuncSetAttribute(gemm_bf16x3, cudaFuncAttributeMaxDynamicSharedMemorySize, GSMEM);
        configured = 1;
    }

    dim3 blk(256);

    // 0) split inputs to bf16 hi/lo
    split_kernel<<<(S * HID + 255) / 256, 256>>>(hs, hshi, hslo, S * HID);
    split_kernel<<<(HID * HID + 255) / 256, 256>>>(Wq, wqhi, wqlo, HID * HID);
    split_kernel<<<(KVHID * HID + 255) / 256, 256>>>(Wk, wkhi, wklo, KVHID * HID);
    split_kernel<<<(KVHID * HID + 255) / 256, 256>>>(Wv, wvhi, wvlo, KVHID * HID);
    split_kernel<<<(HID * HID + 255) / 256, 256>>>(Wo, wohi, wolo, HID * HID);

    // 1-3) projections (fp32 out)
    gemm_bf16x3<<<dim3(HID / 128, S / 128, 1), blk, GSMEM>>>(
        hshi, hslo, wqhi, wqlo, q, nullptr, nullptr,
        HID, HID, HID, HID, 0, 0, 0, 1, 0);
    gemm_bf16x3<<<dim3(KVHID / 128, S / 128, 1), blk, GSMEM>>>(
        hshi, hslo, wkhi, wklo, k, nullptr, nullptr,
        HID, HID, HID, KVHID, 0, 0, 0, 1, 0);
    gemm_bf16x3<<<dim3(KVHID / 128, S / 128, 1), blk, GSMEM>>>(
        hshi, hslo, wvhi, wvlo, v, nullptr, nullptr,
        HID, HID, HID, KVHID, 0, 0, 0, 1, 0);

    // 4) RoPE + gamma; emit q/k hi/lo
    rope_scale_kernel<<<dim3(S, H + HKV), 64>>>(q, k, pos, prior, qhi, qlo, khi, klo);
    // 5) eta scale + transpose; emit vT hi/lo
    v_scale_transpose<<<dim3(S, KVHID / 128), 128>>>(v, vthi, vtlo, prior);

    // 6) scores[h] = Q_h @ K_{h/4}^T (fp32), causal tile skip
    gemm_bf16x3<<<dim3(S / 128, S / 128, H), blk, GSMEM>>>(
        qhi, qlo, khi, klo, sc, nullptr, nullptr,
        D, HID, KVHID, S,
        (size_t)D, (size_t)D, (size_t)S * S, GROUPS, 1);

    // 7) fused steering softmax -> probs hi/lo (causal)
    softmax_steer<<<dim3(S, H), blk>>>(sc, prior, m1, m2, phi, plo);

    // 8) ctx[h] = P_h @ V_{h/4} (NT on vT), K-loop clamped by causality,
    //    emits ctx hi/lo directly
    gemm_bf16x3<<<dim3(D / 128, S / 128, H), blk, GSMEM>>>(
        phi, plo, vthi, vtlo, nullptr, cxhi, cxlo,
        S, S, S, HID,
        (size_t)S * S, (size_t)D * S, (size_t)D, GROUPS, 2);

    // 9) out = ctx @ Wo^T
    gemm_bf16x3<<<dim3(HID / 128, S / 128, 1), blk, GSMEM>>>(
        cxhi, cxlo, wohi, wolo, out, nullptr, nullptr,
        HID, HID, HID, HID, 0, 0, 0, 1, 0);
}

// round 5
// speedup vs baseline: 3.2417x; 1.3356x over previous
#include <cuda_runtime.h>
#include <cuda_bf16.h>
#include <math.h>
#include <stdint.h>

// Problem constants (B=1)
#define S     1024
#define H     32
#define HKV   8
#define D     128
#define HID   4096
#define KVHID 1024
#define GROUPS 4

typedef __nv_bfloat16 bf16;

// ---------------- scratch (static device globals: no allocs allowed) -------
__device__ float g_q[(size_t)S * HID];
__device__ float g_k[(size_t)S * KVHID];
__device__ float g_v[(size_t)S * KVHID];
__device__ float g_scores[(size_t)H * S * S];   // 134 MB

__device__ bf16 g_hs_hi[(size_t)S * HID],     g_hs_lo[(size_t)S * HID];
__device__ bf16 g_wq_hi[(size_t)HID * HID],   g_wq_lo[(size_t)HID * HID];
__device__ bf16 g_wk_hi[(size_t)KVHID * HID], g_wk_lo[(size_t)KVHID * HID];
__device__ bf16 g_wv_hi[(size_t)KVHID * HID], g_wv_lo[(size_t)KVHID * HID];
__device__ bf16 g_wo_hi[(size_t)HID * HID],   g_wo_lo[(size_t)HID * HID];
__device__ bf16 g_q_hi[(size_t)S * HID],      g_q_lo[(size_t)S * HID];
__device__ bf16 g_k_hi[(size_t)S * KVHID],    g_k_lo[(size_t)S * KVHID];
__device__ bf16 g_vT_hi[(size_t)KVHID * S],   g_vT_lo[(size_t)KVHID * S];
__device__ bf16 g_p_hi[(size_t)H * S * S],    g_p_lo[(size_t)H * S * S];
__device__ bf16 g_ctx_hi[(size_t)S * HID],    g_ctx_lo[(size_t)S * HID];

// ---------------- helpers ---------------------------------------------------
__device__ __forceinline__ void split_bf16(float x, bf16& hi, bf16& lo) {
    hi = __float2bfloat16(x);
    lo = __float2bfloat16(x - __bfloat162float(hi));
}

__device__ __forceinline__ void mma16816(float* c, const uint32_t* a, const uint32_t* b) {
    asm volatile(
        "mma.sync.aligned.m16n8k16.row.col.f32.bf16.bf16.f32 "
        "{%0,%1,%2,%3}, {%4,%5,%6,%7}, {%8,%9}, {%0,%1,%2,%3};"
        : "+f"(c[0]), "+f"(c[1]), "+f"(c[2]), "+f"(c[3])
        : "r"(a[0]), "r"(a[1]), "r"(a[2]), "r"(a[3]), "r"(b[0]), "r"(b[1]));
}

__device__ __forceinline__ void ldsm4(uint32_t* r, uint32_t addr) {
    asm volatile("ldmatrix.sync.aligned.m8n8.x4.shared.b16 {%0,%1,%2,%3}, [%4];"
        : "=r"(r[0]), "=r"(r[1]), "=r"(r[2]), "=r"(r[3]) : "r"(addr));
}

__device__ __forceinline__ void cp_async16(uint32_t smem_addr, const void* gptr) {
    asm volatile("cp.async.cg.shared.global [%0], [%1], 16;"
                 :: "r"(smem_addr), "l"(gptr));
}
__device__ __forceinline__ void cp_commit() {
    asm volatile("cp.async.commit_group;" ::: "memory");
}
template <int N>
__device__ __forceinline__ void cp_wait() {
    asm volatile("cp.async.wait_group %0;" :: "n"(N) : "memory");
}

__device__ __forceinline__ uint32_t smem_u32(const void* p) {
    uint32_t a;
    asm("{ .reg .u64 t; cvta.to.shared.u64 t, %1; cvt.u32.u64 %0, t; }"
        : "=r"(a) : "l"(p));
    return a;
}

// swizzled offset for a 128-row x 64-byte operand tile:
// row r (0..127), 16-byte chunk c (0..3). Conflict-free for 8-row LDSM phases
// and for the 32-thread STS pattern.
__device__ __forceinline__ uint32_t swoff(uint32_t r, uint32_t c) {
    return r * 64u + (((c ^ (r >> 1)) & 3u) << 4);
}

// ============ generic batched NT GEMM: fp32 via 3x bf16 HMMA ================
// C[z][m][n] = sum_k A[z][m][k]*B[z/zdivB][n][k], A/B pre-split into hi/lo.
// Block tile 128x128, BK=32, 3-stage cp.async pipeline, 1 sync per K-tile,
// ldmatrix fragments, swizzled 64B-row SMEM. 2 CTAs/SM.
// causal_mode: 0 none; 1 skip tiles bx>by (scores); 2 clamp K to (by+1)*128 (PV).
#define ARRB  8192             // 128 rows * 64 B
#define STGB  (4 * ARRB)       // Ahi|Alo|Bhi|Blo = 32768 B
#define STAGES 3
#define GSMEM (STAGES * STGB)  // 98304 B

__global__ void __launch_bounds__(256, 2) gemm_bf16x3(
    const bf16* __restrict__ Ahi, const bf16* __restrict__ Alo,
    const bf16* __restrict__ Bhi, const bf16* __restrict__ Blo,
    float* __restrict__ C, bf16* __restrict__ Chi, bf16* __restrict__ Clo,
    int K, int lda, int ldb, int ldc,
    size_t sA, size_t sB, size_t sC, int zdivB, int causal_mode)
{
    if (causal_mode == 1 && blockIdx.x > blockIdx.y) return;

    int KT = K / 32;
    if (causal_mode == 2) {
        int kt_max = (blockIdx.y + 1) * 4;
        if (KT > kt_max) KT = kt_max;
    }

    extern __shared__ char smem[];
    const uint32_t smem_b = smem_u32(smem);
    const int tid = threadIdx.x;
    const int wid = tid >> 5;
    const int lane = tid & 31;
    const int g  = lane >> 2;
    const int tc = lane & 3;
    const int warp_m = wid & 3;   // 4 warps along M
    const int warp_n = wid >> 2;  // 2 warps along N

    const size_t zoffA = (size_t)blockIdx.z * sA + (size_t)blockIdx.y * 128 * lda;
    const size_t zoffB = (size_t)(blockIdx.z / zdivB) * sB + (size_t)blockIdx.x * 128 * ldb;
    Ahi += zoffA; Alo += zoffA;
    Bhi += zoffB; Blo += zoffB;

    // cp.async slots (2 x 16B per operand array per thread)
    const int r0 = tid >> 2, c0 = tid & 3;
    const int r1 = (tid + 256) >> 2;
    const uint32_t sts0 = swoff(r0, c0);
    const uint32_t sts1 = swoff(r1, c0);

    // ldmatrix addressing
    // A (16x16 tile, mt in {0,1}): lanes 0-7 M0(rows+0..7,klo), 8-15 M1(rows+8..15,klo),
    // 16-23 M2(rows,khi), 24-31 M3(rows+8,khi)
    const uint32_t aRow0 = warp_m * 32 + ((lane >> 3) & 1) * 8 + (lane & 7);
    const uint32_t aSel  = (uint32_t)lane >> 4;            // 0/1 -> k chunk
    // B (two 8-col groups per x4): lanes 0-7 (nt even rows, klo), 8-15 (klo? no: ksel),
    // mapping: rowsel = (lane>>4)&1 (nt pair half), csel = (lane>>3)&1
    const uint32_t bSel  = ((uint32_t)lane >> 3) & 1;
    const uint32_t bRowB = warp_n * 64 + ((lane >> 4) & 1) * 8 + (lane & 7);

    float acc[2][8][4];
#pragma unroll
    for (int i = 0; i < 2; i++)
#pragma unroll
        for (int j = 0; j < 8; j++)
#pragma unroll
            for (int e = 0; e < 4; e++) acc[i][j][e] = 0.0f;

    auto issue_stage = [&](int kt, int s) {
        const uint32_t sb = smem_b + s * STGB;
        int kk = kt * 32;
        cp_async16(sb + 0*ARRB + sts0, Ahi + (size_t)r0 * lda + kk + c0 * 8);
        cp_async16(sb + 0*ARRB + sts1, Ahi + (size_t)r1 * lda + kk + c0 * 8);
        cp_async16(sb + 1*ARRB + sts0, Alo + (size_t)r0 * lda + kk + c0 * 8);
        cp_async16(sb + 1*ARRB + sts1, Alo + (size_t)r1 * lda + kk + c0 * 8);
        cp_async16(sb + 2*ARRB + sts0, Bhi + (size_t)r0 * ldb + kk + c0 * 8);
        cp_async16(sb + 2*ARRB + sts1, Bhi + (size_t)r1 * ldb + kk + c0 * 8);
        cp_async16(sb + 3*ARRB + sts0, Blo + (size_t)r0 * ldb + kk + c0 * 8);
        cp_async16(sb + 3*ARRB + sts1, Blo + (size_t)r1 * ldb + kk + c0 * 8);
    };

#pragma unroll
    for (int p = 0; p < STAGES - 1; p++) {
        if (p < KT) issue_stage(p, p);
        cp_commit();
    }

    int s = 0;
    for (int kt = 0; kt < KT; kt++) {
        cp_wait<STAGES - 2>();
        __syncthreads();

        int nk = kt + STAGES - 1;
        int ns = s + STAGES - 1; if (ns >= STAGES) ns -= STAGES;
        if (nk < KT) issue_stage(nk, ns);
        cp_commit();

        const uint32_t sb = smem_b + s * STGB;
        const uint32_t sa_hi = sb + 0 * ARRB;
        const uint32_t sa_lo = sb + 1 * ARRB;
        const uint32_t sb_hi = sb + 2 * ARRB;
        const uint32_t sb_lo = sb + 3 * ARRB;

#pragma unroll
        for (int ks = 0; ks < 2; ks++) {
            const uint32_t ac = ks * 2 + aSel;
            uint32_t AH[2][4], AL[2][4];
#pragma unroll
            for (int mt = 0; mt < 2; mt++) {
                uint32_t off = swoff(aRow0 + mt * 16, ac);
                ldsm4(AH[mt], sa_hi + off);
                ldsm4(AL[mt], sa_lo + off);
            }
            const uint32_t bc = ks * 2 + bSel;
#pragma unroll
            for (int p = 0; p < 4; p++) {       // nt pair p -> nt = 2p, 2p+1
                uint32_t off = swoff(bRowB + p * 16, bc);
                uint32_t BH[4], BL[4];
                ldsm4(BH, sb_hi + off);
                ldsm4(BL, sb_lo + off);
#pragma unroll
                for (int mt = 0; mt < 2; mt++)
#pragma unroll
                    for (int q = 0; q < 2; q++) {
                        float* a = acc[mt][2 * p + q];
                        mma16816(a, AH[mt], BH + 2 * q);
                        mma16816(a, AH[mt], BL + 2 * q);
                        mma16816(a, AL[mt], BH + 2 * q);
                    }
            }
        }
        if (++s == STAGES) s = 0;
    }

    // epilogue
    const int rowb = blockIdx.y * 128 + warp_m * 32;
    const int colb = blockIdx.x * 128 + warp_n * 64;
    if (C) {
        float* Cz = C + (size_t)blockIdx.z * sC;
#pragma unroll
        for (int mt = 0; mt < 2; mt++)
#pragma unroll
            for (int nt = 0; nt < 8; nt++) {
                int rr = rowb + mt * 16 + g;
                int cc = colb + nt * 8 + tc * 2;
                *(float2*)(Cz + (size_t)rr * ldc + cc) =
                    make_float2(acc[mt][nt][0], acc[mt][nt][1]);
                *(float2*)(Cz + (size_t)(rr + 8) * ldc + cc) =
                    make_float2(acc[mt][nt][2], acc[mt][nt][3]);
            }
    }
    if (Chi) {
        bf16* Hz = Chi + (size_t)blockIdx.z * sC;
        bf16* Lz = Clo + (size_t)blockIdx.z * sC;
#pragma unroll
        for (int mt = 0; mt < 2; mt++)
#pragma unroll
            for (int nt = 0; nt < 8; nt++) {
                int rr = rowb + mt * 16 + g;
                int cc = colb + nt * 8 + tc * 2;
                bf16 h0, l0, h1, l1;
#pragma unroll
                for (int half = 0; half < 2; half++) {
                    int r2 = rr + half * 8;
                    split_bf16(acc[mt][nt][half * 2 + 0], h0, l0);
                    split_bf16(acc[mt][nt][half * 2 + 1], h1, l1);
                    *(__nv_bfloat162*)(Hz + (size_t)r2 * ldc + cc) =
                        __nv_bfloat162(h0, h1);
                    *(__nv_bfloat162*)(Lz + (size_t)r2 * ldc + cc) =
                        __nv_bfloat162(l0, l1);
                }
            }
    }
}

// ---------------- fp32 -> bf16 hi/lo split (vectorized) --------------------
__global__ void split_kernel(const float4* __restrict__ src,
                             __nv_bfloat162* __restrict__ hi,
                             __nv_bfloat162* __restrict__ lo, int n4)
{
    int i = blockIdx.x * blockDim.x + threadIdx.x;
    if (i < n4) {
        float4 v = src[i];
        bf16 hx, lx, hy, ly, hz, lz, hw, lw;
        split_bf16(v.x, hx, lx); split_bf16(v.y, hy, ly);
        split_bf16(v.z, hz, lz); split_bf16(v.w, hw, lw);
        hi[i * 2 + 0] = __nv_bfloat162(hx, hy);
        hi[i * 2 + 1] = __nv_bfloat162(hz, hw);
        lo[i * 2 + 0] = __nv_bfloat162(lx, ly);
        lo[i * 2 + 1] = __nv_bfloat162(lz, lw);
    }
}

// ---------------- RoPE + gamma steering; emits bf16 hi/lo ------------------
__global__ void rope_scale_kernel(const float* __restrict__ q, const float* __restrict__ k,
                                  const int* __restrict__ pos,
                                  const float* __restrict__ prior,
                                  bf16* __restrict__ qhi, bf16* __restrict__ qlo,
                                  bf16* __restrict__ khi, bf16* __restrict__ klo)
{
    int s = blockIdx.x;
    int h = blockIdx.y;
    int d = threadIdx.x;   // 0..63

    float p = (float)pos[s];
    // 10000^(-d/64) = exp2(-log2(10000)/64 * d)
    float inv = exp2f(-0.2076245760856056f * (float)d);
    float sn, c;
    sincosf(p * inv, &sn, &c);

    if (h < H) {
        size_t base = (size_t)s * HID + h * D;
        float x1 = q[base + d], x2 = q[base + d + 64];
        float y1 = x1 * c - x2 * sn;
        float y2 = x2 * c + x1 * sn;
        bf16 hh, ll;
        split_bf16(y1, hh, ll); qhi[base + d] = hh;      qlo[base + d] = ll;
        split_bf16(y2, hh, ll); qhi[base + d + 64] = hh; qlo[base + d + 64] = ll;
    } else {
        size_t base = (size_t)s * KVHID + (h - H) * D;
        float gg = 1.0f + 0.5f * prior[s];
        float scale = fminf(fmaxf(gg, 0.5f), 2.0f);
        float x1 = k[base + d], x2 = k[base + d + 64];
        float y1 = (x1 * c - x2 * sn) * scale;
        float y2 = (x2 * c + x1 * sn) * scale;
        bf16 hh, ll;
        split_bf16(y1, hh, ll); khi[base + d] = hh;      klo[base + d] = ll;
        split_bf16(y2, hh, ll); khi[base + d + 64] = hh; klo[base + d + 64] = ll;
    }
}

// ---------------- v: eta scale + transpose; emits bf16 hi/lo ---------------
__global__ void v_scale_transpose(const float* __restrict__ v,
                                  bf16* __restrict__ vThi, bf16* __restrict__ vTlo,
                                  const float* __restrict__ prior)
{
    int s = blockIdx.x;
    int c = blockIdx.y * 128 + threadIdx.x;
    float e = 1.0f + 0.5f * prior[s];
    float eta = fminf(fmaxf(e, 0.5f), 2.0f);
    bf16 hh, ll;
    split_bf16(v[(size_t)s * KVHID + c] * eta, hh, ll);
    vThi[(size_t)c * S + s] = hh;
    vTlo[(size_t)c * S + s] = ll;
}

// ---------------- fused steering softmax (causal) ---------------------------
// probs for j > row are exactly 0 (reference: exp underflow). Zero-fill only
// up to the PV K-clamp boundary ((row/128 + 1)*128).
__global__ __launch_bounds__(256) void softmax_steer(
    const float* __restrict__ scores,
    const float* __restrict__ prior, const float* __restrict__ m1,
    const float* __restrict__ m2,
    bf16* __restrict__ phi, bf16* __restrict__ plo)
{
    int row = blockIdx.x;
    int h   = blockIdx.y;
    const float* srow = scores + ((size_t)h * S + row) * S;
    const int n = row + 1;

    __shared__ float buf[S];
    __shared__ float red[256];
    int tid = threadIdx.x;

    float l1 = m1[h], l2 = m2[h];
    const float rsq = 0.08838834764831845f;   // 1/sqrt(128)

    float lmax = -1e30f;
    for (int j = tid; j < n; j += 256) {
        float pj = prior[j];
        float bias = fminf(fmaxf(pj, -5.0f), 5.0f);
        float a = srow[j] * rsq + bias * l1;
        buf[j] = a;
        lmax = fmaxf(lmax, a);
    }
    red[tid] = lmax; __syncthreads();
    for (int off = 128; off > 0; off >>= 1) {
        if (tid < off) red[tid] = fmaxf(red[tid], red[tid + off]);
        __syncthreads();
    }
    float M = red[0];
    __syncthreads();

    float ls = 0.0f, lw = 0.0f;
    for (int j = tid; j < n; j += 256) {
        float e = expf(buf[j] - M);
        buf[j] = e;
        ls += e;
        lw += e * (1.0f + 0.5f * prior[j]);
    }
    red[tid] = ls; __syncthreads();
    for (int off = 128; off > 0; off >>= 1) {
        if (tid < off) red[tid] += red[tid + off];
        __syncthreads();
    }
    float sum = red[0];
    __syncthreads();
    red[tid] = lw; __syncthreads();
    for (int off = 128; off > 0; off >>= 1) {
        if (tid < off) red[tid] += red[tid + off];
        __syncthreads();
    }
    float wsum = red[0];
    __syncthreads();

    float invs = 1.0f / sum;
    float invw = 1.0f / wsum;
    size_t obase = ((size_t)h * S + row) * S;
    for (int j = tid; j < n; j += 256) {
        float e  = buf[j];
        float p  = e * invs;
        float sp = e * (1.0f + 0.5f * prior[j]) * invw;
        float pf = p + (sp - p) * l2;
        bf16 hh, ll;
        split_bf16(pf, hh, ll);
        phi[obase + j] = hh;
        plo[obase + j] = ll;
    }
    // zero only the region PV actually reads
    const int zend = ((row >> 7) + 1) << 7;
    const bf16 z = __float2bfloat16(0.0f);
    for (int j = n + tid; j < zend; j += 256) {
        phi[obase + j] = z;
        plo[obase + j] = z;
    }
}

// ---------------- launch ----------------------------------------------------
extern "C" void kernel_launch(void* const* d_in, const int* in_sizes, int n_in,
                              void* d_out, int out_size)
{
    const float* hs    = (const float*)d_in[0];
    const int*   pos   = (const int*)  d_in[2];
    const float* Wq    = (const float*)d_in[3];
    const float* Wk    = (const float*)d_in[4];
    const float* Wv    = (const float*)d_in[5];
    const float* Wo    = (const float*)d_in[6];
    const float* prior = (const float*)d_in[7];
    const float* m1    = (const float*)d_in[8];
    const float* m2    = (const float*)d_in[9];
    float* out = (float*)d_out;

    float *q, *k, *v, *sc;
    bf16 *hshi, *hslo, *wqhi, *wqlo, *wkhi, *wklo, *wvhi, *wvlo, *wohi, *wolo;
    bf16 *qhi, *qlo, *khi, *klo, *vthi, *vtlo, *phi, *plo, *cxhi, *cxlo;
    cudaGetSymbolAddress((void**)&q,    g_q);
    cudaGetSymbolAddress((void**)&k,    g_k);
    cudaGetSymbolAddress((void**)&v,    g_v);
    cudaGetSymbolAddress((void**)&sc,   g_scores);
    cudaGetSymbolAddress((void**)&hshi, g_hs_hi); cudaGetSymbolAddress((void**)&hslo, g_hs_lo);
    cudaGetSymbolAddress((void**)&wqhi, g_wq_hi); cudaGetSymbolAddress((void**)&wqlo, g_wq_lo);
    cudaGetSymbolAddress((void**)&wkhi, g_wk_hi); cudaGetSymbolAddress((void**)&wklo, g_wk_lo);
    cudaGetSymbolAddress((void**)&wvhi, g_wv_hi); cudaGetSymbolAddress((void**)&wvlo, g_wv_lo);
    cudaGetSymbolAddress((void**)&wohi, g_wo_hi); cudaGetSymbolAddress((void**)&wolo, g_wo_lo);
    cudaGetSymbolAddress((void**)&qhi,  g_q_hi);  cudaGetSymbolAddress((void**)&qlo,  g_q_lo);
    cudaGetSymbolAddress((void**)&khi,  g_k_hi);  cudaGetSymbolAddress((void**)&klo,  g_k_lo);
    cudaGetSymbolAddress((void**)&vthi, g_vT_hi); cudaGetSymbolAddress((void**)&vtlo, g_vT_lo);
    cudaGetSymbolAddress((void**)&phi,  g_p_hi);  cudaGetSymbolAddress((void**)&plo,  g_p_lo);
    cudaGetSymbolAddress((void**)&cxhi, g_ctx_hi); cudaGetSymbolAddress((void**)&cxlo, g_ctx_lo);

    static int configured = 0;
    if (!configured) {
        cudaFuncSetAttribute(gemm_bf16x3, cudaFuncAttributeMaxDynamicSharedMemorySize, GSMEM);
        configured = 1;
    }

    dim3 blk(256);

    // 0) split inputs to bf16 hi/lo (vectorized: n/4 threads)
    split_kernel<<<(S * HID / 4 + 255) / 256, 256>>>(
        (const float4*)hs, (__nv_bfloat162*)hshi, (__nv_bfloat162*)hslo, S * HID / 4);
    split_kernel<<<(HID * HID / 4 + 255) / 256, 256>>>(
        (const float4*)Wq, (__nv_bfloat162*)wqhi, (__nv_bfloat162*)wqlo, HID * HID / 4);
    split_kernel<<<(KVHID * HID / 4 + 255) / 256, 256>>>(
        (const float4*)Wk, (__nv_bfloat162*)wkhi, (__nv_bfloat162*)wklo, KVHID * HID / 4);
    split_kernel<<<(KVHID * HID / 4 + 255) / 256, 256>>>(
        (const float4*)Wv, (__nv_bfloat162*)wvhi, (__nv_bfloat162*)wvlo, KVHID * HID / 4);
    split_kernel<<<(HID * HID / 4 + 255) / 256, 256>>>(
        (const float4*)Wo, (__nv_bfloat162*)wohi, (__nv_bfloat162*)wolo, HID * HID / 4);

    // 1-3) projections (fp32 out)
    gemm_bf16x3<<<dim3(HID / 128, S / 128, 1), blk, GSMEM>>>(
        hshi, hslo, wqhi, wqlo, q, nullptr, nullptr,
        HID, HID, HID, HID, 0, 0, 0, 1, 0);
    gemm_bf16x3<<<dim3(KVHID / 128, S / 128, 1), blk, GSMEM>>>(
        hshi, hslo, wkhi, wklo, k, nullptr, nullptr,
        HID, HID, HID, KVHID, 0, 0, 0, 1, 0);
    gemm_bf16x3<<<dim3(KVHID / 128, S / 128, 1), blk, GSMEM>>>(
        hshi, hslo, wvhi, wvlo, v, nullptr, nullptr,
        HID, HID, HID, KVHID, 0, 0, 0, 1, 0);

    // 4) RoPE + gamma; emit q/k hi/lo
    rope_scale_kernel<<<dim3(S, H + HKV), 64>>>(q, k, pos, prior, qhi, qlo, khi, klo);
    // 5) eta scale + transpose; emit vT hi/lo
    v_scale_transpose<<<dim3(S, KVHID / 128), 128>>>(v, vthi, vtlo, prior);

    // 6) scores[h] = Q_h @ K_{h/4}^T (fp32), causal tile skip
    gemm_bf16x3<<<dim3(S / 128, S / 128, H), blk, GSMEM>>>(
        qhi, qlo, khi, klo, sc, nullptr, nullptr,
        D, HID, KVHID, S,
        (size_t)D, (size_t)D, (size_t)S * S, GROUPS, 1);

    // 7) fused steering softmax -> probs hi/lo (causal)
    softmax_steer<<<dim3(S, H), blk>>>(sc, prior, m1, m2, phi, plo);

    // 8) ctx[h] = P_h @ V_{h/4} (NT on vT), K clamped by causality, bf16 out
    gemm_bf16x3<<<dim3(D / 128, S / 128, H), blk, GSMEM>>>(
        phi, plo, vthi, vtlo, nullptr, cxhi, cxlo,
        S, S, S, HID,
        (size_t)S * S, (size_t)D * S, (size_t)D, GROUPS, 2);

    // 9) out = ctx @ Wo^T
    gemm_bf16x3<<<dim3(HID / 128, S / 128, 1), blk, GSMEM>>>(
        cxhi, cxlo, wohi, wolo, out, nullptr, nullptr,
        HID, HID, HID, HID, 0, 0, 0, 1, 0);
}

// round 6
// speedup vs baseline: 4.8341x; 1.4912x over previous
#include <cuda_runtime.h>
#include <cuda_fp16.h>
#include <math.h>
#include <stdint.h>

// Problem constants (B=1)
#define S     1024
#define H     32
#define HKV   8
#define D     128
#define HID   4096
#define KVHID 1024
#define QKVW  (HID + 2 * KVHID)   // 6144
#define GROUPS 4

// ---------------- scratch (static device globals: no allocs allowed) -------
__device__ float g_qkv[(size_t)S * QKVW];        // fused q|k|v projection out
__device__ float g_scores[(size_t)H * S * S];    // 134 MB

__device__ __half g_hs_hi[(size_t)S * HID],  g_hs_lo[(size_t)S * HID];
__device__ __half g_wqkv_hi[(size_t)QKVW * HID];   // Wq|Wk|Wv rows, fp16
__device__ __half g_wo_hi[(size_t)HID * HID];
__device__ __half g_q_hi[(size_t)S * HID],   g_q_lo[(size_t)S * HID];
__device__ __half g_k_hi[(size_t)S * KVHID];
__device__ __half g_vT_hi[(size_t)KVHID * S];
__device__ __half g_p_hi[(size_t)H * S * S], g_p_lo[(size_t)H * S * S];
__device__ __half g_ctx_hi[(size_t)S * HID], g_ctx_lo[(size_t)S * HID];

// ---------------- helpers ---------------------------------------------------
__device__ __forceinline__ void split_fp16(float x, __half& hi, __half& lo) {
    hi = __float2half(x);
    lo = __float2half(x - __half2float(hi));
}

__device__ __forceinline__ void mma16816(float* c, const uint32_t* a, const uint32_t* b) {
    asm volatile(
        "mma.sync.aligned.m16n8k16.row.col.f32.f16.f16.f32 "
        "{%0,%1,%2,%3}, {%4,%5,%6,%7}, {%8,%9}, {%0,%1,%2,%3};"
        : "+f"(c[0]), "+f"(c[1]), "+f"(c[2]), "+f"(c[3])
        : "r"(a[0]), "r"(a[1]), "r"(a[2]), "r"(a[3]), "r"(b[0]), "r"(b[1]));
}

__device__ __forceinline__ void ldsm4(uint32_t* r, uint32_t addr) {
    asm volatile("ldmatrix.sync.aligned.m8n8.x4.shared.b16 {%0,%1,%2,%3}, [%4];"
        : "=r"(r[0]), "=r"(r[1]), "=r"(r[2]), "=r"(r[3]) : "r"(addr));
}

__device__ __forceinline__ void cp_async16(uint32_t smem_addr, const void* gptr) {
    asm volatile("cp.async.cg.shared.global [%0], [%1], 16;"
                 :: "r"(smem_addr), "l"(gptr));
}
__device__ __forceinline__ void cp_commit() {
    asm volatile("cp.async.commit_group;" ::: "memory");
}
template <int N>
__device__ __forceinline__ void cp_wait() {
    asm volatile("cp.async.wait_group %0;" :: "n"(N) : "memory");
}

__device__ __forceinline__ uint32_t smem_u32(const void* p) {
    uint32_t a;
    asm("{ .reg .u64 t; cvta.to.shared.u64 t, %1; cvt.u32.u64 %0, t; }"
        : "=r"(a) : "l"(p));
    return a;
}

// swizzled offset, 128-row x 64B operand tile
__device__ __forceinline__ uint32_t swoff(uint32_t r, uint32_t c) {
    return r * 64u + (((c ^ (r >> 1)) & 3u) << 4);
}

// ============ generic batched NT GEMM: fp32 via 2x fp16 HMMA ================
// C[z][m][n] = sum_k A[z][m][k]*B[z/zdivB][n][k]
// A pre-split (hi+lo fp16), B rounded to fp16 (hi only).
// Block tile 128x128, BK=32, 4-stage cp.async, ldmatrix, swizzled SMEM,
// 2 CTAs/SM. causal_mode: 0 none; 1 skip bx>by; 2 clamp K to (by+1)*128.
#define ARRB  8192             // 128 rows * 64 B
#define STGB  (3 * ARRB)       // Ahi|Alo|Bhi = 24576 B
#define STAGES 4
#define GSMEM (STAGES * STGB)  // 98304 B

__global__ void __launch_bounds__(256, 2) gemm_fp16x2(
    const __half* __restrict__ Ahi, const __half* __restrict__ Alo,
    const __half* __restrict__ Bhi,
    float* __restrict__ C, __half* __restrict__ Chi, __half* __restrict__ Clo,
    int K, int lda, int ldb, int ldc,
    size_t sA, size_t sB, size_t sC, int zdivB, int causal_mode)
{
    if (causal_mode == 1 && blockIdx.x > blockIdx.y) return;

    int KT = K / 32;
    if (causal_mode == 2) {
        int kt_max = (blockIdx.y + 1) * 4;
        if (KT > kt_max) KT = kt_max;
    }

    extern __shared__ char smem[];
    const uint32_t smem_b = smem_u32(smem);
    const int tid = threadIdx.x;
    const int wid = tid >> 5;
    const int lane = tid & 31;
    const int g  = lane >> 2;
    const int tc = lane & 3;
    const int warp_m = wid & 3;
    const int warp_n = wid >> 2;

    const size_t zoffA = (size_t)blockIdx.z * sA + (size_t)blockIdx.y * 128 * lda;
    const size_t zoffB = (size_t)(blockIdx.z / zdivB) * sB + (size_t)blockIdx.x * 128 * ldb;
    Ahi += zoffA; Alo += zoffA;
    Bhi += zoffB;

    const int r0 = tid >> 2, c0 = tid & 3;
    const int r1 = (tid + 256) >> 2;
    const uint32_t sts0 = swoff(r0, c0);
    const uint32_t sts1 = swoff(r1, c0);

    const uint32_t aRow0 = warp_m * 32 + ((lane >> 3) & 1) * 8 + (lane & 7);
    const uint32_t aSel  = (uint32_t)lane >> 4;
    const uint32_t bSel  = ((uint32_t)lane >> 3) & 1;
    const uint32_t bRowB = warp_n * 64 + ((lane >> 4) & 1) * 8 + (lane & 7);

    float acc[2][8][4];
#pragma unroll
    for (int i = 0; i < 2; i++)
#pragma unroll
        for (int j = 0; j < 8; j++)
#pragma unroll
            for (int e = 0; e < 4; e++) acc[i][j][e] = 0.0f;

    auto issue_stage = [&](int kt, int s) {
        const uint32_t sb = smem_b + s * STGB;
        int kk = kt * 32;
        cp_async16(sb + 0*ARRB + sts0, Ahi + (size_t)r0 * lda + kk + c0 * 8);
        cp_async16(sb + 0*ARRB + sts1, Ahi + (size_t)r1 * lda + kk + c0 * 8);
        cp_async16(sb + 1*ARRB + sts0, Alo + (size_t)r0 * lda + kk + c0 * 8);
        cp_async16(sb + 1*ARRB + sts1, Alo + (size_t)r1 * lda + kk + c0 * 8);
        cp_async16(sb + 2*ARRB + sts0, Bhi + (size_t)r0 * ldb + kk + c0 * 8);
        cp_async16(sb + 2*ARRB + sts1, Bhi + (size_t)r1 * ldb + kk + c0 * 8);
    };

#pragma unroll
    for (int p = 0; p < STAGES - 1; p++) {
        if (p < KT) issue_stage(p, p);
        cp_commit();
    }

    int s = 0;
    for (int kt = 0; kt < KT; kt++) {
        cp_wait<STAGES - 2>();
        __syncthreads();

        int nk = kt + STAGES - 1;
        int ns = s + STAGES - 1; if (ns >= STAGES) ns -= STAGES;
        if (nk < KT) issue_stage(nk, ns);
        cp_commit();

        const uint32_t sb = smem_b + s * STGB;
        const uint32_t sa_hi = sb + 0 * ARRB;
        const uint32_t sa_lo = sb + 1 * ARRB;
        const uint32_t sb_hi = sb + 2 * ARRB;

#pragma unroll
        for (int ks = 0; ks < 2; ks++) {
            const uint32_t ac = ks * 2 + aSel;
            uint32_t AH[2][4], AL[2][4];
#pragma unroll
            for (int mt = 0; mt < 2; mt++) {
                uint32_t off = swoff(aRow0 + mt * 16, ac);
                ldsm4(AH[mt], sa_hi + off);
                ldsm4(AL[mt], sa_lo + off);
            }
            const uint32_t bc = ks * 2 + bSel;
#pragma unroll
            for (int p = 0; p < 4; p++) {
                uint32_t off = swoff(bRowB + p * 16, bc);
                uint32_t BH[4];
                ldsm4(BH, sb_hi + off);
#pragma unroll
                for (int mt = 0; mt < 2; mt++)
#pragma unroll
                    for (int q = 0; q < 2; q++) {
                        float* a = acc[mt][2 * p + q];
                        mma16816(a, AH[mt], BH + 2 * q);
                        mma16816(a, AL[mt], BH + 2 * q);
                    }
            }
        }
        if (++s == STAGES) s = 0;
    }

    // epilogue
    const int rowb = blockIdx.y * 128 + warp_m * 32;
    const int colb = blockIdx.x * 128 + warp_n * 64;
    if (C) {
        float* Cz = C + (size_t)blockIdx.z * sC;
#pragma unroll
        for (int mt = 0; mt < 2; mt++)
#pragma unroll
            for (int nt = 0; nt < 8; nt++) {
                int rr = rowb + mt * 16 + g;
                int cc = colb + nt * 8 + tc * 2;
                *(float2*)(Cz + (size_t)rr * ldc + cc) =
                    make_float2(acc[mt][nt][0], acc[mt][nt][1]);
                *(float2*)(Cz + (size_t)(rr + 8) * ldc + cc) =
                    make_float2(acc[mt][nt][2], acc[mt][nt][3]);
            }
    }
    if (Chi) {
        __half* Hz = Chi + (size_t)blockIdx.z * sC;
        __half* Lz = Clo + (size_t)blockIdx.z * sC;
#pragma unroll
        for (int mt = 0; mt < 2; mt++)
#pragma unroll
            for (int nt = 0; nt < 8; nt++) {
                int rr = rowb + mt * 16 + g;
                int cc = colb + nt * 8 + tc * 2;
                __half h0, l0, h1, l1;
#pragma unroll
                for (int half_i = 0; half_i < 2; half_i++) {
                    int r2 = rr + half_i * 8;
                    split_fp16(acc[mt][nt][half_i * 2 + 0], h0, l0);
                    split_fp16(acc[mt][nt][half_i * 2 + 1], h1, l1);
                    *(__half2*)(Hz + (size_t)r2 * ldc + cc) = __halves2half2(h0, h1);
                    *(__half2*)(Lz + (size_t)r2 * ldc + cc) = __halves2half2(l0, l1);
                }
            }
    }
}

// ---------------- fp32 -> fp16 hi/lo split (vectorized) --------------------
__global__ void split_kernel(const float4* __restrict__ src,
                             __half2* __restrict__ hi, __half2* __restrict__ lo, int n4)
{
    int i = blockIdx.x * blockDim.x + threadIdx.x;
    if (i < n4) {
        float4 v = src[i];
        __half hx, lx, hy, ly, hz, lz, hw, lw;
        split_fp16(v.x, hx, lx); split_fp16(v.y, hy, ly);
        split_fp16(v.z, hz, lz); split_fp16(v.w, hw, lw);
        hi[i * 2 + 0] = __halves2half2(hx, hy);
        hi[i * 2 + 1] = __halves2half2(hz, hw);
        lo[i * 2 + 0] = __halves2half2(lx, ly);
        lo[i * 2 + 1] = __halves2half2(lz, lw);
    }
}

// ---------------- fp32 -> fp16 convert (hi only, vectorized) ---------------
__global__ void cvt_kernel(const float4* __restrict__ src,
                           __half2* __restrict__ hi, int n4)
{
    int i = blockIdx.x * blockDim.x + threadIdx.x;
    if (i < n4) {
        float4 v = src[i];
        hi[i * 2 + 0] = __halves2half2(__float2half(v.x), __float2half(v.y));
        hi[i * 2 + 1] = __halves2half2(__float2half(v.z), __float2half(v.w));
    }
}

// ---------------- RoPE + gamma steering; q scaled by 1/sqrt(D) -------------
// reads merged qkv buffer; q -> hi/lo fp16, k -> hi fp16
__global__ void rope_scale_kernel(const float* __restrict__ qkv,
                                  const int* __restrict__ pos,
                                  const float* __restrict__ prior,
                                  __half* __restrict__ qhi, __half* __restrict__ qlo,
                                  __half* __restrict__ khi)
{
    int s = blockIdx.x;
    int h = blockIdx.y;
    int d = threadIdx.x;   // 0..63

    float p = (float)pos[s];
    float inv = exp2f(-0.2076245760856056f * (float)d);  // 10000^(-d/64)
    float sn, c;
    sincosf(p * inv, &sn, &c);

    if (h < H) {
        const float* base = qkv + (size_t)s * QKVW + h * D;
        const float rsq = 0.08838834764831845f;   // 1/sqrt(128)
        float x1 = base[d], x2 = base[d + 64];
        float y1 = (x1 * c - x2 * sn) * rsq;
        float y2 = (x2 * c + x1 * sn) * rsq;
        size_t ob = (size_t)s * HID + h * D;
        __half hh, ll;
        split_fp16(y1, hh, ll); qhi[ob + d] = hh;      qlo[ob + d] = ll;
        split_fp16(y2, hh, ll); qhi[ob + d + 64] = hh; qlo[ob + d + 64] = ll;
    } else {
        const float* base = qkv + (size_t)s * QKVW + HID + (h - H) * D;
        float gg = 1.0f + 0.5f * prior[s];
        float scale = fminf(fmaxf(gg, 0.5f), 2.0f);
        float x1 = base[d], x2 = base[d + 64];
        float y1 = (x1 * c - x2 * sn) * scale;
        float y2 = (x2 * c + x1 * sn) * scale;
        size_t ob = (size_t)s * KVHID + (h - H) * D;
        khi[ob + d]      = __float2half(y1);
        khi[ob + d + 64] = __float2half(y2);
    }
}

// ---------------- v: eta scale + transpose; fp16 hi only -------------------
__global__ void v_scale_transpose(const float* __restrict__ qkv,
                                  __half* __restrict__ vThi,
                                  const float* __restrict__ prior)
{
    int s = blockIdx.x;
    int c = blockIdx.y * 128 + threadIdx.x;
    float e = 1.0f + 0.5f * prior[s];
    float eta = fminf(fmaxf(e, 0.5f), 2.0f);
    float v = qkv[(size_t)s * QKVW + HID + KVHID + c];
    vThi[(size_t)c * S + s] = __float2half(v * eta);
}

// ---------------- fused steering softmax (causal) ---------------------------
__global__ __launch_bounds__(256) void softmax_steer(
    const float* __restrict__ scores,
    const float* __restrict__ prior, const float* __restrict__ m1,
    const float* __restrict__ m2,
    __half* __restrict__ phi, __half* __restrict__ plo)
{
    int row = blockIdx.x;
    int h   = blockIdx.y;
    const float* srow = scores + ((size_t)h * S + row) * S;
    const int n = row + 1;

    __shared__ float buf[S];
    __shared__ float red[256];
    int tid = threadIdx.x;

    float l1 = m1[h], l2 = m2[h];

    float lmax = -1e30f;
    for (int j = tid; j < n; j += 256) {
        float pj = prior[j];
        float bias = fminf(fmaxf(pj, -5.0f), 5.0f);
        float a = srow[j] + bias * l1;        // 1/sqrt(D) already folded into q
        buf[j] = a;
        lmax = fmaxf(lmax, a);
    }
    red[tid] = lmax; __syncthreads();
    for (int off = 128; off > 0; off >>= 1) {
        if (tid < off) red[tid] = fmaxf(red[tid], red[tid + off]);
        __syncthreads();
    }
    float M = red[0];
    __syncthreads();

    float ls = 0.0f, lw = 0.0f;
    for (int j = tid; j < n; j += 256) {
        float e = expf(buf[j] - M);
        buf[j] = e;
        ls += e;
        lw += e * (1.0f + 0.5f * prior[j]);
    }
    red[tid] = ls; __syncthreads();
    for (int off = 128; off > 0; off >>= 1) {
        if (tid < off) red[tid] += red[tid + off];
        __syncthreads();
    }
    float sum = red[0];
    __syncthreads();
    red[tid] = lw; __syncthreads();
    for (int off = 128; off > 0; off >>= 1) {
        if (tid < off) red[tid] += red[tid + off];
        __syncthreads();
    }
    float wsum = red[0];
    __syncthreads();

    float invs = 1.0f / sum;
    float invw = 1.0f / wsum;
    size_t obase = ((size_t)h * S + row) * S;
    for (int j = tid; j < n; j += 256) {
        float e  = buf[j];
        float p  = e * invs;
        float sp = e * (1.0f + 0.5f * prior[j]) * invw;
        float pf = p + (sp - p) * l2;
        __half hh, ll;
        split_fp16(pf, hh, ll);
        phi[obase + j] = hh;
        plo[obase + j] = ll;
    }
    const int zend = ((row >> 7) + 1) << 7;
    const __half z = __float2half(0.0f);
    for (int j = n + tid; j < zend; j += 256) {
        phi[obase + j] = z;
        plo[obase + j] = z;
    }
}

// ---------------- launch ----------------------------------------------------
extern "C" void kernel_launch(void* const* d_in, const int* in_sizes, int n_in,
                              void* d_out, int out_size)
{
    const float* hs    = (const float*)d_in[0];
    const int*   pos   = (const int*)  d_in[2];
    const float* Wq    = (const float*)d_in[3];
    const float* Wk    = (const float*)d_in[4];
    const float* Wv    = (const float*)d_in[5];
    const float* Wo    = (const float*)d_in[6];
    const float* prior = (const float*)d_in[7];
    const float* m1    = (const float*)d_in[8];
    const float* m2    = (const float*)d_in[9];
    float* out = (float*)d_out;

    float *qkv, *sc;
    __half *hshi, *hslo, *wqkvhi, *wohi;
    __half *qhi, *qlo, *khi, *vthi, *phi, *plo, *cxhi, *cxlo;
    cudaGetSymbolAddress((void**)&qkv,   g_qkv);
    cudaGetSymbolAddress((void**)&sc,    g_scores);
    cudaGetSymbolAddress((void**)&hshi,  g_hs_hi);  cudaGetSymbolAddress((void**)&hslo, g_hs_lo);
    cudaGetSymbolAddress((void**)&wqkvhi,g_wqkv_hi);
    cudaGetSymbolAddress((void**)&wohi,  g_wo_hi);
    cudaGetSymbolAddress((void**)&qhi,   g_q_hi);   cudaGetSymbolAddress((void**)&qlo,  g_q_lo);
    cudaGetSymbolAddress((void**)&khi,   g_k_hi);
    cudaGetSymbolAddress((void**)&vthi,  g_vT_hi);
    cudaGetSymbolAddress((void**)&phi,   g_p_hi);   cudaGetSymbolAddress((void**)&plo,  g_p_lo);
    cudaGetSymbolAddress((void**)&cxhi,  g_ctx_hi); cudaGetSymbolAddress((void**)&cxlo, g_ctx_lo);

    static int configured = 0;
    if (!configured) {
        cudaFuncSetAttribute(gemm_fp16x2, cudaFuncAttributeMaxDynamicSharedMemorySize, GSMEM);
        configured = 1;
    }

    dim3 blk(256);

    // 0) hs -> fp16 hi/lo; weights -> fp16 (concatenated Wq|Wk|Wv, and Wo)
    split_kernel<<<(S * HID / 4 + 255) / 256, 256>>>(
        (const float4*)hs, (__half2*)hshi, (__half2*)hslo, S * HID / 4);
    cvt_kernel<<<(HID * HID / 4 + 255) / 256, 256>>>(
        (const float4*)Wq, (__half2*)wqkvhi, HID * HID / 4);
    cvt_kernel<<<(KVHID * HID / 4 + 255) / 256, 256>>>(
        (const float4*)Wk, (__half2*)(wqkvhi + (size_t)HID * HID), KVHID * HID / 4);
    cvt_kernel<<<(KVHID * HID / 4 + 255) / 256, 256>>>(
        (const float4*)Wv, (__half2*)(wqkvhi + (size_t)(HID + KVHID) * HID), KVHID * HID / 4);
    cvt_kernel<<<(HID * HID / 4 + 255) / 256, 256>>>(
        (const float4*)Wo, (__half2*)wohi, HID * HID / 4);

    // 1) merged projection: qkv = hs @ [Wq|Wk|Wv]^T   [S, 6144]
    gemm_fp16x2<<<dim3(QKVW / 128, S / 128, 1), blk, GSMEM>>>(
        hshi, hslo, wqkvhi, qkv, nullptr, nullptr,
        HID, HID, HID, QKVW, 0, 0, 0, 1, 0);

    // 2) RoPE + gamma (+1/sqrt(D) into q)
    rope_scale_kernel<<<dim3(S, H + HKV), 64>>>(qkv, pos, prior, qhi, qlo, khi);
    // 3) eta scale + transpose -> vT fp16
    v_scale_transpose<<<dim3(S, KVHID / 128), 128>>>(qkv, vthi, prior);

    // 4) scores[h] = Qs_h @ K_{h/4}^T (fp32), causal tile skip
    gemm_fp16x2<<<dim3(S / 128, S / 128, H), blk, GSMEM>>>(
        qhi, qlo, khi, sc, nullptr, nullptr,
        D, HID, KVHID, S,
        (size_t)D, (size_t)D, (size_t)S * S, GROUPS, 1);

    // 5) fused steering softmax -> probs fp16 hi/lo (causal)
    softmax_steer<<<dim3(S, H), blk>>>(sc, prior, m1, m2, phi, plo);

    // 6) ctx[h] = P_h @ V_{h/4}, K clamped by causality, fp16 hi/lo out
    gemm_fp16x2<<<dim3(D / 128, S / 128, H), blk, GSMEM>>>(
        phi, plo, vthi, nullptr, cxhi, cxlo,
        S, S, S, HID,
        (size_t)S * S, (size_t)D * S, (size_t)D, GROUPS, 2);

    // 7) out = ctx @ Wo^T
    gemm_fp16x2<<<dim3(HID / 128, S / 128, 1), blk, GSMEM>>>(
        cxhi, cxlo, wohi, out, nullptr, nullptr,
        HID, HID, HID, HID, 0, 0, 0, 1, 0);
}

// round 7
// speedup vs baseline: 6.1220x; 1.2664x over previous
#include <cuda_runtime.h>
#include <cuda_fp16.h>
#include <math.h>
#include <stdint.h>

// Problem constants (B=1)
#define S     1024
#define H     32
#define HKV   8
#define D     128
#define HID   4096
#define KVHID 1024
#define QKVW  (HID + 2 * KVHID)   // 6144
#define GROUPS 4

// ---------------- scratch (static device globals: no allocs allowed) -------
__device__ float g_qkv[(size_t)S * QKVW];

__device__ __half g_hs_hi[(size_t)S * HID],  g_hs_lo[(size_t)S * HID];
__device__ __half g_wqkv_hi[(size_t)QKVW * HID];
__device__ __half g_wo_hi[(size_t)HID * HID];
__device__ __half g_q_hi[(size_t)S * HID],   g_q_lo[(size_t)S * HID];
__device__ __half g_k_hi[(size_t)S * KVHID];
__device__ __half g_vT_hi[(size_t)KVHID * S];
__device__ __half g_ctx_hi[(size_t)S * HID], g_ctx_lo[(size_t)S * HID];

// ---------------- helpers ---------------------------------------------------
__device__ __forceinline__ void split_fp16(float x, __half& hi, __half& lo) {
    hi = __float2half(x);
    lo = __float2half(x - __half2float(hi));
}

__device__ __forceinline__ void mma16816(float* c, const uint32_t* a, const uint32_t* b) {
    asm volatile(
        "mma.sync.aligned.m16n8k16.row.col.f32.f16.f16.f32 "
        "{%0,%1,%2,%3}, {%4,%5,%6,%7}, {%8,%9}, {%0,%1,%2,%3};"
        : "+f"(c[0]), "+f"(c[1]), "+f"(c[2]), "+f"(c[3])
        : "r"(a[0]), "r"(a[1]), "r"(a[2]), "r"(a[3]), "r"(b[0]), "r"(b[1]));
}

__device__ __forceinline__ void ldsm4(uint32_t* r, uint32_t addr) {
    asm volatile("ldmatrix.sync.aligned.m8n8.x4.shared.b16 {%0,%1,%2,%3}, [%4];"
        : "=r"(r[0]), "=r"(r[1]), "=r"(r[2]), "=r"(r[3]) : "r"(addr));
}

__device__ __forceinline__ void cp_async16(uint32_t smem_addr, const void* gptr) {
    asm volatile("cp.async.cg.shared.global [%0], [%1], 16;"
                 :: "r"(smem_addr), "l"(gptr));
}
__device__ __forceinline__ void cp_commit() {
    asm volatile("cp.async.commit_group;" ::: "memory");
}
template <int N>
__device__ __forceinline__ void cp_wait() {
    asm volatile("cp.async.wait_group %0;" :: "n"(N) : "memory");
}

__device__ __forceinline__ uint32_t smem_u32(const void* p) {
    uint32_t a;
    asm("{ .reg .u64 t; cvta.to.shared.u64 t, %1; cvt.u32.u64 %0, t; }"
        : "=r"(a) : "l"(p));
    return a;
}

__device__ __forceinline__ uint32_t packh2(float a, float b) {
    __half2 h = __halves2half2(__float2half(a), __float2half(b));
    return *(uint32_t*)&h;
}

// swizzled offset, 128-row x 64B operand tile
__device__ __forceinline__ uint32_t swoff(uint32_t r, uint32_t c) {
    return r * 64u + (((c ^ (r >> 1)) & 3u) << 4);
}

// ============ generic NT GEMM: fp32 via 2x fp16 HMMA (validated R6) =========
#define ARRB  8192
#define STGB  (3 * ARRB)
#define STAGES 4
#define GSMEM (STAGES * STGB)

__global__ void __launch_bounds__(256, 2) gemm_fp16x2(
    const __half* __restrict__ Ahi, const __half* __restrict__ Alo,
    const __half* __restrict__ Bhi,
    float* __restrict__ C, int K, int lda, int ldb, int ldc)
{
    extern __shared__ char smem[];
    const uint32_t smem_b = smem_u32(smem);
    const int tid = threadIdx.x;
    const int wid = tid >> 5;
    const int lane = tid & 31;
    const int g  = lane >> 2;
    const int tc = lane & 3;
    const int warp_m = wid & 3;
    const int warp_n = wid >> 2;
    const int KT = K / 32;

    Ahi += (size_t)blockIdx.y * 128 * lda;
    Alo += (size_t)blockIdx.y * 128 * lda;
    Bhi += (size_t)blockIdx.x * 128 * ldb;

    const int r0 = tid >> 2, c0 = tid & 3;
    const int r1 = (tid + 256) >> 2;
    const uint32_t sts0 = swoff(r0, c0);
    const uint32_t sts1 = swoff(r1, c0);

    const uint32_t aRow0 = warp_m * 32 + ((lane >> 3) & 1) * 8 + (lane & 7);
    const uint32_t aSel  = (uint32_t)lane >> 4;
    const uint32_t bSel  = ((uint32_t)lane >> 3) & 1;
    const uint32_t bRowB = warp_n * 64 + ((lane >> 4) & 1) * 8 + (lane & 7);

    float acc[2][8][4];
#pragma unroll
    for (int i = 0; i < 2; i++)
#pragma unroll
        for (int j = 0; j < 8; j++)
#pragma unroll
            for (int e = 0; e < 4; e++) acc[i][j][e] = 0.0f;

    auto issue_stage = [&](int kt, int s) {
        const uint32_t sb = smem_b + s * STGB;
        int kk = kt * 32;
        cp_async16(sb + 0*ARRB + sts0, Ahi + (size_t)r0 * lda + kk + c0 * 8);
        cp_async16(sb + 0*ARRB + sts1, Ahi + (size_t)r1 * lda + kk + c0 * 8);
        cp_async16(sb + 1*ARRB + sts0, Alo + (size_t)r0 * lda + kk + c0 * 8);
        cp_async16(sb + 1*ARRB + sts1, Alo + (size_t)r1 * lda + kk + c0 * 8);
        cp_async16(sb + 2*ARRB + sts0, Bhi + (size_t)r0 * ldb + kk + c0 * 8);
        cp_async16(sb + 2*ARRB + sts1, Bhi + (size_t)r1 * ldb + kk + c0 * 8);
    };

#pragma unroll
    for (int p = 0; p < STAGES - 1; p++) {
        if (p < KT) issue_stage(p, p);
        cp_commit();
    }

    int s = 0;
    for (int kt = 0; kt < KT; kt++) {
        cp_wait<STAGES - 2>();
        __syncthreads();

        int nk = kt + STAGES - 1;
        int ns = s + STAGES - 1; if (ns >= STAGES) ns -= STAGES;
        if (nk < KT) issue_stage(nk, ns);
        cp_commit();

        const uint32_t sb = smem_b + s * STGB;
        const uint32_t sa_hi = sb + 0 * ARRB;
        const uint32_t sa_lo = sb + 1 * ARRB;
        const uint32_t sb_hi = sb + 2 * ARRB;

#pragma unroll
        for (int ks = 0; ks < 2; ks++) {
            const uint32_t ac = ks * 2 + aSel;
            uint32_t AH[2][4], AL[2][4];
#pragma unroll
            for (int mt = 0; mt < 2; mt++) {
                uint32_t off = swoff(aRow0 + mt * 16, ac);
                ldsm4(AH[mt], sa_hi + off);
                ldsm4(AL[mt], sa_lo + off);
            }
            const uint32_t bc = ks * 2 + bSel;
#pragma unroll
            for (int p = 0; p < 4; p++) {
                uint32_t off = swoff(bRowB + p * 16, bc);
                uint32_t BH[4];
                ldsm4(BH, sb_hi + off);
#pragma unroll
                for (int mt = 0; mt < 2; mt++)
#pragma unroll
                    for (int q = 0; q < 2; q++) {
                        float* a = acc[mt][2 * p + q];
                        mma16816(a, AH[mt], BH + 2 * q);
                        mma16816(a, AL[mt], BH + 2 * q);
                    }
            }
        }
        if (++s == STAGES) s = 0;
    }

    const int rowb = blockIdx.y * 128 + warp_m * 32;
    const int colb = blockIdx.x * 128 + warp_n * 64;
#pragma unroll
    for (int mt = 0; mt < 2; mt++)
#pragma unroll
        for (int nt = 0; nt < 8; nt++) {
            int rr = rowb + mt * 16 + g;
            int cc = colb + nt * 8 + tc * 2;
            *(float2*)(C + (size_t)rr * ldc + cc) =
                make_float2(acc[mt][nt][0], acc[mt][nt][1]);
            *(float2*)(C + (size_t)(rr + 8) * ldc + cc) =
                make_float2(acc[mt][nt][2], acc[mt][nt][3]);
        }
}

// ======================= fused flash attention ==============================
// One CTA = (head h, 128-row Q block by). 8 warps, each owns 16 S-rows.
// S = Q.K^T (fp16 2-product), online steering softmax (binary l1/l2),
// O += P.V (fp16 single product), O /= sum. Emits ctx hi/lo fp16.
#define FA_QHI   0
#define FA_QLO   32768
#define FA_BIAS  65536
#define FA_U     69632
#define FA_KV0   73728
#define FA_KSTG  65536
#define FA_SMEM  (FA_KV0 + 2 * FA_KSTG)   // 204800

__global__ void __launch_bounds__(256, 1) flash_attn(
    const __half* __restrict__ qhi, const __half* __restrict__ qlo,
    const __half* __restrict__ khi, const __half* __restrict__ vthi,
    const float* __restrict__ prior, const float* __restrict__ m1,
    const float* __restrict__ m2,
    __half* __restrict__ cxhi, __half* __restrict__ cxlo)
{
    const int h    = blockIdx.x;
    const int by   = 7 - (int)blockIdx.y;   // heavy blocks dispatched first
    const int hk   = h >> 2;
    const int nblk = by + 1;

    extern __shared__ char smem[];
    const uint32_t sb = smem_u32(smem);
    const int tid = threadIdx.x;
    const int wid = tid >> 5;
    const int lane = tid & 31;
    const int g = lane >> 2, tc = lane & 3;

    const float l1 = m1[h], l2 = m2[h];

    // bias / u tables (l1, l2 are exactly 0.0 or 1.0)
    float* biasb = (float*)(smem + FA_BIAS);
    float* ub    = (float*)(smem + FA_U);
    for (int j = tid; j < S; j += 256) {
        float pj = prior[j];
        biasb[j] = fminf(fmaxf(pj, -5.0f), 5.0f) * l1;
        ub[j]    = 1.0f + 0.5f * pj * l2;
    }

    // Q tile (hi+lo) -> SMEM, 4 sub-arrays of 128x32 fp16
    {
        const __half* qh = qhi + (size_t)(by * 128) * HID + h * D;
        const __half* ql = qlo + (size_t)(by * 128) * HID + h * D;
#pragma unroll
        for (int t = 0; t < 8; t++) {
            int id = tid + t * 256;
            int r = id >> 4, cc = id & 15;
            uint32_t dst = (uint32_t)(cc >> 2) * 8192 + swoff(r, cc & 3);
            cp_async16(sb + FA_QHI + dst, qh + (size_t)r * HID + cc * 8);
            cp_async16(sb + FA_QLO + dst, ql + (size_t)r * HID + cc * 8);
        }
    }

    auto issue_kv = [&](int j, int st) {
        const uint32_t kb = sb + FA_KV0 + st * FA_KSTG;
        const __half* kp = khi  + (size_t)(j * 128) * KVHID + hk * D;
        const __half* vp = vthi + (size_t)(hk * 128) * S + j * 128;
#pragma unroll
        for (int t = 0; t < 8; t++) {
            int id = tid + t * 256;
            int r = id >> 4, cc = id & 15;
            uint32_t dst = (uint32_t)(cc >> 2) * 8192 + swoff(r, cc & 3);
            cp_async16(kb + dst,         kp + (size_t)r * KVHID + cc * 8);
            cp_async16(kb + 32768 + dst, vp + (size_t)r * S + cc * 8);
        }
    };

    issue_kv(0, 0);
    cp_commit();

    const uint32_t aRowQ = wid * 16 + ((lane >> 3) & 1) * 8 + (lane & 7);
    const uint32_t aSel  = (uint32_t)lane >> 4;
    const uint32_t bSel  = ((uint32_t)lane >> 3) & 1;
    const uint32_t bRow  = ((lane >> 4) & 1) * 8 + (lane & 7);

    float oacc[16][4];
#pragma unroll
    for (int i = 0; i < 16; i++)
#pragma unroll
        for (int e = 0; e < 4; e++) oacc[i][e] = 0.0f;
    float mrun0 = -1e30f, mrun1 = -1e30f;
    float srun0 = 0.0f,   srun1 = 0.0f;

    const int row0 = wid * 16 + g;   // local row for c0,c1 (c2,c3 -> +8)

    for (int j = 0; j < nblk; j++) {
        const int st = j & 1;
        if (j + 1 < nblk) { issue_kv(j + 1, st ^ 1); cp_commit(); cp_wait<1>(); }
        else              { cp_wait<0>(); }
        __syncthreads();

        const uint32_t kb = sb + FA_KV0 + st * FA_KSTG;
        const uint32_t vb = kb + 32768;

        // ---- S = Q.K^T (2-product) ----
        float sacc[16][4];
#pragma unroll
        for (int i = 0; i < 16; i++)
#pragma unroll
            for (int e = 0; e < 4; e++) sacc[i][e] = 0.0f;

#pragma unroll
        for (int kf = 0; kf < 8; kf++) {
            uint32_t sub = (uint32_t)(kf >> 1) * 8192;
            uint32_t kc  = (uint32_t)(kf & 1) * 2;
            uint32_t AH[4], AL[4];
            uint32_t aoff = sub + swoff(aRowQ, kc + aSel);
            ldsm4(AH, sb + FA_QHI + aoff);
            ldsm4(AL, sb + FA_QLO + aoff);
#pragma unroll
            for (int p = 0; p < 8; p++) {
                uint32_t BH[4];
                ldsm4(BH, kb + sub + swoff(bRow + p * 16, kc + bSel));
#pragma unroll
                for (int q = 0; q < 2; q++) {
                    float* a = sacc[2 * p + q];
                    mma16816(a, AH, BH + 2 * q);
                    mma16816(a, AL, BH + 2 * q);
                }
            }
        }

        // ---- online steering softmax ----
        const float* bias = biasb + j * 128;
        const float* uu   = ub + j * 128;
        const bool diag = (j == by);

        float mb0 = -1e30f, mb1 = -1e30f;
#pragma unroll
        for (int nt = 0; nt < 16; nt++) {
            int k0 = nt * 8 + tc * 2;
            float b0 = bias[k0], b1 = bias[k0 + 1];
            float a0 = sacc[nt][0] + b0;
            float a1 = sacc[nt][1] + b1;
            float a2 = sacc[nt][2] + b0;
            float a3 = sacc[nt][3] + b1;
            if (diag) {
                if (k0     > row0)     a0 = -1e30f;
                if (k0 + 1 > row0)     a1 = -1e30f;
                if (k0     > row0 + 8) a2 = -1e30f;
                if (k0 + 1 > row0 + 8) a3 = -1e30f;
            }
            sacc[nt][0] = a0; sacc[nt][1] = a1;
            sacc[nt][2] = a2; sacc[nt][3] = a3;
            mb0 = fmaxf(mb0, fmaxf(a0, a1));
            mb1 = fmaxf(mb1, fmaxf(a2, a3));
        }
        mb0 = fmaxf(mb0, __shfl_xor_sync(0xffffffffu, mb0, 1));
        mb0 = fmaxf(mb0, __shfl_xor_sync(0xffffffffu, mb0, 2));
        mb1 = fmaxf(mb1, __shfl_xor_sync(0xffffffffu, mb1, 1));
        mb1 = fmaxf(mb1, __shfl_xor_sync(0xffffffffu, mb1, 2));

        float mn0 = fmaxf(mrun0, mb0);
        float mn1 = fmaxf(mrun1, mb1);
        float sc0 = __expf(mrun0 - mn0);
        float sc1 = __expf(mrun1 - mn1);
        mrun0 = mn0; mrun1 = mn1;

        float rs0 = 0.0f, rs1 = 0.0f;
#pragma unroll
        for (int nt = 0; nt < 16; nt++) {
            int k0 = nt * 8 + tc * 2;
            float u0 = uu[k0], u1 = uu[k0 + 1];
            float e0 = __expf(sacc[nt][0] - mn0) * u0;
            float e1 = __expf(sacc[nt][1] - mn0) * u1;
            float e2 = __expf(sacc[nt][2] - mn1) * u0;
            float e3 = __expf(sacc[nt][3] - mn1) * u1;
            sacc[nt][0] = e0; sacc[nt][1] = e1;
            sacc[nt][2] = e2; sacc[nt][3] = e3;
            rs0 += e0 + e1; rs1 += e2 + e3;
            oacc[nt][0] *= sc0; oacc[nt][1] *= sc0;
            oacc[nt][2] *= sc1; oacc[nt][3] *= sc1;
        }
        rs0 += __shfl_xor_sync(0xffffffffu, rs0, 1);
        rs0 += __shfl_xor_sync(0xffffffffu, rs0, 2);
        rs1 += __shfl_xor_sync(0xffffffffu, rs1, 1);
        rs1 += __shfl_xor_sync(0xffffffffu, rs1, 2);
        srun0 = srun0 * sc0 + rs0;
        srun1 = srun1 * sc1 + rs1;

        // ---- O += P.V (C-frag -> A-frag repack, single product) ----
#pragma unroll
        for (int kf = 0; kf < 8; kf++) {
            uint32_t AP[4];
            AP[0] = packh2(sacc[2 * kf][0],     sacc[2 * kf][1]);
            AP[1] = packh2(sacc[2 * kf][2],     sacc[2 * kf][3]);
            AP[2] = packh2(sacc[2 * kf + 1][0], sacc[2 * kf + 1][1]);
            AP[3] = packh2(sacc[2 * kf + 1][2], sacc[2 * kf + 1][3]);
            uint32_t sub = (uint32_t)(kf >> 1) * 8192;
            uint32_t kc  = (uint32_t)(kf & 1) * 2;
#pragma unroll
            for (int p = 0; p < 8; p++) {
                uint32_t BV[4];
                ldsm4(BV, vb + sub + swoff(bRow + p * 16, kc + bSel));
                mma16816(oacc[2 * p],     AP, BV);
                mma16816(oacc[2 * p + 1], AP, BV + 2);
            }
        }
        __syncthreads();   // protect KV stage before next overwrite
    }

    // ---- epilogue: normalize, split to ctx hi/lo ----
    float inv0 = 1.0f / srun0;
    float inv1 = 1.0f / srun1;
    int grow = by * 128 + wid * 16 + g;
    __half* Hp = cxhi + (size_t)grow * HID + h * D + tc * 2;
    __half* Lp = cxlo + (size_t)grow * HID + h * D + tc * 2;
#pragma unroll
    for (int nt = 0; nt < 16; nt++) {
        __half h0, l0, h1, l1;
        split_fp16(oacc[nt][0] * inv0, h0, l0);
        split_fp16(oacc[nt][1] * inv0, h1, l1);
        *(__half2*)(Hp + nt * 8) = __halves2half2(h0, h1);
        *(__half2*)(Lp + nt * 8) = __halves2half2(l0, l1);
        split_fp16(oacc[nt][2] * inv1, h0, l0);
        split_fp16(oacc[nt][3] * inv1, h1, l1);
        *(__half2*)(Hp + (size_t)8 * HID + nt * 8) = __halves2half2(h0, h1);
        *(__half2*)(Lp + (size_t)8 * HID + nt * 8) = __halves2half2(l0, l1);
    }
}

// ---------------- fp32 -> fp16 hi/lo split (vectorized) --------------------
__global__ void split_kernel(const float4* __restrict__ src,
                             __half2* __restrict__ hi, __half2* __restrict__ lo, int n4)
{
    int i = blockIdx.x * blockDim.x + threadIdx.x;
    if (i < n4) {
        float4 v = src[i];
        __half hx, lx, hy, ly, hz, lz, hw, lw;
        split_fp16(v.x, hx, lx); split_fp16(v.y, hy, ly);
        split_fp16(v.z, hz, lz); split_fp16(v.w, hw, lw);
        hi[i * 2 + 0] = __halves2half2(hx, hy);
        hi[i * 2 + 1] = __halves2half2(hz, hw);
        lo[i * 2 + 0] = __halves2half2(lx, ly);
        lo[i * 2 + 1] = __halves2half2(lz, lw);
    }
}

// ---------------- fp32 -> fp16 convert (hi only, vectorized) ---------------
__global__ void cvt_kernel(const float4* __restrict__ src,
                           __half2* __restrict__ hi, int n4)
{
    int i = blockIdx.x * blockDim.x + threadIdx.x;
    if (i < n4) {
        float4 v = src[i];
        hi[i * 2 + 0] = __halves2half2(__float2half(v.x), __float2half(v.y));
        hi[i * 2 + 1] = __halves2half2(__float2half(v.z), __float2half(v.w));
    }
}

// ---------------- RoPE + gamma steering; q scaled by 1/sqrt(D) -------------
__global__ void rope_scale_kernel(const float* __restrict__ qkv,
                                  const int* __restrict__ pos,
                                  const float* __restrict__ prior,
                                  __half* __restrict__ qhi, __half* __restrict__ qlo,
                                  __half* __restrict__ khi)
{
    int s = blockIdx.x;
    int h = blockIdx.y;
    int d = threadIdx.x;   // 0..63

    float p = (float)pos[s];
    float inv = exp2f(-0.2076245760856056f * (float)d);
    float sn, c;
    sincosf(p * inv, &sn, &c);

    if (h < H) {
        const float* base = qkv + (size_t)s * QKVW + h * D;
        const float rsq = 0.08838834764831845f;
        float x1 = base[d], x2 = base[d + 64];
        float y1 = (x1 * c - x2 * sn) * rsq;
        float y2 = (x2 * c + x1 * sn) * rsq;
        size_t ob = (size_t)s * HID + h * D;
        __half hh, ll;
        split_fp16(y1, hh, ll); qhi[ob + d] = hh;      qlo[ob + d] = ll;
        split_fp16(y2, hh, ll); qhi[ob + d + 64] = hh; qlo[ob + d + 64] = ll;
    } else {
        const float* base = qkv + (size_t)s * QKVW + HID + (h - H) * D;
        float gg = 1.0f + 0.5f * prior[s];
        float scale = fminf(fmaxf(gg, 0.5f), 2.0f);
        float x1 = base[d], x2 = base[d + 64];
        float y1 = (x1 * c - x2 * sn) * scale;
        float y2 = (x2 * c + x1 * sn) * scale;
        size_t ob = (size_t)s * KVHID + (h - H) * D;
        khi[ob + d]      = __float2half(y1);
        khi[ob + d + 64] = __float2half(y2);
    }
}

// ---------------- v: eta scale + transpose; fp16 ---------------------------
__global__ void v_scale_transpose(const float* __restrict__ qkv,
                                  __half* __restrict__ vThi,
                                  const float* __restrict__ prior)
{
    int s = blockIdx.x;
    int c = blockIdx.y * 128 + threadIdx.x;
    float e = 1.0f + 0.5f * prior[s];
    float eta = fminf(fmaxf(e, 0.5f), 2.0f);
    float v = qkv[(size_t)s * QKVW + HID + KVHID + c];
    vThi[(size_t)c * S + s] = __float2half(v * eta);
}

// ---------------- launch ----------------------------------------------------
extern "C" void kernel_launch(void* const* d_in, const int* in_sizes, int n_in,
                              void* d_out, int out_size)
{
    const float* hs    = (const float*)d_in[0];
    const int*   pos   = (const int*)  d_in[2];
    const float* Wq    = (const float*)d_in[3];
    const float* Wk    = (const float*)d_in[4];
    const float* Wv    = (const float*)d_in[5];
    const float* Wo    = (const float*)d_in[6];
    const float* prior = (const float*)d_in[7];
    const float* m1    = (const float*)d_in[8];
    const float* m2    = (const float*)d_in[9];
    float* out = (float*)d_out;

    float *qkv;
    __half *hshi, *hslo, *wqkvhi, *wohi;
    __half *qhi, *qlo, *khi, *vthi, *cxhi, *cxlo;
    cudaGetSymbolAddress((void**)&qkv,   g_qkv);
    cudaGetSymbolAddress((void**)&hshi,  g_hs_hi);  cudaGetSymbolAddress((void**)&hslo, g_hs_lo);
    cudaGetSymbolAddress((void**)&wqkvhi,g_wqkv_hi);
    cudaGetSymbolAddress((void**)&wohi,  g_wo_hi);
    cudaGetSymbolAddress((void**)&qhi,   g_q_hi);   cudaGetSymbolAddress((void**)&qlo,  g_q_lo);
    cudaGetSymbolAddress((void**)&khi,   g_k_hi);
    cudaGetSymbolAddress((void**)&vthi,  g_vT_hi);
    cudaGetSymbolAddress((void**)&cxhi,  g_ctx_hi); cudaGetSymbolAddress((void**)&cxlo, g_ctx_lo);

    static int configured = 0;
    if (!configured) {
        cudaFuncSetAttribute(gemm_fp16x2, cudaFuncAttributeMaxDynamicSharedMemorySize, GSMEM);
        cudaFuncSetAttribute(flash_attn,  cudaFuncAttributeMaxDynamicSharedMemorySize, FA_SMEM);
        configured = 1;
    }

    dim3 blk(256);

    // 0) converts
    split_kernel<<<(S * HID / 4 + 255) / 256, 256>>>(
        (const float4*)hs, (__half2*)hshi, (__half2*)hslo, S * HID / 4);
    cvt_kernel<<<(HID * HID / 4 + 255) / 256, 256>>>(
        (const float4*)Wq, (__half2*)wqkvhi, HID * HID / 4);
    cvt_kernel<<<(KVHID * HID / 4 + 255) / 256, 256>>>(
        (const float4*)Wk, (__half2*)(wqkvhi + (size_t)HID * HID), KVHID * HID / 4);
    cvt_kernel<<<(KVHID * HID / 4 + 255) / 256, 256>>>(
        (const float4*)Wv, (__half2*)(wqkvhi + (size_t)(HID + KVHID) * HID), KVHID * HID / 4);
    cvt_kernel<<<(HID * HID / 4 + 255) / 256, 256>>>(
        (const float4*)Wo, (__half2*)wohi, HID * HID / 4);

    // 1) merged projection: qkv = hs @ [Wq|Wk|Wv]^T
    gemm_fp16x2<<<dim3(QKVW / 128, S / 128), blk, GSMEM>>>(
        hshi, hslo, wqkvhi, qkv, HID, HID, HID, QKVW);

    // 2) RoPE + gamma (+1/sqrt(D) into q); 3) eta + transpose
    rope_scale_kernel<<<dim3(S, H + HKV), 64>>>(qkv, pos, prior, qhi, qlo, khi);
    v_scale_transpose<<<dim3(S, KVHID / 128), 128>>>(qkv, vthi, prior);

    // 4) fused flash attention -> ctx hi/lo
    flash_attn<<<dim3(H, S / 128), blk, FA_SMEM>>>(
        qhi, qlo, khi, vthi, prior, m1, m2, cxhi, cxlo);

    // 5) out = ctx @ Wo^T
    gemm_fp16x2<<<dim3(HID / 128, S / 128), blk, GSMEM>>>(
        cxhi, cxlo, wohi, out, HID, HID, HID, HID);
}

// round 8
// speedup vs baseline: 8.6857x; 1.4188x over previous
#include <cuda_runtime.h>
#include <cuda_fp16.h>
#include <math.h>
#include <stdint.h>

// Problem constants (B=1)
#define S     1024
#define H     32
#define HKV   8
#define D     128
#define HID   4096
#define KVHID 1024
#define QKVW  (HID + 2 * KVHID)   // 6144
#define GROUPS 4

// ---------------- scratch (static device globals: no allocs allowed) -------
__device__ float g_qkv[(size_t)S * QKVW];

__device__ __half g_hs_hi[(size_t)S * HID];
__device__ __half g_wqkv_hi[(size_t)QKVW * HID];
__device__ __half g_wo_hi[(size_t)HID * HID];
__device__ __half g_q_hi[(size_t)S * HID];
__device__ __half g_k_hi[(size_t)S * KVHID];
__device__ __half g_vT_hi[(size_t)KVHID * S];
__device__ __half g_ctx_hi[(size_t)S * HID];

// ---------------- helpers ---------------------------------------------------
__device__ __forceinline__ void mma16816(float* c, const uint32_t* a, const uint32_t* b) {
    asm volatile(
        "mma.sync.aligned.m16n8k16.row.col.f32.f16.f16.f32 "
        "{%0,%1,%2,%3}, {%4,%5,%6,%7}, {%8,%9}, {%0,%1,%2,%3};"
        : "+f"(c[0]), "+f"(c[1]), "+f"(c[2]), "+f"(c[3])
        : "r"(a[0]), "r"(a[1]), "r"(a[2]), "r"(a[3]), "r"(b[0]), "r"(b[1]));
}

__device__ __forceinline__ void ldsm4(uint32_t* r, uint32_t addr) {
    asm volatile("ldmatrix.sync.aligned.m8n8.x4.shared.b16 {%0,%1,%2,%3}, [%4];"
        : "=r"(r[0]), "=r"(r[1]), "=r"(r[2]), "=r"(r[3]) : "r"(addr));
}

__device__ __forceinline__ void cp_async16(uint32_t smem_addr, const void* gptr) {
    asm volatile("cp.async.cg.shared.global [%0], [%1], 16;"
                 :: "r"(smem_addr), "l"(gptr));
}
__device__ __forceinline__ void cp_commit() {
    asm volatile("cp.async.commit_group;" ::: "memory");
}
template <int N>
__device__ __forceinline__ void cp_wait() {
    asm volatile("cp.async.wait_group %0;" :: "n"(N) : "memory");
}

__device__ __forceinline__ uint32_t smem_u32(const void* p) {
    uint32_t a;
    asm("{ .reg .u64 t; cvta.to.shared.u64 t, %1; cvt.u32.u64 %0, t; }"
        : "=r"(a) : "l"(p));
    return a;
}

__device__ __forceinline__ uint32_t packh2(float a, float b) {
    __half2 h = __halves2half2(__float2half(a), __float2half(b));
    return *(uint32_t*)&h;
}

// swizzled offset, 128-row x 64B operand tile
__device__ __forceinline__ uint32_t swoff(uint32_t r, uint32_t c) {
    return r * 64u + (((c ^ (r >> 1)) & 3u) << 4);
}

// ============ generic NT GEMM: single-product fp16 HMMA =====================
// C[m][n] = sum_k A[m][k]*B[n][k]   (A,B fp16; fp32 accum/out)
// Block tile 128x128, BK=32, 5-stage cp.async, ldmatrix, swizzled SMEM.
#define ARRB  8192             // 128 rows * 64 B
#define STGB  (2 * ARRB)       // Ahi|Bhi = 16384 B
#define STAGES 5
#define GSMEM (STAGES * STGB)  // 81920 B

__global__ void __launch_bounds__(256, 2) gemm_fp16(
    const __half* __restrict__ Ahi, const __half* __restrict__ Bhi,
    float* __restrict__ C, int K, int lda, int ldb, int ldc)
{
    extern __shared__ char smem[];
    const uint32_t smem_b = smem_u32(smem);
    const int tid = threadIdx.x;
    const int wid = tid >> 5;
    const int lane = tid & 31;
    const int g  = lane >> 2;
    const int tc = lane & 3;
    const int warp_m = wid & 3;
    const int warp_n = wid >> 2;
    const int KT = K / 32;

    Ahi += (size_t)blockIdx.y * 128 * lda;
    Bhi += (size_t)blockIdx.x * 128 * ldb;

    const int r0 = tid >> 2, c0 = tid & 3;
    const int r1 = (tid + 256) >> 2;
    const uint32_t sts0 = swoff(r0, c0);
    const uint32_t sts1 = swoff(r1, c0);

    const uint32_t aRow0 = warp_m * 32 + ((lane >> 3) & 1) * 8 + (lane & 7);
    const uint32_t aSel  = (uint32_t)lane >> 4;
    const uint32_t bSel  = ((uint32_t)lane >> 3) & 1;
    const uint32_t bRowB = warp_n * 64 + ((lane >> 4) & 1) * 8 + (lane & 7);

    float acc[2][8][4];
#pragma unroll
    for (int i = 0; i < 2; i++)
#pragma unroll
        for (int j = 0; j < 8; j++)
#pragma unroll
            for (int e = 0; e < 4; e++) acc[i][j][e] = 0.0f;

    auto issue_stage = [&](int kt, int s) {
        const uint32_t sb = smem_b + s * STGB;
        int kk = kt * 32;
        cp_async16(sb + sts0,        Ahi + (size_t)r0 * lda + kk + c0 * 8);
        cp_async16(sb + sts1,        Ahi + (size_t)r1 * lda + kk + c0 * 8);
        cp_async16(sb + ARRB + sts0, Bhi + (size_t)r0 * ldb + kk + c0 * 8);
        cp_async16(sb + ARRB + sts1, Bhi + (size_t)r1 * ldb + kk + c0 * 8);
    };

#pragma unroll
    for (int p = 0; p < STAGES - 1; p++) {
        if (p < KT) issue_stage(p, p);
        cp_commit();
    }

    int s = 0;
    for (int kt = 0; kt < KT; kt++) {
        cp_wait<STAGES - 2>();
        __syncthreads();

        int nk = kt + STAGES - 1;
        int ns = s + STAGES - 1; if (ns >= STAGES) ns -= STAGES;
        if (nk < KT) issue_stage(nk, ns);
        cp_commit();

        const uint32_t sa_hi = smem_b + s * STGB;
        const uint32_t sb_hi = sa_hi + ARRB;

#pragma unroll
        for (int ks = 0; ks < 2; ks++) {
            const uint32_t ac = ks * 2 + aSel;
            uint32_t AH[2][4];
#pragma unroll
            for (int mt = 0; mt < 2; mt++)
                ldsm4(AH[mt], sa_hi + swoff(aRow0 + mt * 16, ac));
            const uint32_t bc = ks * 2 + bSel;
#pragma unroll
            for (int p = 0; p < 4; p++) {
                uint32_t BH[4];
                ldsm4(BH, sb_hi + swoff(bRowB + p * 16, bc));
#pragma unroll
                for (int mt = 0; mt < 2; mt++)
#pragma unroll
                    for (int q = 0; q < 2; q++)
                        mma16816(acc[mt][2 * p + q], AH[mt], BH + 2 * q);
            }
        }
        if (++s == STAGES) s = 0;
    }

    const int rowb = blockIdx.y * 128 + warp_m * 32;
    const int colb = blockIdx.x * 128 + warp_n * 64;
#pragma unroll
    for (int mt = 0; mt < 2; mt++)
#pragma unroll
        for (int nt = 0; nt < 8; nt++) {
            int rr = rowb + mt * 16 + g;
            int cc = colb + nt * 8 + tc * 2;
            *(float2*)(C + (size_t)rr * ldc + cc) =
                make_float2(acc[mt][nt][0], acc[mt][nt][1]);
            *(float2*)(C + (size_t)(rr + 8) * ldc + cc) =
                make_float2(acc[mt][nt][2], acc[mt][nt][3]);
        }
}

// ======================= fused flash attention ==============================
// One CTA = (head h, 128-row Q block by). S = Q.K^T (single fp16 product —
// QK errors are negligible vs the O(1) bias spread), online steering softmax
// (binary l1/l2), O += P.V, O /= sum. Emits ctx hi fp16.
#define FA_QHI   0
#define FA_BIAS  32768
#define FA_U     36864
#define FA_KV0   40960
#define FA_KSTG  65536
#define FA_SMEM  (FA_KV0 + 2 * FA_KSTG)   // 172032

__global__ void __launch_bounds__(256, 1) flash_attn(
    const __half* __restrict__ qhi,
    const __half* __restrict__ khi, const __half* __restrict__ vthi,
    const float* __restrict__ prior, const float* __restrict__ m1,
    const float* __restrict__ m2,
    __half* __restrict__ cxhi)
{
    const int h    = blockIdx.x;
    const int by   = 7 - (int)blockIdx.y;   // heavy blocks dispatched first
    const int hk   = h >> 2;
    const int nblk = by + 1;

    extern __shared__ char smem[];
    const uint32_t sb = smem_u32(smem);
    const int tid = threadIdx.x;
    const int wid = tid >> 5;
    const int lane = tid & 31;
    const int g = lane >> 2, tc = lane & 3;

    const float l1 = m1[h], l2 = m2[h];

    float* biasb = (float*)(smem + FA_BIAS);
    float* ub    = (float*)(smem + FA_U);
    for (int j = tid; j < S; j += 256) {
        float pj = prior[j];
        biasb[j] = fminf(fmaxf(pj, -5.0f), 5.0f) * l1;
        ub[j]    = 1.0f + 0.5f * pj * l2;
    }

    // Q tile -> SMEM, 4 sub-arrays of 128x32 fp16
    {
        const __half* qh = qhi + (size_t)(by * 128) * HID + h * D;
#pragma unroll
        for (int t = 0; t < 8; t++) {
            int id = tid + t * 256;
            int r = id >> 4, cc = id & 15;
            uint32_t dst = (uint32_t)(cc >> 2) * 8192 + swoff(r, cc & 3);
            cp_async16(sb + FA_QHI + dst, qh + (size_t)r * HID + cc * 8);
        }
    }

    auto issue_kv = [&](int j, int st) {
        const uint32_t kb = sb + FA_KV0 + st * FA_KSTG;
        const __half* kp = khi  + (size_t)(j * 128) * KVHID + hk * D;
        const __half* vp = vthi + (size_t)(hk * 128) * S + j * 128;
#pragma unroll
        for (int t = 0; t < 8; t++) {
            int id = tid + t * 256;
            int r = id >> 4, cc = id & 15;
            uint32_t dst = (uint32_t)(cc >> 2) * 8192 + swoff(r, cc & 3);
            cp_async16(kb + dst,         kp + (size_t)r * KVHID + cc * 8);
            cp_async16(kb + 32768 + dst, vp + (size_t)r * S + cc * 8);
        }
    };

    issue_kv(0, 0);
    cp_commit();

    const uint32_t aRowQ = wid * 16 + ((lane >> 3) & 1) * 8 + (lane & 7);
    const uint32_t aSel  = (uint32_t)lane >> 4;
    const uint32_t bSel  = ((uint32_t)lane >> 3) & 1;
    const uint32_t bRow  = ((lane >> 4) & 1) * 8 + (lane & 7);

    float oacc[16][4];
#pragma unroll
    for (int i = 0; i < 16; i++)
#pragma unroll
        for (int e = 0; e < 4; e++) oacc[i][e] = 0.0f;
    float mrun0 = -1e30f, mrun1 = -1e30f;
    float srun0 = 0.0f,   srun1 = 0.0f;

    const int row0 = wid * 16 + g;

    for (int j = 0; j < nblk; j++) {
        const int st = j & 1;
        if (j + 1 < nblk) { issue_kv(j + 1, st ^ 1); cp_commit(); cp_wait<1>(); }
        else              { cp_wait<0>(); }
        __syncthreads();

        const uint32_t kb = sb + FA_KV0 + st * FA_KSTG;
        const uint32_t vb = kb + 32768;

        // ---- S = Q.K^T ----
        float sacc[16][4];
#pragma unroll
        for (int i = 0; i < 16; i++)
#pragma unroll
            for (int e = 0; e < 4; e++) sacc[i][e] = 0.0f;

#pragma unroll
        for (int kf = 0; kf < 8; kf++) {
            uint32_t sub = (uint32_t)(kf >> 1) * 8192;
            uint32_t kc  = (uint32_t)(kf & 1) * 2;
            uint32_t AH[4];
            ldsm4(AH, sb + FA_QHI + sub + swoff(aRowQ, kc + aSel));
#pragma unroll
            for (int p = 0; p < 8; p++) {
                uint32_t BH[4];
                ldsm4(BH, kb + sub + swoff(bRow + p * 16, kc + bSel));
#pragma unroll
                for (int q = 0; q < 2; q++)
                    mma16816(sacc[2 * p + q], AH, BH + 2 * q);
            }
        }

        // ---- online steering softmax ----
        const float* bias = biasb + j * 128;
        const float* uu   = ub + j * 128;
        const bool diag = (j == by);

        float mb0 = -1e30f, mb1 = -1e30f;
#pragma unroll
        for (int nt = 0; nt < 16; nt++) {
            int k0 = nt * 8 + tc * 2;
            float b0 = bias[k0], b1 = bias[k0 + 1];
            float a0 = sacc[nt][0] + b0;
            float a1 = sacc[nt][1] + b1;
            float a2 = sacc[nt][2] + b0;
            float a3 = sacc[nt][3] + b1;
            if (diag) {
                if (k0     > row0)     a0 = -1e30f;
                if (k0 + 1 > row0)     a1 = -1e30f;
                if (k0     > row0 + 8) a2 = -1e30f;
                if (k0 + 1 > row0 + 8) a3 = -1e30f;
            }
            sacc[nt][0] = a0; sacc[nt][1] = a1;
            sacc[nt][2] = a2; sacc[nt][3] = a3;
            mb0 = fmaxf(mb0, fmaxf(a0, a1));
            mb1 = fmaxf(mb1, fmaxf(a2, a3));
        }
        mb0 = fmaxf(mb0, __shfl_xor_sync(0xffffffffu, mb0, 1));
        mb0 = fmaxf(mb0, __shfl_xor_sync(0xffffffffu, mb0, 2));
        mb1 = fmaxf(mb1, __shfl_xor_sync(0xffffffffu, mb1, 1));
        mb1 = fmaxf(mb1, __shfl_xor_sync(0xffffffffu, mb1, 2));

        float mn0 = fmaxf(mrun0, mb0);
        float mn1 = fmaxf(mrun1, mb1);
        float sc0 = __expf(mrun0 - mn0);
        float sc1 = __expf(mrun1 - mn1);
        mrun0 = mn0; mrun1 = mn1;

        float rs0 = 0.0f, rs1 = 0.0f;
#pragma unroll
        for (int nt = 0; nt < 16; nt++) {
            int k0 = nt * 8 + tc * 2;
            float u0 = uu[k0], u1 = uu[k0 + 1];
            float e0 = __expf(sacc[nt][0] - mn0) * u0;
            float e1 = __expf(sacc[nt][1] - mn0) * u1;
            float e2 = __expf(sacc[nt][2] - mn1) * u0;
            float e3 = __expf(sacc[nt][3] - mn1) * u1;
            sacc[nt][0] = e0; sacc[nt][1] = e1;
            sacc[nt][2] = e2; sacc[nt][3] = e3;
            rs0 += e0 + e1; rs1 += e2 + e3;
            oacc[nt][0] *= sc0; oacc[nt][1] *= sc0;
            oacc[nt][2] *= sc1; oacc[nt][3] *= sc1;
        }
        rs0 += __shfl_xor_sync(0xffffffffu, rs0, 1);
        rs0 += __shfl_xor_sync(0xffffffffu, rs0, 2);
        rs1 += __shfl_xor_sync(0xffffffffu, rs1, 1);
        rs1 += __shfl_xor_sync(0xffffffffu, rs1, 2);
        srun0 = srun0 * sc0 + rs0;
        srun1 = srun1 * sc1 + rs1;

        // ---- O += P.V (C-frag -> A-frag repack) ----
#pragma unroll
        for (int kf = 0; kf < 8; kf++) {
            uint32_t AP[4];
            AP[0] = packh2(sacc[2 * kf][0],     sacc[2 * kf][1]);
            AP[1] = packh2(sacc[2 * kf][2],     sacc[2 * kf][3]);
            AP[2] = packh2(sacc[2 * kf + 1][0], sacc[2 * kf + 1][1]);
            AP[3] = packh2(sacc[2 * kf + 1][2], sacc[2 * kf + 1][3]);
            uint32_t sub = (uint32_t)(kf >> 1) * 8192;
            uint32_t kc  = (uint32_t)(kf & 1) * 2;
#pragma unroll
            for (int p = 0; p < 8; p++) {
                uint32_t BV[4];
                ldsm4(BV, vb + sub + swoff(bRow + p * 16, kc + bSel));
                mma16816(oacc[2 * p],     AP, BV);
                mma16816(oacc[2 * p + 1], AP, BV + 2);
            }
        }
        __syncthreads();
    }

    // ---- epilogue: normalize, fp16 ctx ----
    float inv0 = 1.0f / srun0;
    float inv1 = 1.0f / srun1;
    int grow = by * 128 + wid * 16 + g;
    __half* Hp = cxhi + (size_t)grow * HID + h * D + tc * 2;
#pragma unroll
    for (int nt = 0; nt < 16; nt++) {
        *(__half2*)(Hp + nt * 8) =
            __halves2half2(__float2half(oacc[nt][0] * inv0),
                           __float2half(oacc[nt][1] * inv0));
        *(__half2*)(Hp + (size_t)8 * HID + nt * 8) =
            __halves2half2(__float2half(oacc[nt][2] * inv1),
                           __float2half(oacc[nt][3] * inv1));
    }
}

// ---------------- fp32 -> fp16 convert (4 float4 per thread) ---------------
__global__ void cvt_kernel(const float4* __restrict__ src,
                           __half2* __restrict__ hi, int n4)
{
    int i0 = (blockIdx.x * blockDim.x + threadIdx.x) * 4;
#pragma unroll
    for (int t = 0; t < 4; t++) {
        int i = i0 + t;
        if (i < n4) {
            float4 v = src[i];
            hi[i * 2 + 0] = __halves2half2(__float2half(v.x), __float2half(v.y));
            hi[i * 2 + 1] = __halves2half2(__float2half(v.z), __float2half(v.w));
        }
    }
}

// ---------------- RoPE + gamma steering; q scaled by 1/sqrt(D) -------------
__global__ void rope_scale_kernel(const float* __restrict__ qkv,
                                  const int* __restrict__ pos,
                                  const float* __restrict__ prior,
                                  __half* __restrict__ qhi,
                                  __half* __restrict__ khi)
{
    int s = blockIdx.x;
    int h = blockIdx.y;
    int d = threadIdx.x;   // 0..63

    float p = (float)pos[s];
    float inv = exp2f(-0.2076245760856056f * (float)d);  // 10000^(-d/64)
    float sn, c;
    sincosf(p * inv, &sn, &c);

    if (h < H) {
        const float* base = qkv + (size_t)s * QKVW + h * D;
        const float rsq = 0.08838834764831845f;
        float x1 = base[d], x2 = base[d + 64];
        float y1 = (x1 * c - x2 * sn) * rsq;
        float y2 = (x2 * c + x1 * sn) * rsq;
        size_t ob = (size_t)s * HID + h * D;
        qhi[ob + d]      = __float2half(y1);
        qhi[ob + d + 64] = __float2half(y2);
    } else {
        const float* base = qkv + (size_t)s * QKVW + HID + (h - H) * D;
        float gg = 1.0f + 0.5f * prior[s];
        float scale = fminf(fmaxf(gg, 0.5f), 2.0f);
        float x1 = base[d], x2 = base[d + 64];
        float y1 = (x1 * c - x2 * sn) * scale;
        float y2 = (x2 * c + x1 * sn) * scale;
        size_t ob = (size_t)s * KVHID + (h - H) * D;
        khi[ob + d]      = __float2half(y1);
        khi[ob + d + 64] = __float2half(y2);
    }
}

// ---------------- v: eta scale + transpose; fp16 ---------------------------
__global__ void v_scale_transpose(const float* __restrict__ qkv,
                                  __half* __restrict__ vThi,
                                  const float* __restrict__ prior)
{
    int s = blockIdx.x;
    int c = blockIdx.y * 128 + threadIdx.x;
    float e = 1.0f + 0.5f * prior[s];
    float eta = fminf(fmaxf(e, 0.5f), 2.0f);
    float v = qkv[(size_t)s * QKVW + HID + KVHID + c];
    vThi[(size_t)c * S + s] = __float2half(v * eta);
}

// ---------------- launch ----------------------------------------------------
extern "C" void kernel_launch(void* const* d_in, const int* in_sizes, int n_in,
                              void* d_out, int out_size)
{
    const float* hs    = (const float*)d_in[0];
    const int*   pos   = (const int*)  d_in[2];
    const float* Wq    = (const float*)d_in[3];
    const float* Wk    = (const float*)d_in[4];
    const float* Wv    = (const float*)d_in[5];
    const float* Wo    = (const float*)d_in[6];
    const float* prior = (const float*)d_in[7];
    const float* m1    = (const float*)d_in[8];
    const float* m2    = (const float*)d_in[9];
    float* out = (float*)d_out;

    float *qkv;
    __half *hshi, *wqkvhi, *wohi, *qhi, *khi, *vthi, *cxhi;
    cudaGetSymbolAddress((void**)&qkv,   g_qkv);
    cudaGetSymbolAddress((void**)&hshi,  g_hs_hi);
    cudaGetSymbolAddress((void**)&wqkvhi,g_wqkv_hi);
    cudaGetSymbolAddress((void**)&wohi,  g_wo_hi);
    cudaGetSymbolAddress((void**)&qhi,   g_q_hi);
    cudaGetSymbolAddress((void**)&khi,   g_k_hi);
    cudaGetSymbolAddress((void**)&vthi,  g_vT_hi);
    cudaGetSymbolAddress((void**)&cxhi,  g_ctx_hi);

    static int configured = 0;
    if (!configured) {
        cudaFuncSetAttribute(gemm_fp16, cudaFuncAttributeMaxDynamicSharedMemorySize, GSMEM);
        cudaFuncSetAttribute(flash_attn, cudaFuncAttributeMaxDynamicSharedMemorySize, FA_SMEM);
        configured = 1;
    }

    dim3 blk(256);

    // 0) converts (fp32 -> fp16)
    cvt_kernel<<<(S * HID / 4 + 1023) / 1024, 256>>>(
        (const float4*)hs, (__half2*)hshi, S * HID / 4);
    cvt_kernel<<<(HID * HID / 4 + 1023) / 1024, 256>>>(
        (const float4*)Wq, (__half2*)wqkvhi, HID * HID / 4);
    cvt_kernel<<<(KVHID * HID / 4 + 1023) / 1024, 256>>>(
        (const float4*)Wk, (__half2*)(wqkvhi + (size_t)HID * HID), KVHID * HID / 4);
    cvt_kernel<<<(KVHID * HID / 4 + 1023) / 1024, 256>>>(
        (const float4*)Wv, (__half2*)(wqkvhi + (size_t)(HID + KVHID) * HID), KVHID * HID / 4);
    cvt_kernel<<<(HID * HID / 4 + 1023) / 1024, 256>>>(
        (const float4*)Wo, (__half2*)wohi, HID * HID / 4);

    // 1) merged projection: qkv = hs @ [Wq|Wk|Wv]^T
    gemm_fp16<<<dim3(QKVW / 128, S / 128), blk, GSMEM>>>(
        hshi, wqkvhi, qkv, HID, HID, HID, QKVW);

    // 2) RoPE + gamma (+1/sqrt(D) into q); 3) eta + transpose
    rope_scale_kernel<<<dim3(S, H + HKV), 64>>>(qkv, pos, prior, qhi, khi);
    v_scale_transpose<<<dim3(S, KVHID / 128), 128>>>(qkv, vthi, prior);

    // 4) fused flash attention -> ctx fp16
    flash_attn<<<dim3(H, S / 128), blk, FA_SMEM>>>(
        qhi, khi, vthi, prior, m1, m2, cxhi);

    // 5) out = ctx @ Wo^T
    gemm_fp16<<<dim3(HID / 128, S / 128), blk, GSMEM>>>(
        cxhi, wohi, out, HID, HID, HID, HID);
}

// round 9
// speedup vs baseline: 10.4024x; 1.1976x over previous
#include <cuda_runtime.h>
#include <cuda_fp16.h>
#include <math.h>
#include <stdint.h>

// Problem constants (B=1)
#define S     1024
#define H     32
#define HKV   8
#define D     128
#define HID   4096
#define KVHID 1024
#define QKVW  (HID + 2 * KVHID)   // 6144
#define GROUPS 4

// ---------------- scratch (static device globals: no allocs allowed) -------
__device__ float g_qkv[(size_t)S * QKVW];

__device__ __half g_hs_hi[(size_t)S * HID];
__device__ __half g_wqkv_hi[(size_t)QKVW * HID];
__device__ __half g_wo_hi[(size_t)HID * HID];
__device__ __half g_q_hi[(size_t)S * HID];
__device__ __half g_k_hi[(size_t)S * KVHID];
__device__ __half g_vT_hi[(size_t)KVHID * S];
__device__ __half g_ctx_hi[(size_t)S * HID];

// ---------------- helpers ---------------------------------------------------
__device__ __forceinline__ void mma16816(float* c, const uint32_t* a, const uint32_t* b) {
    asm volatile(
        "mma.sync.aligned.m16n8k16.row.col.f32.f16.f16.f32 "
        "{%0,%1,%2,%3}, {%4,%5,%6,%7}, {%8,%9}, {%0,%1,%2,%3};"
        : "+f"(c[0]), "+f"(c[1]), "+f"(c[2]), "+f"(c[3])
        : "r"(a[0]), "r"(a[1]), "r"(a[2]), "r"(a[3]), "r"(b[0]), "r"(b[1]));
}

__device__ __forceinline__ void ldsm4(uint32_t* r, uint32_t addr) {
    asm volatile("ldmatrix.sync.aligned.m8n8.x4.shared.b16 {%0,%1,%2,%3}, [%4];"
        : "=r"(r[0]), "=r"(r[1]), "=r"(r[2]), "=r"(r[3]) : "r"(addr));
}

__device__ __forceinline__ void cp_async16(uint32_t smem_addr, const void* gptr) {
    asm volatile("cp.async.cg.shared.global [%0], [%1], 16;"
                 :: "r"(smem_addr), "l"(gptr));
}
__device__ __forceinline__ void cp_commit() {
    asm volatile("cp.async.commit_group;" ::: "memory");
}
template <int N>
__device__ __forceinline__ void cp_wait() {
    asm volatile("cp.async.wait_group %0;" :: "n"(N) : "memory");
}

__device__ __forceinline__ uint32_t smem_u32(const void* p) {
    uint32_t a;
    asm("{ .reg .u64 t; cvta.to.shared.u64 t, %1; cvt.u32.u64 %0, t; }"
        : "=r"(a) : "l"(p));
    return a;
}

__device__ __forceinline__ uint32_t packh2(float a, float b) {
    __half2 h = __halves2half2(__float2half(a), __float2half(b));
    return *(uint32_t*)&h;
}

// swizzled offset, 128-row x 64B operand tile
__device__ __forceinline__ uint32_t swoff(uint32_t r, uint32_t c) {
    return r * 64u + (((c ^ (r >> 1)) & 3u) << 4);
}

// ============ generic NT GEMM: single-product fp16 HMMA =====================
// C[m][n] = sum_k A[m][k]*B[n][k]   (A,B fp16; fp32 accum/out)
// Block tile 128x128, BK=32, 5-stage cp.async, ldmatrix, swizzled SMEM.
#define ARRB  8192             // 128 rows * 64 B
#define STGB  (2 * ARRB)       // Ahi|Bhi = 16384 B
#define STAGES 5
#define GSMEM (STAGES * STGB)  // 81920 B

__global__ void __launch_bounds__(256, 2) gemm_fp16(
    const __half* __restrict__ Ahi, const __half* __restrict__ Bhi,
    float* __restrict__ C, int K, int lda, int ldb, int ldc)
{
    extern __shared__ char smem[];
    const uint32_t smem_b = smem_u32(smem);
    const int tid = threadIdx.x;
    const int wid = tid >> 5;
    const int lane = tid & 31;
    const int g  = lane >> 2;
    const int tc = lane & 3;
    const int warp_m = wid & 3;
    const int warp_n = wid >> 2;
    const int KT = K / 32;

    Ahi += (size_t)blockIdx.y * 128 * lda;
    Bhi += (size_t)blockIdx.x * 128 * ldb;

    const int r0 = tid >> 2, c0 = tid & 3;
    const int r1 = (tid + 256) >> 2;
    const uint32_t sts0 = swoff(r0, c0);
    const uint32_t sts1 = swoff(r1, c0);

    const uint32_t aRow0 = warp_m * 32 + ((lane >> 3) & 1) * 8 + (lane & 7);
    const uint32_t aSel  = (uint32_t)lane >> 4;
    const uint32_t bSel  = ((uint32_t)lane >> 3) & 1;
    const uint32_t bRowB = warp_n * 64 + ((lane >> 4) & 1) * 8 + (lane & 7);

    float acc[2][8][4];
#pragma unroll
    for (int i = 0; i < 2; i++)
#pragma unroll
        for (int j = 0; j < 8; j++)
#pragma unroll
            for (int e = 0; e < 4; e++) acc[i][j][e] = 0.0f;

    auto issue_stage = [&](int kt, int s) {
        const uint32_t sb = smem_b + s * STGB;
        int kk = kt * 32;
        cp_async16(sb + sts0,        Ahi + (size_t)r0 * lda + kk + c0 * 8);
        cp_async16(sb + sts1,        Ahi + (size_t)r1 * lda + kk + c0 * 8);
        cp_async16(sb + ARRB + sts0, Bhi + (size_t)r0 * ldb + kk + c0 * 8);
        cp_async16(sb + ARRB + sts1, Bhi + (size_t)r1 * ldb + kk + c0 * 8);
    };

#pragma unroll
    for (int p = 0; p < STAGES - 1; p++) {
        if (p < KT) issue_stage(p, p);
        cp_commit();
    }

    int s = 0;
    for (int kt = 0; kt < KT; kt++) {
        cp_wait<STAGES - 2>();
        __syncthreads();

        int nk = kt + STAGES - 1;
        int ns = s + STAGES - 1; if (ns >= STAGES) ns -= STAGES;
        if (nk < KT) issue_stage(nk, ns);
        cp_commit();

        const uint32_t sa_hi = smem_b + s * STGB;
        const uint32_t sb_hi = sa_hi + ARRB;

#pragma unroll
        for (int ks = 0; ks < 2; ks++) {
            const uint32_t ac = ks * 2 + aSel;
            uint32_t AH[2][4];
#pragma unroll
            for (int mt = 0; mt < 2; mt++)
                ldsm4(AH[mt], sa_hi + swoff(aRow0 + mt * 16, ac));
            const uint32_t bc = ks * 2 + bSel;
#pragma unroll
            for (int p = 0; p < 4; p++) {
                uint32_t BH[4];
                ldsm4(BH, sb_hi + swoff(bRowB + p * 16, bc));
#pragma unroll
                for (int mt = 0; mt < 2; mt++)
#pragma unroll
                    for (int q = 0; q < 2; q++)
                        mma16816(acc[mt][2 * p + q], AH[mt], BH + 2 * q);
            }
        }
        if (++s == STAGES) s = 0;
    }

    const int rowb = blockIdx.y * 128 + warp_m * 32;
    const int colb = blockIdx.x * 128 + warp_n * 64;
#pragma unroll
    for (int mt = 0; mt < 2; mt++)
#pragma unroll
        for (int nt = 0; nt < 8; nt++) {
            int rr = rowb + mt * 16 + g;
            int cc = colb + nt * 8 + tc * 2;
            *(float2*)(C + (size_t)rr * ldc + cc) =
                make_float2(acc[mt][nt][0], acc[mt][nt][1]);
            *(float2*)(C + (size_t)(rr + 8) * ldc + cc) =
                make_float2(acc[mt][nt][2], acc[mt][nt][3]);
        }
}

// ======================= fused flash attention ==============================
#define FA_QHI   0
#define FA_BIAS  32768
#define FA_U     36864
#define FA_KV0   40960
#define FA_KSTG  65536
#define FA_SMEM  (FA_KV0 + 2 * FA_KSTG)   // 172032

__global__ void __launch_bounds__(256, 1) flash_attn(
    const __half* __restrict__ qhi,
    const __half* __restrict__ khi, const __half* __restrict__ vthi,
    const float* __restrict__ prior, const float* __restrict__ m1,
    const float* __restrict__ m2,
    __half* __restrict__ cxhi)
{
    const int h    = blockIdx.x;
    const int by   = 7 - (int)blockIdx.y;   // heavy blocks dispatched first
    const int hk   = h >> 2;
    const int nblk = by + 1;

    extern __shared__ char smem[];
    const uint32_t sb = smem_u32(smem);
    const int tid = threadIdx.x;
    const int wid = tid >> 5;
    const int lane = tid & 31;
    const int g = lane >> 2, tc = lane & 3;

    const float l1 = m1[h], l2 = m2[h];

    float* biasb = (float*)(smem + FA_BIAS);
    float* ub    = (float*)(smem + FA_U);
    for (int j = tid; j < S; j += 256) {
        float pj = prior[j];
        biasb[j] = fminf(fmaxf(pj, -5.0f), 5.0f) * l1;
        ub[j]    = 1.0f + 0.5f * pj * l2;
    }

    // Q tile -> SMEM, 4 sub-arrays of 128x32 fp16
    {
        const __half* qh = qhi + (size_t)(by * 128) * HID + h * D;
#pragma unroll
        for (int t = 0; t < 8; t++) {
            int id = tid + t * 256;
            int r = id >> 4, cc = id & 15;
            uint32_t dst = (uint32_t)(cc >> 2) * 8192 + swoff(r, cc & 3);
            cp_async16(sb + FA_QHI + dst, qh + (size_t)r * HID + cc * 8);
        }
    }

    auto issue_kv = [&](int j, int st) {
        const uint32_t kb = sb + FA_KV0 + st * FA_KSTG;
        const __half* kp = khi  + (size_t)(j * 128) * KVHID + hk * D;
        const __half* vp = vthi + (size_t)(hk * 128) * S + j * 128;
#pragma unroll
        for (int t = 0; t < 8; t++) {
            int id = tid + t * 256;
            int r = id >> 4, cc = id & 15;
            uint32_t dst = (uint32_t)(cc >> 2) * 8192 + swoff(r, cc & 3);
            cp_async16(kb + dst,         kp + (size_t)r * KVHID + cc * 8);
            cp_async16(kb + 32768 + dst, vp + (size_t)r * S + cc * 8);
        }
    };

    issue_kv(0, 0);
    cp_commit();

    const uint32_t aRowQ = wid * 16 + ((lane >> 3) & 1) * 8 + (lane & 7);
    const uint32_t aSel  = (uint32_t)lane >> 4;
    const uint32_t bSel  = ((uint32_t)lane >> 3) & 1;
    const uint32_t bRow  = ((lane >> 4) & 1) * 8 + (lane & 7);

    float oacc[16][4];
#pragma unroll
    for (int i = 0; i < 16; i++)
#pragma unroll
        for (int e = 0; e < 4; e++) oacc[i][e] = 0.0f;
    float mrun0 = -1e30f, mrun1 = -1e30f;
    float srun0 = 0.0f,   srun1 = 0.0f;

    const int row0 = wid * 16 + g;

    for (int j = 0; j < nblk; j++) {
        const int st = j & 1;
        if (j + 1 < nblk) { issue_kv(j + 1, st ^ 1); cp_commit(); cp_wait<1>(); }
        else              { cp_wait<0>(); }
        __syncthreads();

        const uint32_t kb = sb + FA_KV0 + st * FA_KSTG;
        const uint32_t vb = kb + 32768;

        // ---- S = Q.K^T ----
        float sacc[16][4];
#pragma unroll
        for (int i = 0; i < 16; i++)
#pragma unroll
            for (int e = 0; e < 4; e++) sacc[i][e] = 0.0f;

#pragma unroll
        for (int kf = 0; kf < 8; kf++) {
            uint32_t sub = (uint32_t)(kf >> 1) * 8192;
            uint32_t kc  = (uint32_t)(kf & 1) * 2;
            uint32_t AH[4];
            ldsm4(AH, sb + FA_QHI + sub + swoff(aRowQ, kc + aSel));
#pragma unroll
            for (int p = 0; p < 8; p++) {
                uint32_t BH[4];
                ldsm4(BH, kb + sub + swoff(bRow + p * 16, kc + bSel));
#pragma unroll
                for (int q = 0; q < 2; q++)
                    mma16816(sacc[2 * p + q], AH, BH + 2 * q);
            }
        }

        // ---- online steering softmax ----
        const float* bias = biasb + j * 128;
        const float* uu   = ub + j * 128;
        const bool diag = (j == by);

        float mb0 = -1e30f, mb1 = -1e30f;
#pragma unroll
        for (int nt = 0; nt < 16; nt++) {
            int k0 = nt * 8 + tc * 2;
            float b0 = bias[k0], b1 = bias[k0 + 1];
            float a0 = sacc[nt][0] + b0;
            float a1 = sacc[nt][1] + b1;
            float a2 = sacc[nt][2] + b0;
            float a3 = sacc[nt][3] + b1;
            if (diag) {
                if (k0     > row0)     a0 = -1e30f;
                if (k0 + 1 > row0)     a1 = -1e30f;
                if (k0     > row0 + 8) a2 = -1e30f;
                if (k0 + 1 > row0 + 8) a3 = -1e30f;
            }
            sacc[nt][0] = a0; sacc[nt][1] = a1;
            sacc[nt][2] = a2; sacc[nt][3] = a3;
            mb0 = fmaxf(mb0, fmaxf(a0, a1));
            mb1 = fmaxf(mb1, fmaxf(a2, a3));
        }
        mb0 = fmaxf(mb0, __shfl_xor_sync(0xffffffffu, mb0, 1));
        mb0 = fmaxf(mb0, __shfl_xor_sync(0xffffffffu, mb0, 2));
        mb1 = fmaxf(mb1, __shfl_xor_sync(0xffffffffu, mb1, 1));
        mb1 = fmaxf(mb1, __shfl_xor_sync(0xffffffffu, mb1, 2));

        float mn0 = fmaxf(mrun0, mb0);
        float mn1 = fmaxf(mrun1, mb1);
        float sc0 = __expf(mrun0 - mn0);
        float sc1 = __expf(mrun1 - mn1);
        mrun0 = mn0; mrun1 = mn1;

        float rs0 = 0.0f, rs1 = 0.0f;
#pragma unroll
        for (int nt = 0; nt < 16; nt++) {
            int k0 = nt * 8 + tc * 2;
            float u0 = uu[k0], u1 = uu[k0 + 1];
            float e0 = __expf(sacc[nt][0] - mn0) * u0;
            float e1 = __expf(sacc[nt][1] - mn0) * u1;
            float e2 = __expf(sacc[nt][2] - mn1) * u0;
            float e3 = __expf(sacc[nt][3] - mn1) * u1;
            sacc[nt][0] = e0; sacc[nt][1] = e1;
            sacc[nt][2] = e2; sacc[nt][3] = e3;
            rs0 += e0 + e1; rs1 += e2 + e3;
            oacc[nt][0] *= sc0; oacc[nt][1] *= sc0;
            oacc[nt][2] *= sc1; oacc[nt][3] *= sc1;
        }
        rs0 += __shfl_xor_sync(0xffffffffu, rs0, 1);
        rs0 += __shfl_xor_sync(0xffffffffu, rs0, 2);
        rs1 += __shfl_xor_sync(0xffffffffu, rs1, 1);
        rs1 += __shfl_xor_sync(0xffffffffu, rs1, 2);
        srun0 = srun0 * sc0 + rs0;
        srun1 = srun1 * sc1 + rs1;

        // ---- O += P.V ----
#pragma unroll
        for (int kf = 0; kf < 8; kf++) {
            uint32_t AP[4];
            AP[0] = packh2(sacc[2 * kf][0],     sacc[2 * kf][1]);
            AP[1] = packh2(sacc[2 * kf][2],     sacc[2 * kf][3]);
            AP[2] = packh2(sacc[2 * kf + 1][0], sacc[2 * kf + 1][1]);
            AP[3] = packh2(sacc[2 * kf + 1][2], sacc[2 * kf + 1][3]);
            uint32_t sub = (uint32_t)(kf >> 1) * 8192;
            uint32_t kc  = (uint32_t)(kf & 1) * 2;
#pragma unroll
            for (int p = 0; p < 8; p++) {
                uint32_t BV[4];
                ldsm4(BV, vb + sub + swoff(bRow + p * 16, kc + bSel));
                mma16816(oacc[2 * p],     AP, BV);
                mma16816(oacc[2 * p + 1], AP, BV + 2);
            }
        }
        __syncthreads();
    }

    // ---- epilogue ----
    float inv0 = 1.0f / srun0;
    float inv1 = 1.0f / srun1;
    int grow = by * 128 + wid * 16 + g;
    __half* Hp = cxhi + (size_t)grow * HID + h * D + tc * 2;
#pragma unroll
    for (int nt = 0; nt < 16; nt++) {
        *(__half2*)(Hp + nt * 8) =
            __halves2half2(__float2half(oacc[nt][0] * inv0),
                           __float2half(oacc[nt][1] * inv0));
        *(__half2*)(Hp + (size_t)8 * HID + nt * 8) =
            __halves2half2(__float2half(oacc[nt][2] * inv1),
                           __float2half(oacc[nt][3] * inv1));
    }
}

// ---------------- fp32 -> fp16 convert (coalesced grid-stride) -------------
__global__ void cvt_kernel(const float4* __restrict__ src,
                           __half2* __restrict__ hi, int n4)
{
    int stride = gridDim.x * blockDim.x;
    for (int i = blockIdx.x * blockDim.x + threadIdx.x; i < n4; i += stride) {
        float4 v = src[i];
        hi[i * 2 + 0] = __halves2half2(__float2half(v.x), __float2half(v.y));
        hi[i * 2 + 1] = __halves2half2(__float2half(v.z), __float2half(v.w));
    }
}

// ---------------- RoPE + gamma steering; q scaled by 1/sqrt(D) -------------
// block = 256 threads = 4 heads' worth of rotation pairs for one s
__global__ void rope_scale_kernel(const float* __restrict__ qkv,
                                  const int* __restrict__ pos,
                                  const float* __restrict__ prior,
                                  __half* __restrict__ qhi,
                                  __half* __restrict__ khi)
{
    int s  = blockIdx.x;
    int h  = blockIdx.y * 4 + (threadIdx.x >> 6);   // head index 0..39
    int d  = threadIdx.x & 63;

    float p = (float)pos[s];
    float inv = exp2f(-0.2076245760856056f * (float)d);  // 10000^(-d/64)
    float sn, c;
    sincosf(p * inv, &sn, &c);

    if (h < H) {
        const float* base = qkv + (size_t)s * QKVW + h * D;
        const float rsq = 0.08838834764831845f;
        float x1 = base[d], x2 = base[d + 64];
        float y1 = (x1 * c - x2 * sn) * rsq;
        float y2 = (x2 * c + x1 * sn) * rsq;
        size_t ob = (size_t)s * HID + h * D;
        qhi[ob + d]      = __float2half(y1);
        qhi[ob + d + 64] = __float2half(y2);
    } else {
        const float* base = qkv + (size_t)s * QKVW + HID + (h - H) * D;
        float gg = 1.0f + 0.5f * prior[s];
        float scale = fminf(fmaxf(gg, 0.5f), 2.0f);
        float x1 = base[d], x2 = base[d + 64];
        float y1 = (x1 * c - x2 * sn) * scale;
        float y2 = (x2 * c + x1 * sn) * scale;
        size_t ob = (size_t)s * KVHID + (h - H) * D;
        khi[ob + d]      = __float2half(y1);
        khi[ob + d + 64] = __float2half(y2);
    }
}

// ---------------- v: eta scale + 32x32 tiled transpose (coalesced) ---------
// grid (S/32, KVHID/32), 256 threads (8 rows of 32)
__global__ void v_scale_transpose(const float* __restrict__ qkv,
                                  __half* __restrict__ vThi,
                                  const float* __restrict__ prior)
{
    __shared__ __half tile[32][33];
    __shared__ float  eta_s[32];
    int s0 = blockIdx.x * 32;
    int c0 = blockIdx.y * 32;
    int tx = threadIdx.x & 31;      // column within tile
    int ty = threadIdx.x >> 5;      // row group (0..7)

    if (threadIdx.x < 32) {
        float e = 1.0f + 0.5f * prior[s0 + threadIdx.x];
        eta_s[threadIdx.x] = fminf(fmaxf(e, 0.5f), 2.0f);
    }
    __syncthreads();

#pragma unroll
    for (int r = 0; r < 4; r++) {
        int srow = ty + r * 8 + 0;          // 0..31 over 4 iters
        int ss = s0 + ty + r * 8;
        float v = qkv[(size_t)ss * QKVW + HID + KVHID + c0 + tx];
        tile[ty + r * 8][tx] = __float2half(v * eta_s[ty + r * 8]);
        (void)srow;
    }
    __syncthreads();

#pragma unroll
    for (int r = 0; r < 4; r++) {
        int cc = ty + r * 8;                // local col -> global c0+cc
        vThi[(size_t)(c0 + cc) * S + s0 + tx] = tile[tx][cc];
    }
}

// ---------------- launch ----------------------------------------------------
extern "C" void kernel_launch(void* const* d_in, const int* in_sizes, int n_in,
                              void* d_out, int out_size)
{
    const float* hs    = (const float*)d_in[0];
    const int*   pos   = (const int*)  d_in[2];
    const float* Wq    = (const float*)d_in[3];
    const float* Wk    = (const float*)d_in[4];
    const float* Wv    = (const float*)d_in[5];
    const float* Wo    = (const float*)d_in[6];
    const float* prior = (const float*)d_in[7];
    const float* m1    = (const float*)d_in[8];
    const float* m2    = (const float*)d_in[9];
    float* out = (float*)d_out;

    float *qkv;
    __half *hshi, *wqkvhi, *wohi, *qhi, *khi, *vthi, *cxhi;
    cudaGetSymbolAddress((void**)&qkv,   g_qkv);
    cudaGetSymbolAddress((void**)&hshi,  g_hs_hi);
    cudaGetSymbolAddress((void**)&wqkvhi,g_wqkv_hi);
    cudaGetSymbolAddress((void**)&wohi,  g_wo_hi);
    cudaGetSymbolAddress((void**)&qhi,   g_q_hi);
    cudaGetSymbolAddress((void**)&khi,   g_k_hi);
    cudaGetSymbolAddress((void**)&vthi,  g_vT_hi);
    cudaGetSymbolAddress((void**)&cxhi,  g_ctx_hi);

    static int configured = 0;
    if (!configured) {
        cudaFuncSetAttribute(gemm_fp16, cudaFuncAttributeMaxDynamicSharedMemorySize, GSMEM);
        cudaFuncSetAttribute(flash_attn, cudaFuncAttributeMaxDynamicSharedMemorySize, FA_SMEM);
        configured = 1;
    }

    dim3 blk(256);

    // 0) converts (fp32 -> fp16), coalesced grid-stride, ~2 iters/thread
    cvt_kernel<<<2048, 256>>>((const float4*)hs, (__half2*)hshi, S * HID / 4);
    cvt_kernel<<<8192, 256>>>((const float4*)Wq, (__half2*)wqkvhi, HID * HID / 4);
    cvt_kernel<<<2048, 256>>>(
        (const float4*)Wk, (__half2*)(wqkvhi + (size_t)HID * HID), KVHID * HID / 4);
    cvt_kernel<<<2048, 256>>>(
        (const float4*)Wv, (__half2*)(wqkvhi + (size_t)(HID + KVHID) * HID), KVHID * HID / 4);
    cvt_kernel<<<8192, 256>>>((const float4*)Wo, (__half2*)wohi, HID * HID / 4);

    // 1) merged projection: qkv = hs @ [Wq|Wk|Wv]^T
    gemm_fp16<<<dim3(QKVW / 128, S / 128), blk, GSMEM>>>(
        hshi, wqkvhi, qkv, HID, HID, HID, QKVW);

    // 2) RoPE + gamma (+1/sqrt(D) into q); 3) eta + tiled transpose
    rope_scale_kernel<<<dim3(S, (H + HKV) / 4), 256>>>(qkv, pos, prior, qhi, khi);
    v_scale_transpose<<<dim3(S / 32, KVHID / 32), 256>>>(qkv, vthi, prior);

    // 4) fused flash attention -> ctx fp16
    flash_attn<<<dim3(H, S / 128), blk, FA_SMEM>>>(
        qhi, khi, vthi, prior, m1, m2, cxhi);

    // 5) out = ctx @ Wo^T
    gemm_fp16<<<dim3(HID / 128, S / 128), blk, GSMEM>>>(
        cxhi, wohi, out, HID, HID, HID, HID);
}

// round 10
// speedup vs baseline: 10.7127x; 1.0298x over previous
#include <cuda_runtime.h>
#include <cuda_fp16.h>
#include <math.h>
#include <stdint.h>

// Problem constants (B=1)
#define S     1024
#define H     32
#define HKV   8
#define D     128
#define HID   4096
#define KVHID 1024
#define QKVW  (HID + 2 * KVHID)   // 6144
#define GROUPS 4

// ---------------- scratch (static device globals: no allocs allowed) -------
__device__ float g_qkv[(size_t)S * QKVW];

__device__ __half g_hs_hi[(size_t)S * HID];
__device__ __half g_wqkv_hi[(size_t)QKVW * HID];
__device__ __half g_wo_hi[(size_t)HID * HID];
__device__ __half g_q_hi[(size_t)S * HID];
__device__ __half g_k_hi[(size_t)S * KVHID];
__device__ __half g_vT_hi[(size_t)KVHID * S];
__device__ __half g_ctx_hi[(size_t)S * HID];

// ---------------- helpers ---------------------------------------------------
__device__ __forceinline__ void mma16816(float* c, const uint32_t* a, const uint32_t* b) {
    asm volatile(
        "mma.sync.aligned.m16n8k16.row.col.f32.f16.f16.f32 "
        "{%0,%1,%2,%3}, {%4,%5,%6,%7}, {%8,%9}, {%0,%1,%2,%3};"
        : "+f"(c[0]), "+f"(c[1]), "+f"(c[2]), "+f"(c[3])
        : "r"(a[0]), "r"(a[1]), "r"(a[2]), "r"(a[3]), "r"(b[0]), "r"(b[1]));
}

__device__ __forceinline__ void ldsm4(uint32_t* r, uint32_t addr) {
    asm volatile("ldmatrix.sync.aligned.m8n8.x4.shared.b16 {%0,%1,%2,%3}, [%4];"
        : "=r"(r[0]), "=r"(r[1]), "=r"(r[2]), "=r"(r[3]) : "r"(addr));
}

__device__ __forceinline__ void cp_async16(uint32_t smem_addr, const void* gptr) {
    asm volatile("cp.async.cg.shared.global [%0], [%1], 16;"
                 :: "r"(smem_addr), "l"(gptr));
}
__device__ __forceinline__ void cp_commit() {
    asm volatile("cp.async.commit_group;" ::: "memory");
}
template <int N>
__device__ __forceinline__ void cp_wait() {
    asm volatile("cp.async.wait_group %0;" :: "n"(N) : "memory");
}

__device__ __forceinline__ uint32_t smem_u32(const void* p) {
    uint32_t a;
    asm("{ .reg .u64 t; cvta.to.shared.u64 t, %1; cvt.u32.u64 %0, t; }"
        : "=r"(a) : "l"(p));
    return a;
}

__device__ __forceinline__ uint32_t packh2(float a, float b) {
    __half2 h = __halves2half2(__float2half(a), __float2half(b));
    return *(uint32_t*)&h;
}

// swizzled offset, 128-row x 64B operand tile
__device__ __forceinline__ uint32_t swoff(uint32_t r, uint32_t c) {
    return r * 64u + (((c ^ (r >> 1)) & 3u) << 4);
}

// ============ generic NT GEMM: single-product fp16 HMMA =====================
#define ARRB  8192             // 128 rows * 64 B
#define STGB  (2 * ARRB)       // Ahi|Bhi = 16384 B
#define STAGES 5
#define GSMEM (STAGES * STGB)  // 81920 B

__global__ void __launch_bounds__(256, 2) gemm_fp16(
    const __half* __restrict__ Ahi, const __half* __restrict__ Bhi,
    float* __restrict__ C, int K, int lda, int ldb, int ldc)
{
    extern __shared__ char smem[];
    const uint32_t smem_b = smem_u32(smem);
    const int tid = threadIdx.x;
    const int wid = tid >> 5;
    const int lane = tid & 31;
    const int g  = lane >> 2;
    const int tc = lane & 3;
    const int warp_m = wid & 3;
    const int warp_n = wid >> 2;
    const int KT = K / 32;

    Ahi += (size_t)blockIdx.y * 128 * lda;
    Bhi += (size_t)blockIdx.x * 128 * ldb;

    const int r0 = tid >> 2, c0 = tid & 3;
    const int r1 = (tid + 256) >> 2;
    const uint32_t sts0 = swoff(r0, c0);
    const uint32_t sts1 = swoff(r1, c0);

    const uint32_t aRow0 = warp_m * 32 + ((lane >> 3) & 1) * 8 + (lane & 7);
    const uint32_t aSel  = (uint32_t)lane >> 4;
    const uint32_t bSel  = ((uint32_t)lane >> 3) & 1;
    const uint32_t bRowB = warp_n * 64 + ((lane >> 4) & 1) * 8 + (lane & 7);

    float acc[2][8][4];
#pragma unroll
    for (int i = 0; i < 2; i++)
#pragma unroll
        for (int j = 0; j < 8; j++)
#pragma unroll
            for (int e = 0; e < 4; e++) acc[i][j][e] = 0.0f;

    auto issue_stage = [&](int kt, int s) {
        const uint32_t sb = smem_b + s * STGB;
        int kk = kt * 32;
        cp_async16(sb + sts0,        Ahi + (size_t)r0 * lda + kk + c0 * 8);
        cp_async16(sb + sts1,        Ahi + (size_t)r1 * lda + kk + c0 * 8);
        cp_async16(sb + ARRB + sts0, Bhi + (size_t)r0 * ldb + kk + c0 * 8);
        cp_async16(sb + ARRB + sts1, Bhi + (size_t)r1 * ldb + kk + c0 * 8);
    };

#pragma unroll
    for (int p = 0; p < STAGES - 1; p++) {
        if (p < KT) issue_stage(p, p);
        cp_commit();
    }

    int s = 0;
    for (int kt = 0; kt < KT; kt++) {
        cp_wait<STAGES - 2>();
        __syncthreads();

        int nk = kt + STAGES - 1;
        int ns = s + STAGES - 1; if (ns >= STAGES) ns -= STAGES;
        if (nk < KT) issue_stage(nk, ns);
        cp_commit();

        const uint32_t sa_hi = smem_b + s * STGB;
        const uint32_t sb_hi = sa_hi + ARRB;

#pragma unroll
        for (int ks = 0; ks < 2; ks++) {
            const uint32_t ac = ks * 2 + aSel;
            uint32_t AH[2][4];
#pragma unroll
            for (int mt = 0; mt < 2; mt++)
                ldsm4(AH[mt], sa_hi + swoff(aRow0 + mt * 16, ac));
            const uint32_t bc = ks * 2 + bSel;
#pragma unroll
            for (int p = 0; p < 4; p++) {
                uint32_t BH[4];
                ldsm4(BH, sb_hi + swoff(bRowB + p * 16, bc));
#pragma unroll
                for (int mt = 0; mt < 2; mt++)
#pragma unroll
                    for (int q = 0; q < 2; q++)
                        mma16816(acc[mt][2 * p + q], AH[mt], BH + 2 * q);
            }
        }
        if (++s == STAGES) s = 0;
    }

    const int rowb = blockIdx.y * 128 + warp_m * 32;
    const int colb = blockIdx.x * 128 + warp_n * 64;
#pragma unroll
    for (int mt = 0; mt < 2; mt++)
#pragma unroll
        for (int nt = 0; nt < 8; nt++) {
            int rr = rowb + mt * 16 + g;
            int cc = colb + nt * 8 + tc * 2;
            *(float2*)(C + (size_t)rr * ldc + cc) =
                make_float2(acc[mt][nt][0], acc[mt][nt][1]);
            *(float2*)(C + (size_t)(rr + 8) * ldc + cc) =
                make_float2(acc[mt][nt][2], acc[mt][nt][3]);
        }
}

// ======================= fused flash attention ==============================
#define FA_QHI   0
#define FA_BIAS  32768
#define FA_U     36864
#define FA_KV0   40960
#define FA_KSTG  65536
#define FA_SMEM  (FA_KV0 + 2 * FA_KSTG)   // 172032

__global__ void __launch_bounds__(256, 1) flash_attn(
    const __half* __restrict__ qhi,
    const __half* __restrict__ khi, const __half* __restrict__ vthi,
    const float* __restrict__ prior, const float* __restrict__ m1,
    const float* __restrict__ m2,
    __half* __restrict__ cxhi)
{
    const int h    = blockIdx.x;
    const int by   = 7 - (int)blockIdx.y;   // heavy blocks dispatched first
    const int hk   = h >> 2;
    const int nblk = by + 1;

    extern __shared__ char smem[];
    const uint32_t sb = smem_u32(smem);
    const int tid = threadIdx.x;
    const int wid = tid >> 5;
    const int lane = tid & 31;
    const int g = lane >> 2, tc = lane & 3;

    const float l1 = m1[h], l2 = m2[h];

    float* biasb = (float*)(smem + FA_BIAS);
    float* ub    = (float*)(smem + FA_U);
    for (int j = tid; j < S; j += 256) {
        float pj = prior[j];
        biasb[j] = fminf(fmaxf(pj, -5.0f), 5.0f) * l1;
        ub[j]    = 1.0f + 0.5f * pj * l2;
    }

    // Q tile -> SMEM, 4 sub-arrays of 128x32 fp16
    {
        const __half* qh = qhi + (size_t)(by * 128) * HID + h * D;
#pragma unroll
        for (int t = 0; t < 8; t++) {
            int id = tid + t * 256;
            int r = id >> 4, cc = id & 15;
            uint32_t dst = (uint32_t)(cc >> 2) * 8192 + swoff(r, cc & 3);
            cp_async16(sb + FA_QHI + dst, qh + (size_t)r * HID + cc * 8);
        }
    }

    auto issue_kv = [&](int j, int st) {
        const uint32_t kb = sb + FA_KV0 + st * FA_KSTG;
        const __half* kp = khi  + (size_t)(j * 128) * KVHID + hk * D;
        const __half* vp = vthi + (size_t)(hk * 128) * S + j * 128;
#pragma unroll
        for (int t = 0; t < 8; t++) {
            int id = tid + t * 256;
            int r = id >> 4, cc = id & 15;
            uint32_t dst = (uint32_t)(cc >> 2) * 8192 + swoff(r, cc & 3);
            cp_async16(kb + dst,         kp + (size_t)r * KVHID + cc * 8);
            cp_async16(kb + 32768 + dst, vp + (size_t)r * S + cc * 8);
        }
    };

    issue_kv(0, 0);
    cp_commit();

    const uint32_t aRowQ = wid * 16 + ((lane >> 3) & 1) * 8 + (lane & 7);
    const uint32_t aSel  = (uint32_t)lane >> 4;
    const uint32_t bSel  = ((uint32_t)lane >> 3) & 1;
    const uint32_t bRow  = ((lane >> 4) & 1) * 8 + (lane & 7);

    float oacc[16][4];
#pragma unroll
    for (int i = 0; i < 16; i++)
#pragma unroll
        for (int e = 0; e < 4; e++) oacc[i][e] = 0.0f;
    float mrun0 = -1e30f, mrun1 = -1e30f;
    float srun0 = 0.0f,   srun1 = 0.0f;

    const int row0 = wid * 16 + g;

    for (int j = 0; j < nblk; j++) {
        const int st = j & 1;
        if (j + 1 < nblk) { issue_kv(j + 1, st ^ 1); cp_commit(); cp_wait<1>(); }
        else              { cp_wait<0>(); }
        __syncthreads();

        const uint32_t kb = sb + FA_KV0 + st * FA_KSTG;
        const uint32_t vb = kb + 32768;

        // ---- S = Q.K^T ----
        float sacc[16][4];
#pragma unroll
        for (int i = 0; i < 16; i++)
#pragma unroll
            for (int e = 0; e < 4; e++) sacc[i][e] = 0.0f;

#pragma unroll
        for (int kf = 0; kf < 8; kf++) {
            uint32_t sub = (uint32_t)(kf >> 1) * 8192;
            uint32_t kc  = (uint32_t)(kf & 1) * 2;
            uint32_t AH[4];
            ldsm4(AH, sb + FA_QHI + sub + swoff(aRowQ, kc + aSel));
#pragma unroll
            for (int p = 0; p < 8; p++) {
                uint32_t BH[4];
                ldsm4(BH, kb + sub + swoff(bRow + p * 16, kc + bSel));
#pragma unroll
                for (int q = 0; q < 2; q++)
                    mma16816(sacc[2 * p + q], AH, BH + 2 * q);
            }
        }

        // ---- online steering softmax ----
        const float* bias = biasb + j * 128;
        const float* uu   = ub + j * 128;
        const bool diag = (j == by);

        float mb0 = -1e30f, mb1 = -1e30f;
#pragma unroll
        for (int nt = 0; nt < 16; nt++) {
            int k0 = nt * 8 + tc * 2;
            float b0 = bias[k0], b1 = bias[k0 + 1];
            float a0 = sacc[nt][0] + b0;
            float a1 = sacc[nt][1] + b1;
            float a2 = sacc[nt][2] + b0;
            float a3 = sacc[nt][3] + b1;
            if (diag) {
                if (k0     > row0)     a0 = -1e30f;
                if (k0 + 1 > row0)     a1 = -1e30f;
                if (k0     > row0 + 8) a2 = -1e30f;
                if (k0 + 1 > row0 + 8) a3 = -1e30f;
            }
            sacc[nt][0] = a0; sacc[nt][1] = a1;
            sacc[nt][2] = a2; sacc[nt][3] = a3;
            mb0 = fmaxf(mb0, fmaxf(a0, a1));
            mb1 = fmaxf(mb1, fmaxf(a2, a3));
        }
        mb0 = fmaxf(mb0, __shfl_xor_sync(0xffffffffu, mb0, 1));
        mb0 = fmaxf(mb0, __shfl_xor_sync(0xffffffffu, mb0, 2));
        mb1 = fmaxf(mb1, __shfl_xor_sync(0xffffffffu, mb1, 1));
        mb1 = fmaxf(mb1, __shfl_xor_sync(0xffffffffu, mb1, 2));

        float mn0 = fmaxf(mrun0, mb0);
        float mn1 = fmaxf(mrun1, mb1);
        float sc0 = __expf(mrun0 - mn0);
        float sc1 = __expf(mrun1 - mn1);
        mrun0 = mn0; mrun1 = mn1;

        float rs0 = 0.0f, rs1 = 0.0f;
#pragma unroll
        for (int nt = 0; nt < 16; nt++) {
            int k0 = nt * 8 + tc * 2;
            float u0 = uu[k0], u1 = uu[k0 + 1];
            float e0 = __expf(sacc[nt][0] - mn0) * u0;
            float e1 = __expf(sacc[nt][1] - mn0) * u1;
            float e2 = __expf(sacc[nt][2] - mn1) * u0;
            float e3 = __expf(sacc[nt][3] - mn1) * u1;
            sacc[nt][0] = e0; sacc[nt][1] = e1;
            sacc[nt][2] = e2; sacc[nt][3] = e3;
            rs0 += e0 + e1; rs1 += e2 + e3;
            oacc[nt][0] *= sc0; oacc[nt][1] *= sc0;
            oacc[nt][2] *= sc1; oacc[nt][3] *= sc1;
        }
        rs0 += __shfl_xor_sync(0xffffffffu, rs0, 1);
        rs0 += __shfl_xor_sync(0xffffffffu, rs0, 2);
        rs1 += __shfl_xor_sync(0xffffffffu, rs1, 1);
        rs1 += __shfl_xor_sync(0xffffffffu, rs1, 2);
        srun0 = srun0 * sc0 + rs0;
        srun1 = srun1 * sc1 + rs1;

        // ---- O += P.V ----
#pragma unroll
        for (int kf = 0; kf < 8; kf++) {
            uint32_t AP[4];
            AP[0] = packh2(sacc[2 * kf][0],     sacc[2 * kf][1]);
            AP[1] = packh2(sacc[2 * kf][2],     sacc[2 * kf][3]);
            AP[2] = packh2(sacc[2 * kf + 1][0], sacc[2 * kf + 1][1]);
            AP[3] = packh2(sacc[2 * kf + 1][2], sacc[2 * kf + 1][3]);
            uint32_t sub = (uint32_t)(kf >> 1) * 8192;
            uint32_t kc  = (uint32_t)(kf & 1) * 2;
#pragma unroll
            for (int p = 0; p < 8; p++) {
                uint32_t BV[4];
                ldsm4(BV, vb + sub + swoff(bRow + p * 16, kc + bSel));
                mma16816(oacc[2 * p],     AP, BV);
                mma16816(oacc[2 * p + 1], AP, BV + 2);
            }
        }
        __syncthreads();
    }

    // ---- epilogue ----
    float inv0 = 1.0f / srun0;
    float inv1 = 1.0f / srun1;
    int grow = by * 128 + wid * 16 + g;
    __half* Hp = cxhi + (size_t)grow * HID + h * D + tc * 2;
#pragma unroll
    for (int nt = 0; nt < 16; nt++) {
        *(__half2*)(Hp + nt * 8) =
            __halves2half2(__float2half(oacc[nt][0] * inv0),
                           __float2half(oacc[nt][1] * inv0));
        *(__half2*)(Hp + (size_t)8 * HID + nt * 8) =
            __halves2half2(__float2half(oacc[nt][2] * inv1),
                           __float2half(oacc[nt][3] * inv1));
    }
}

// ---------------- fused fp32 -> fp16 convert (all 5 tensors, one launch) ---
// One float4 per thread-iteration; one uint2 (8B) store. Segment boundaries
// are multiples of 2^20 float4s, so warps never straddle segments.
#define N4_HS  (S * HID / 4)          // 1M
#define N4_WQ  (HID * HID / 4)        // 4M
#define N4_WK  (KVHID * HID / 4)      // 1M
#define N4_WV  (KVHID * HID / 4)      // 1M
#define N4_WO  (HID * HID / 4)        // 4M
#define N4_TOT (N4_HS + N4_WQ + N4_WK + N4_WV + N4_WO)   // 11M

__global__ void cvt_all_kernel(
    const float4* __restrict__ hs, const float4* __restrict__ wq,
    const float4* __restrict__ wk, const float4* __restrict__ wv,
    const float4* __restrict__ wo,
    uint2* __restrict__ hshi, uint2* __restrict__ wqkvhi,
    uint2* __restrict__ wohi)
{
    const int c1 = N4_HS;
    const int c2 = c1 + N4_WQ;
    const int c3 = c2 + N4_WK;
    const int c4 = c3 + N4_WV;
    int stride = gridDim.x * blockDim.x;
    for (int i = blockIdx.x * blockDim.x + threadIdx.x; i < N4_TOT; i += stride) {
        const float4* src;
        uint2* dst;
        int off;
        if (i < c1)       { src = hs; dst = hshi;   off = i; }
        else if (i < c2)  { src = wq; dst = wqkvhi; off = i - c1; }
        else if (i < c3)  { src = wk; dst = wqkvhi + N4_WQ; off = i - c2; }
        else if (i < c4)  { src = wv; dst = wqkvhi + N4_WQ + N4_WK; off = i - c3; }
        else              { src = wo; dst = wohi;   off = i - c4; }
        float4 v = src[off];
        __half2 a = __floats2half2_rn(v.x, v.y);
        __half2 b = __floats2half2_rn(v.z, v.w);
        uint2 w;
        w.x = *(uint32_t*)&a;
        w.y = *(uint32_t*)&b;
        dst[off] = w;
    }
}

// ---------------- fused RoPE(+gamma) and V eta-scale+transpose -------------
// grid (1024, 11): y<10 -> rope (4 heads per block); y==10 -> one 32x32
// transpose tile per x (s0 = (x&31)*32, c0 = (x>>5)*32).
__global__ void prep_kernel(const float* __restrict__ qkv,
                            const int* __restrict__ pos,
                            const float* __restrict__ prior,
                            __half* __restrict__ qhi,
                            __half* __restrict__ khi,
                            __half* __restrict__ vThi)
{
    if (blockIdx.y < 10) {
        int s  = blockIdx.x;
        int h  = blockIdx.y * 4 + (threadIdx.x >> 6);   // 0..39
        int d  = threadIdx.x & 63;

        float p = (float)pos[s];
        float inv = exp2f(-0.2076245760856056f * (float)d);  // 10000^(-d/64)
        float sn, c;
        sincosf(p * inv, &sn, &c);

        if (h < H) {
            const float* base = qkv + (size_t)s * QKVW + h * D;
            const float rsq = 0.08838834764831845f;
            float x1 = base[d], x2 = base[d + 64];
            float y1 = (x1 * c - x2 * sn) * rsq;
            float y2 = (x2 * c + x1 * sn) * rsq;
            size_t ob = (size_t)s * HID + h * D;
            qhi[ob + d]      = __float2half(y1);
            qhi[ob + d + 64] = __float2half(y2);
        } else {
            const float* base = qkv + (size_t)s * QKVW + HID + (h - H) * D;
            float gg = 1.0f + 0.5f * prior[s];
            float scale = fminf(fmaxf(gg, 0.5f), 2.0f);
            float x1 = base[d], x2 = base[d + 64];
            float y1 = (x1 * c - x2 * sn) * scale;
            float y2 = (x2 * c + x1 * sn) * scale;
            size_t ob = (size_t)s * KVHID + (h - H) * D;
            khi[ob + d]      = __float2half(y1);
            khi[ob + d + 64] = __float2half(y2);
        }
    } else {
        // V transpose: 32x32 tile
        __shared__ __half tile[32][33];
        __shared__ float  eta_s[32];
        int s0 = (blockIdx.x & 31) * 32;
        int c0 = (blockIdx.x >> 5) * 32;
        int tx = threadIdx.x & 31;
        int ty = threadIdx.x >> 5;

        if (threadIdx.x < 32) {
            float e = 1.0f + 0.5f * prior[s0 + threadIdx.x];
            eta_s[threadIdx.x] = fminf(fmaxf(e, 0.5f), 2.0f);
        }
        __syncthreads();

#pragma unroll
        for (int r = 0; r < 4; r++) {
            int ss = s0 + ty + r * 8;
            float v = qkv[(size_t)ss * QKVW + HID + KVHID + c0 + tx];
            tile[ty + r * 8][tx] = __float2half(v * eta_s[ty + r * 8]);
        }
        __syncthreads();

#pragma unroll
        for (int r = 0; r < 4; r++) {
            int cc = ty + r * 8;
            vThi[(size_t)(c0 + cc) * S + s0 + tx] = tile[tx][cc];
        }
    }
}

// ---------------- launch ----------------------------------------------------
extern "C" void kernel_launch(void* const* d_in, const int* in_sizes, int n_in,
                              void* d_out, int out_size)
{
    const float* hs    = (const float*)d_in[0];
    const int*   pos   = (const int*)  d_in[2];
    const float* Wq    = (const float*)d_in[3];
    const float* Wk    = (const float*)d_in[4];
    const float* Wv    = (const float*)d_in[5];
    const float* Wo    = (const float*)d_in[6];
    const float* prior = (const float*)d_in[7];
    const float* m1    = (const float*)d_in[8];
    const float* m2    = (const float*)d_in[9];
    float* out = (float*)d_out;

    float *qkv;
    __half *hshi, *wqkvhi, *wohi, *qhi, *khi, *vthi, *cxhi;
    cudaGetSymbolAddress((void**)&qkv,   g_qkv);
    cudaGetSymbolAddress((void**)&hshi,  g_hs_hi);
    cudaGetSymbolAddress((void**)&wqkvhi,g_wqkv_hi);
    cudaGetSymbolAddress((void**)&wohi,  g_wo_hi);
    cudaGetSymbolAddress((void**)&qhi,   g_q_hi);
    cudaGetSymbolAddress((void**)&khi,   g_k_hi);
    cudaGetSymbolAddress((void**)&vthi,  g_vT_hi);
    cudaGetSymbolAddress((void**)&cxhi,  g_ctx_hi);

    static int configured = 0;
    if (!configured) {
        cudaFuncSetAttribute(gemm_fp16, cudaFuncAttributeMaxDynamicSharedMemorySize, GSMEM);
        cudaFuncSetAttribute(flash_attn, cudaFuncAttributeMaxDynamicSharedMemorySize, FA_SMEM);
        configured = 1;
    }

    dim3 blk(256);

    // 0) all fp32->fp16 converts in one launch (uint2 stores)
    cvt_all_kernel<<<4096, 256>>>(
        (const float4*)hs, (const float4*)Wq, (const float4*)Wk,
        (const float4*)Wv, (const float4*)Wo,
        (uint2*)hshi, (uint2*)wqkvhi, (uint2*)wohi);

    // 1) merged projection: qkv = hs @ [Wq|Wk|Wv]^T
    gemm_fp16<<<dim3(QKVW / 128, S / 128), blk, GSMEM>>>(
        hshi, wqkvhi, qkv, HID, HID, HID, QKVW);

    // 2) RoPE + gamma (+1/sqrt(D) into q) and eta + tiled transpose, fused
    prep_kernel<<<dim3(S, 11), 256>>>(qkv, pos, prior, qhi, khi, vthi);

    // 3) fused flash attention -> ctx fp16
    flash_attn<<<dim3(H, S / 128), blk, FA_SMEM>>>(
        qhi, khi, vthi, prior, m1, m2, cxhi);

    // 4) out = ctx @ Wo^T
    gemm_fp16<<<dim3(HID / 128, S / 128), blk, GSMEM>>>(
        cxhi, wohi, out, HID, HID, HID, HID);
}

// round 11
// speedup vs baseline: 10.7258x; 1.0012x over previous
#include <cuda_runtime.h>
#include <cuda_fp16.h>
#include <math.h>
#include <stdint.h>

// Problem constants (B=1)
#define S     1024
#define H     32
#define HKV   8
#define D     128
#define HID   4096
#define KVHID 1024
#define QKVW  (HID + 2 * KVHID)   // 6144
#define GROUPS 4

// ---------------- scratch (static device globals: no allocs allowed) -------
__device__ __half g_hs_hi[(size_t)S * HID];
__device__ __half g_wqkv_hi[(size_t)QKVW * HID];
__device__ __half g_wo_hi[(size_t)HID * HID];
__device__ __half g_q_hi[(size_t)S * HID];
__device__ __half g_k_hi[(size_t)S * KVHID];
__device__ __half g_vT_hi[(size_t)KVHID * S];
__device__ __half g_ctx_hi[(size_t)S * HID];

// ---------------- helpers ---------------------------------------------------
__device__ __forceinline__ void mma16816(float* c, const uint32_t* a, const uint32_t* b) {
    asm volatile(
        "mma.sync.aligned.m16n8k16.row.col.f32.f16.f16.f32 "
        "{%0,%1,%2,%3}, {%4,%5,%6,%7}, {%8,%9}, {%0,%1,%2,%3};"
        : "+f"(c[0]), "+f"(c[1]), "+f"(c[2]), "+f"(c[3])
        : "r"(a[0]), "r"(a[1]), "r"(a[2]), "r"(a[3]), "r"(b[0]), "r"(b[1]));
}

__device__ __forceinline__ void ldsm4(uint32_t* r, uint32_t addr) {
    asm volatile("ldmatrix.sync.aligned.m8n8.x4.shared.b16 {%0,%1,%2,%3}, [%4];"
        : "=r"(r[0]), "=r"(r[1]), "=r"(r[2]), "=r"(r[3]) : "r"(addr));
}

__device__ __forceinline__ void cp_async16(uint32_t smem_addr, const void* gptr) {
    asm volatile("cp.async.cg.shared.global [%0], [%1], 16;"
                 :: "r"(smem_addr), "l"(gptr));
}
__device__ __forceinline__ void cp_commit() {
    asm volatile("cp.async.commit_group;" ::: "memory");
}
template <int N>
__device__ __forceinline__ void cp_wait() {
    asm volatile("cp.async.wait_group %0;" :: "n"(N) : "memory");
}

__device__ __forceinline__ uint32_t smem_u32(const void* p) {
    uint32_t a;
    asm("{ .reg .u64 t; cvta.to.shared.u64 t, %1; cvt.u32.u64 %0, t; }"
        : "=r"(a) : "l"(p));
    return a;
}

__device__ __forceinline__ uint32_t packh2(float a, float b) {
    __half2 h = __halves2half2(__float2half(a), __float2half(b));
    return *(uint32_t*)&h;
}

// swizzled offset, 128-row x 64B operand tile
__device__ __forceinline__ uint32_t swoff(uint32_t r, uint32_t c) {
    return r * 64u + (((c ^ (r >> 1)) & 3u) << 4);
}

// ============ generic NT GEMM: single-product fp16 HMMA =====================
// QKV_EPI=false: C[m][n] = sum_k A[m][k]*B[n][k] (fp32 out)
// QKV_EPI=true : fused projection epilogue — RoPE(+1/sqrt(D)) -> qhi,
//                RoPE(+gamma) -> khi, eta+transpose -> vThi. No C write.
#define ARRB  8192             // 128 rows * 64 B
#define STGB  (2 * ARRB)       // Ahi|Bhi = 16384 B
#define STAGES 5
#define GSMEM (STAGES * STGB)  // 81920 B
#define FT_STRIDE 132          // padded fp32 tile row stride (floats)

template <bool QKV_EPI>
__global__ void __launch_bounds__(256, 2) gemm_fp16(
    const __half* __restrict__ Ahi, const __half* __restrict__ Bhi,
    float* __restrict__ C, int K, int lda, int ldb, int ldc,
    const int* __restrict__ pos, const float* __restrict__ prior,
    __half* __restrict__ qhi, __half* __restrict__ khi,
    __half* __restrict__ vthi)
{
    extern __shared__ char smem[];
    const uint32_t smem_b = smem_u32(smem);
    const int tid = threadIdx.x;
    const int wid = tid >> 5;
    const int lane = tid & 31;
    const int g  = lane >> 2;
    const int tc = lane & 3;
    const int warp_m = wid & 3;
    const int warp_n = wid >> 2;
    const int KT = K / 32;

    Ahi += (size_t)blockIdx.y * 128 * lda;
    Bhi += (size_t)blockIdx.x * 128 * ldb;

    const int r0 = tid >> 2, c0 = tid & 3;
    const int r1 = (tid + 256) >> 2;
    const uint32_t sts0 = swoff(r0, c0);
    const uint32_t sts1 = swoff(r1, c0);

    const uint32_t aRow0 = warp_m * 32 + ((lane >> 3) & 1) * 8 + (lane & 7);
    const uint32_t aSel  = (uint32_t)lane >> 4;
    const uint32_t bSel  = ((uint32_t)lane >> 3) & 1;
    const uint32_t bRowB = warp_n * 64 + ((lane >> 4) & 1) * 8 + (lane & 7);

    float acc[2][8][4];
#pragma unroll
    for (int i = 0; i < 2; i++)
#pragma unroll
        for (int j = 0; j < 8; j++)
#pragma unroll
            for (int e = 0; e < 4; e++) acc[i][j][e] = 0.0f;

    auto issue_stage = [&](int kt, int s) {
        const uint32_t sb = smem_b + s * STGB;
        int kk = kt * 32;
        cp_async16(sb + sts0,        Ahi + (size_t)r0 * lda + kk + c0 * 8);
        cp_async16(sb + sts1,        Ahi + (size_t)r1 * lda + kk + c0 * 8);
        cp_async16(sb + ARRB + sts0, Bhi + (size_t)r0 * ldb + kk + c0 * 8);
        cp_async16(sb + ARRB + sts1, Bhi + (size_t)r1 * ldb + kk + c0 * 8);
    };

#pragma unroll
    for (int p = 0; p < STAGES - 1; p++) {
        if (p < KT) issue_stage(p, p);
        cp_commit();
    }

    int s = 0;
    for (int kt = 0; kt < KT; kt++) {
        cp_wait<STAGES - 2>();
        __syncthreads();

        int nk = kt + STAGES - 1;
        int ns = s + STAGES - 1; if (ns >= STAGES) ns -= STAGES;
        if (nk < KT) issue_stage(nk, ns);
        cp_commit();

        const uint32_t sa_hi = smem_b + s * STGB;
        const uint32_t sb_hi = sa_hi + ARRB;

#pragma unroll
        for (int ks = 0; ks < 2; ks++) {
            const uint32_t ac = ks * 2 + aSel;
            uint32_t AH[2][4];
#pragma unroll
            for (int mt = 0; mt < 2; mt++)
                ldsm4(AH[mt], sa_hi + swoff(aRow0 + mt * 16, ac));
            const uint32_t bc = ks * 2 + bSel;
#pragma unroll
            for (int p = 0; p < 4; p++) {
                uint32_t BH[4];
                ldsm4(BH, sb_hi + swoff(bRowB + p * 16, bc));
#pragma unroll
                for (int mt = 0; mt < 2; mt++)
#pragma unroll
                    for (int q = 0; q < 2; q++)
                        mma16816(acc[mt][2 * p + q], AH[mt], BH + 2 * q);
            }
        }
        if (++s == STAGES) s = 0;
    }

    if (!QKV_EPI) {
        const int rowb = blockIdx.y * 128 + warp_m * 32;
        const int colb = blockIdx.x * 128 + warp_n * 64;
#pragma unroll
        for (int mt = 0; mt < 2; mt++)
#pragma unroll
            for (int nt = 0; nt < 8; nt++) {
                int rr = rowb + mt * 16 + g;
                int cc = colb + nt * 8 + tc * 2;
                *(float2*)(C + (size_t)rr * ldc + cc) =
                    make_float2(acc[mt][nt][0], acc[mt][nt][1]);
                *(float2*)(C + (size_t)(rr + 8) * ldc + cc) =
                    make_float2(acc[mt][nt][2], acc[mt][nt][3]);
            }
        return;
    }

    // ================= fused QKV projection epilogue =================
    __syncthreads();                       // stages no longer needed
    float* ft     = (float*)smem;          // 128 x 132 fp32 tile (67.6 KB)
    float* eta_sm = (float*)(smem + 128 * FT_STRIDE * 4);   // 128 floats

    const int s0 = blockIdx.y * 128;
#pragma unroll
    for (int mt = 0; mt < 2; mt++)
#pragma unroll
        for (int nt = 0; nt < 8; nt++) {
            int rr = warp_m * 32 + mt * 16 + g;
            int cc = warp_n * 64 + nt * 8 + tc * 2;
            *(float2*)(ft + rr * FT_STRIDE + cc) =
                make_float2(acc[mt][nt][0], acc[mt][nt][1]);
            *(float2*)(ft + (rr + 8) * FT_STRIDE + cc) =
                make_float2(acc[mt][nt][2], acc[mt][nt][3]);
        }
    if (tid < 128) {
        float pr = prior[s0 + tid];
        eta_sm[tid] = fminf(fmaxf(1.0f + 0.5f * pr, 0.5f), 2.0f);  // gamma==eta
    }
    __syncthreads();

    const int bx = blockIdx.x;
    if (bx < 40) {
        // RoPE path (q: bx 0..31, k: bx 32..39)
        const int r  = tid >> 1;            // row 0..127
        const int dh = (tid & 1) << 5;      // 0 / 32
        const int ss = s0 + r;
        const float p = (float)pos[ss];
        const float scale = (bx < 32) ? 0.08838834764831845f : eta_sm[r];

        uint32_t w1[16], w2[16];
#pragma unroll
        for (int jv = 0; jv < 8; jv++) {
            float4 X1 = *(const float4*)(ft + r * FT_STRIDE + dh + jv * 4);
            float4 X2 = *(const float4*)(ft + r * FT_STRIDE + dh + 64 + jv * 4);
            float y1[4], y2[4];
            const float* x1 = (const float*)&X1;
            const float* x2 = (const float*)&X2;
#pragma unroll
            for (int e = 0; e < 4; e++) {
                int d = dh + jv * 4 + e;
                float inv = exp2f(-0.2076245760856056f * (float)d);
                float sn, cs;
                sincosf(p * inv, &sn, &cs);
                y1[e] = (x1[e] * cs - x2[e] * sn) * scale;
                y2[e] = (x2[e] * cs + x1[e] * sn) * scale;
            }
            w1[jv * 2]     = packh2(y1[0], y1[1]);
            w1[jv * 2 + 1] = packh2(y1[2], y1[3]);
            w2[jv * 2]     = packh2(y2[0], y2[1]);
            w2[jv * 2 + 1] = packh2(y2[2], y2[3]);
        }
        __half* dst = (bx < 32)
            ? qhi + (size_t)ss * HID + bx * 128
            : khi + (size_t)ss * KVHID + (bx - 32) * 128;
#pragma unroll
        for (int k4 = 0; k4 < 4; k4++) {
            *(uint4*)(dst + dh + k4 * 8) =
                make_uint4(w1[k4 * 4], w1[k4 * 4 + 1], w1[k4 * 4 + 2], w1[k4 * 4 + 3]);
            *(uint4*)(dst + dh + 64 + k4 * 8) =
                make_uint4(w2[k4 * 4], w2[k4 * 4 + 1], w2[k4 * 4 + 2], w2[k4 * 4 + 3]);
        }
    } else {
        // V path: eta scale + transpose -> vThi[(hv*128+cc)*S + s]
        const int hv = bx - 40;
#pragma unroll
        for (int ci = 0; ci < 16; ci++) {
            int cc = wid * 16 + ci;
            size_t base = (size_t)(hv * 128 + cc) * S + s0;
#pragma unroll
            for (int q2 = 0; q2 < 4; q2++) {
                int r = lane + 32 * q2;
                vthi[base + r] = __float2half(ft[r * FT_STRIDE + cc] * eta_sm[r]);
            }
        }
    }
}

// ======================= fused flash attention ==============================
#define FA_QHI   0
#define FA_BIAS  32768
#define FA_U     36864
#define FA_KV0   40960
#define FA_KSTG  65536
#define FA_SMEM  (FA_KV0 + 2 * FA_KSTG)   // 172032

__global__ void __launch_bounds__(256, 1) flash_attn(
    const __half* __restrict__ qhi,
    const __half* __restrict__ khi, const __half* __restrict__ vthi,
    const float* __restrict__ prior, const float* __restrict__ m1,
    const float* __restrict__ m2,
    __half* __restrict__ cxhi)
{
    const int h    = blockIdx.x;
    const int by   = 7 - (int)blockIdx.y;   // heavy blocks dispatched first
    const int hk   = h >> 2;
    const int nblk = by + 1;

    extern __shared__ char smem[];
    const uint32_t sb = smem_u32(smem);
    const int tid = threadIdx.x;
    const int wid = tid >> 5;
    const int lane = tid & 31;
    const int g = lane >> 2, tc = lane & 3;

    const float l1 = m1[h], l2 = m2[h];

    float* biasb = (float*)(smem + FA_BIAS);
    float* ub    = (float*)(smem + FA_U);
    for (int j = tid; j < S; j += 256) {
        float pj = prior[j];
        biasb[j] = fminf(fmaxf(pj, -5.0f), 5.0f) * l1;
        ub[j]    = 1.0f + 0.5f * pj * l2;
    }

    {
        const __half* qh = qhi + (size_t)(by * 128) * HID + h * D;
#pragma unroll
        for (int t = 0; t < 8; t++) {
            int id = tid + t * 256;
            int r = id >> 4, cc = id & 15;
            uint32_t dst = (uint32_t)(cc >> 2) * 8192 + swoff(r, cc & 3);
            cp_async16(sb + FA_QHI + dst, qh + (size_t)r * HID + cc * 8);
        }
    }

    auto issue_kv = [&](int j, int st) {
        const uint32_t kb = sb + FA_KV0 + st * FA_KSTG;
        const __half* kp = khi  + (size_t)(j * 128) * KVHID + hk * D;
        const __half* vp = vthi + (size_t)(hk * 128) * S + j * 128;
#pragma unroll
        for (int t = 0; t < 8; t++) {
            int id = tid + t * 256;
            int r = id >> 4, cc = id & 15;
            uint32_t dst = (uint32_t)(cc >> 2) * 8192 + swoff(r, cc & 3);
            cp_async16(kb + dst,         kp + (size_t)r * KVHID + cc * 8);
            cp_async16(kb + 32768 + dst, vp + (size_t)r * S + cc * 8);
        }
    };

    issue_kv(0, 0);
    cp_commit();

    const uint32_t aRowQ = wid * 16 + ((lane >> 3) & 1) * 8 + (lane & 7);
    const uint32_t aSel  = (uint32_t)lane >> 4;
    const uint32_t bSel  = ((uint32_t)lane >> 3) & 1;
    const uint32_t bRow  = ((lane >> 4) & 1) * 8 + (lane & 7);

    float oacc[16][4];
#pragma unroll
    for (int i = 0; i < 16; i++)
#pragma unroll
        for (int e = 0; e < 4; e++) oacc[i][e] = 0.0f;
    float mrun0 = -1e30f, mrun1 = -1e30f;
    float srun0 = 0.0f,   srun1 = 0.0f;

    const int row0 = wid * 16 + g;

    for (int j = 0; j < nblk; j++) {
        const int st = j & 1;
        if (j + 1 < nblk) { issue_kv(j + 1, st ^ 1); cp_commit(); cp_wait<1>(); }
        else              { cp_wait<0>(); }
        __syncthreads();

        const uint32_t kb = sb + FA_KV0 + st * FA_KSTG;
        const uint32_t vb = kb + 32768;

        float sacc[16][4];
#pragma unroll
        for (int i = 0; i < 16; i++)
#pragma unroll
            for (int e = 0; e < 4; e++) sacc[i][e] = 0.0f;

#pragma unroll
        for (int kf = 0; kf < 8; kf++) {
            uint32_t sub = (uint32_t)(kf >> 1) * 8192;
            uint32_t kc  = (uint32_t)(kf & 1) * 2;
            uint32_t AH[4];
            ldsm4(AH, sb + FA_QHI + sub + swoff(aRowQ, kc + aSel));
#pragma unroll
            for (int p = 0; p < 8; p++) {
                uint32_t BH[4];
                ldsm4(BH, kb + sub + swoff(bRow + p * 16, kc + bSel));
#pragma unroll
                for (int q = 0; q < 2; q++)
                    mma16816(sacc[2 * p + q], AH, BH + 2 * q);
            }
        }

        const float* bias = biasb + j * 128;
        const float* uu   = ub + j * 128;
        const bool diag = (j == by);

        float mb0 = -1e30f, mb1 = -1e30f;
#pragma unroll
        for (int nt = 0; nt < 16; nt++) {
            int k0 = nt * 8 + tc * 2;
            float b0 = bias[k0], b1 = bias[k0 + 1];
            float a0 = sacc[nt][0] + b0;
            float a1 = sacc[nt][1] + b1;
            float a2 = sacc[nt][2] + b0;
            float a3 = sacc[nt][3] + b1;
            if (diag) {
                if (k0     > row0)     a0 = -1e30f;
                if (k0 + 1 > row0)     a1 = -1e30f;
                if (k0     > row0 + 8) a2 = -1e30f;
                if (k0 + 1 > row0 + 8) a3 = -1e30f;
            }
            sacc[nt][0] = a0; sacc[nt][1] = a1;
            sacc[nt][2] = a2; sacc[nt][3] = a3;
            mb0 = fmaxf(mb0, fmaxf(a0, a1));
            mb1 = fmaxf(mb1, fmaxf(a2, a3));
        }
        mb0 = fmaxf(mb0, __shfl_xor_sync(0xffffffffu, mb0, 1));
        mb0 = fmaxf(mb0, __shfl_xor_sync(0xffffffffu, mb0, 2));
        mb1 = fmaxf(mb1, __shfl_xor_sync(0xffffffffu, mb1, 1));
        mb1 = fmaxf(mb1, __shfl_xor_sync(0xffffffffu, mb1, 2));

        float mn0 = fmaxf(mrun0, mb0);
        float mn1 = fmaxf(mrun1, mb1);
        float sc0 = __expf(mrun0 - mn0);
        float sc1 = __expf(mrun1 - mn1);
        mrun0 = mn0; mrun1 = mn1;

        float rs0 = 0.0f, rs1 = 0.0f;
#pragma unroll
        for (int nt = 0; nt < 16; nt++) {
            int k0 = nt * 8 + tc * 2;
            float u0 = uu[k0], u1 = uu[k0 + 1];
            float e0 = __expf(sacc[nt][0] - mn0) * u0;
            float e1 = __expf(sacc[nt][1] - mn0) * u1;
            float e2 = __expf(sacc[nt][2] - mn1) * u0;
            float e3 = __expf(sacc[nt][3] - mn1) * u1;
            sacc[nt][0] = e0; sacc[nt][1] = e1;
            sacc[nt][2] = e2; sacc[nt][3] = e3;
            rs0 += e0 + e1; rs1 += e2 + e3;
            oacc[nt][0] *= sc0; oacc[nt][1] *= sc0;
            oacc[nt][2] *= sc1; oacc[nt][3] *= sc1;
        }
        rs0 += __shfl_xor_sync(0xffffffffu, rs0, 1);
        rs0 += __shfl_xor_sync(0xffffffffu, rs0, 2);
        rs1 += __shfl_xor_sync(0xffffffffu, rs1, 1);
        rs1 += __shfl_xor_sync(0xffffffffu, rs1, 2);
        srun0 = srun0 * sc0 + rs0;
        srun1 = srun1 * sc1 + rs1;

#pragma unroll
        for (int kf = 0; kf < 8; kf++) {
            uint32_t AP[4];
            AP[0] = packh2(sacc[2 * kf][0],     sacc[2 * kf][1]);
            AP[1] = packh2(sacc[2 * kf][2],     sacc[2 * kf][3]);
            AP[2] = packh2(sacc[2 * kf + 1][0], sacc[2 * kf + 1][1]);
            AP[3] = packh2(sacc[2 * kf + 1][2], sacc[2 * kf + 1][3]);
            uint32_t sub = (uint32_t)(kf >> 1) * 8192;
            uint32_t kc  = (uint32_t)(kf & 1) * 2;
#pragma unroll
            for (int p = 0; p < 8; p++) {
                uint32_t BV[4];
                ldsm4(BV, vb + sub + swoff(bRow + p * 16, kc + bSel));
                mma16816(oacc[2 * p],     AP, BV);
                mma16816(oacc[2 * p + 1], AP, BV + 2);
            }
        }
        __syncthreads();
    }

    float inv0 = 1.0f / srun0;
    float inv1 = 1.0f / srun1;
    int grow = by * 128 + wid * 16 + g;
    __half* Hp = cxhi + (size_t)grow * HID + h * D + tc * 2;
#pragma unroll
    for (int nt = 0; nt < 16; nt++) {
        *(__half2*)(Hp + nt * 8) =
            __halves2half2(__float2half(oacc[nt][0] * inv0),
                           __float2half(oacc[nt][1] * inv0));
        *(__half2*)(Hp + (size_t)8 * HID + nt * 8) =
            __halves2half2(__float2half(oacc[nt][2] * inv1),
                           __float2half(oacc[nt][3] * inv1));
    }
}

// ---------------- fused fp32 -> fp16 convert (all 5 tensors, one launch) ---
#define N4_HS  (S * HID / 4)
#define N4_WQ  (HID * HID / 4)
#define N4_WK  (KVHID * HID / 4)
#define N4_WV  (KVHID * HID / 4)
#define N4_WO  (HID * HID / 4)
#define N4_TOT (N4_HS + N4_WQ + N4_WK + N4_WV + N4_WO)

__global__ void cvt_all_kernel(
    const float4* __restrict__ hs, const float4* __restrict__ wq,
    const float4* __restrict__ wk, const float4* __restrict__ wv,
    const float4* __restrict__ wo,
    uint2* __restrict__ hshi, uint2* __restrict__ wqkvhi,
    uint2* __restrict__ wohi)
{
    const int c1 = N4_HS;
    const int c2 = c1 + N4_WQ;
    const int c3 = c2 + N4_WK;
    const int c4 = c3 + N4_WV;
    int stride = gridDim.x * blockDim.x;
    for (int i = blockIdx.x * blockDim.x + threadIdx.x; i < N4_TOT; i += stride) {
        const float4* src;
        uint2* dst;
        int off;
        if (i < c1)       { src = hs; dst = hshi;   off = i; }
        else if (i < c2)  { src = wq; dst = wqkvhi; off = i - c1; }
        else if (i < c3)  { src = wk; dst = wqkvhi + N4_WQ; off = i - c2; }
        else if (i < c4)  { src = wv; dst = wqkvhi + N4_WQ + N4_WK; off = i - c3; }
        else              { src = wo; dst = wohi;   off = i - c4; }
        float4 v = src[off];
        __half2 a = __floats2half2_rn(v.x, v.y);
        __half2 b = __floats2half2_rn(v.z, v.w);
        uint2 w;
        w.x = *(uint32_t*)&a;
        w.y = *(uint32_t*)&b;
        dst[off] = w;
    }
}

// ---------------- launch ----------------------------------------------------
extern "C" void kernel_launch(void* const* d_in, const int* in_sizes, int n_in,
                              void* d_out, int out_size)
{
    const float* hs    = (const float*)d_in[0];
    const int*   pos   = (const int*)  d_in[2];
    const float* Wq    = (const float*)d_in[3];
    const float* Wk    = (const float*)d_in[4];
    const float* Wv    = (const float*)d_in[5];
    const float* Wo    = (const float*)d_in[6];
    const float* prior = (const float*)d_in[7];
    const float* m1    = (const float*)d_in[8];
    const float* m2    = (const float*)d_in[9];
    float* out = (float*)d_out;

    __half *hshi, *wqkvhi, *wohi, *qhi, *khi, *vthi, *cxhi;
    cudaGetSymbolAddress((void**)&hshi,  g_hs_hi);
    cudaGetSymbolAddress((void**)&wqkvhi,g_wqkv_hi);
    cudaGetSymbolAddress((void**)&wohi,  g_wo_hi);
    cudaGetSymbolAddress((void**)&qhi,   g_q_hi);
    cudaGetSymbolAddress((void**)&khi,   g_k_hi);
    cudaGetSymbolAddress((void**)&vthi,  g_vT_hi);
    cudaGetSymbolAddress((void**)&cxhi,  g_ctx_hi);

    static int configured = 0;
    if (!configured) {
        cudaFuncSetAttribute(gemm_fp16<true>,
            cudaFuncAttributeMaxDynamicSharedMemorySize, GSMEM);
        cudaFuncSetAttribute(gemm_fp16<false>,
            cudaFuncAttributeMaxDynamicSharedMemorySize, GSMEM);
        cudaFuncSetAttribute(flash_attn,
            cudaFuncAttributeMaxDynamicSharedMemorySize, FA_SMEM);
        configured = 1;
    }

    dim3 blk(256);

    // 0) all fp32->fp16 converts in one launch
    cvt_all_kernel<<<4096, 256>>>(
        (const float4*)hs, (const float4*)Wq, (const float4*)Wk,
        (const float4*)Wv, (const float4*)Wo,
        (uint2*)hshi, (uint2*)wqkvhi, (uint2*)wohi);

    // 1) merged projection GEMM with fused RoPE/scale/transpose epilogue
    gemm_fp16<true><<<dim3(QKVW / 128, S / 128), blk, GSMEM>>>(
        hshi, wqkvhi, nullptr, HID, HID, HID, 0,
        pos, prior, qhi, khi, vthi);

    // 2) fused flash attention -> ctx fp16
    flash_attn<<<dim3(H, S / 128), blk, FA_SMEM>>>(
        qhi, khi, vthi, prior, m1, m2, cxhi);

    // 3) out = ctx @ Wo^T
    gemm_fp16<false><<<dim3(HID / 128, S / 128), blk, GSMEM>>>(
        cxhi, wohi, out, HID, HID, HID, HID,
        nullptr, nullptr, nullptr, nullptr, nullptr);
}